// round 1
// baseline (speedup 1.0000x reference)
#include <cuda_runtime.h>

// Problem constants
#define B_  8
#define L_  4096
#define N_  128
#define F_  128
#define H_  8
#define DK_ 16
#define DV_ 32
#define TK_ 128
#define TV_ 256
#define BOT_ 256
#define FFN_ 2048
#define INV_C 0.9995003746877732f  // 1/sqrt(1+1e-3)

#define MPIX (B_*L_)   // 32768
#define MMEM (B_*N_)   // 1024

// -------------------- scratch (device globals; no allocation) --------------------
__device__ float g_pix [MPIX*BOT_];   // 32 MB  relu(BN(pixel @ W_pix1))
__device__ float g_pqkv[MPIX*512];    // 64 MB  BN(pix @ W_pix_qkv)
__device__ float g_mem [MMEM*BOT_];
__device__ float g_mqkv[MMEM*512];
__device__ float g_retmem[MMEM*TV_];
__device__ float g_memout[MMEM*F_];
__device__ float g_ffn [MMEM*FFN_];
__device__ float g_pret[MPIX*TV_];    // 32 MB

// -------------------- FFMA-only exp / rcp (avoid MUFU bottleneck) --------------------
__device__ __forceinline__ float fast_exp(float x) {
    // exp(x) = 2^(x*log2e); valid (clamped) for |x| <= 87
    x = fmaxf(-87.0f, fminf(87.0f, x));
    float y = x * 1.4426950408889634f;
    float z = y + 12582912.0f;            // round-to-nearest via magic add (1.5*2^23)
    int   iz = __float_as_int(z);         // = 0x4B400000 + n
    float f  = y - (z - 12582912.0f);     // frac in [-0.5, 0.5]
    float p = 1.33335581e-3f;
    p = fmaf(p, f, 9.61812910e-3f);
    p = fmaf(p, f, 5.55041087e-2f);
    p = fmaf(p, f, 2.40226510e-1f);
    p = fmaf(p, f, 6.93147182e-1f);
    p = fmaf(p, f, 1.0f);
    float s = __int_as_float((iz + (127 - 0x4B400000)) << 23);  // 2^n
    return p * s;
}

__device__ __forceinline__ float fast_rcp(float d) {
    // Newton iterations from bit-trick estimate; rel err < 1e-9 for normal d > 0
    float r = __int_as_float(0x7EF311C3 - __float_as_int(d));
    r = r * (2.0f - d * r);
    r = r * (2.0f - d * r);
    r = r * (2.0f - d * r);
    return r;
}

__device__ __forceinline__ float fast_sigmoid(float x) {
    return fast_rcp(1.0f + fast_exp(-x));
}

// -------------------- generic fp32 GEMM + BN epilogue --------------------
// C[M,N] = epi( A[M,K] @ Bw[K,N] )  with epi: y*gamma*INV + beta (+res) (+relu)
// Requires M%64==0, N%64==0, K%16==0 (true for all call sites).
template<bool RELU, bool RES>
__global__ void gemm_bn(const float* __restrict__ A, const float* __restrict__ Bw,
                        const float* __restrict__ bn, const float* __restrict__ res,
                        float* __restrict__ C, int M, int Nn, int K) {
    __shared__ float As[16][68];
    __shared__ float Bs[16][68];
    const int tid = threadIdx.x;
    const int tx = tid & 15, ty = tid >> 4;
    const int n0 = blockIdx.x * 64, m0 = blockIdx.y * 64;

    const int la_m = tid >> 2;          // 0..63
    const int la_k = (tid & 3) * 4;     // 0,4,8,12
    const int lb_k = tid >> 4;          // 0..15
    const int lb_n = (tid & 15) * 4;    // 0..60

    const float* Aptr = A  + (size_t)(m0 + la_m) * K + la_k;
    const float* Bptr = Bw + (size_t)lb_k * Nn + n0 + lb_n;

    float acc[4][4] = {};

    for (int k0 = 0; k0 < K; k0 += 16) {
        float4 av = *(const float4*)(Aptr + k0);
        float4 bv = *(const float4*)(Bptr + (size_t)k0 * Nn);
        As[la_k + 0][la_m] = av.x;
        As[la_k + 1][la_m] = av.y;
        As[la_k + 2][la_m] = av.z;
        As[la_k + 3][la_m] = av.w;
        *(float4*)&Bs[lb_k][lb_n] = bv;
        __syncthreads();
        #pragma unroll
        for (int kk = 0; kk < 16; kk++) {
            float4 a4 = *(const float4*)&As[kk][ty * 4];
            float4 b4 = *(const float4*)&Bs[kk][tx * 4];
            float ar[4] = {a4.x, a4.y, a4.z, a4.w};
            float br[4] = {b4.x, b4.y, b4.z, b4.w};
            #pragma unroll
            for (int i = 0; i < 4; i++)
                #pragma unroll
                for (int j = 0; j < 4; j++)
                    acc[i][j] = fmaf(ar[i], br[j], acc[i][j]);
        }
        __syncthreads();
    }

    #pragma unroll
    for (int j = 0; j < 4; j++) {
        int col = n0 + tx * 4 + j;
        float g = bn[col] * INV_C;
        float bta = bn[Nn + col];
        #pragma unroll
        for (int i = 0; i < 4; i++) {
            size_t idx = (size_t)(m0 + ty * 4 + i) * Nn + col;
            float v = fmaf(acc[i][j], g, bta);
            if (RES)  v += res[idx];
            if (RELU) v = fmaxf(v, 0.0f);
            C[idx] = v;
        }
    }
}

// -------------------- memory-path attention (softmax over L+N=4224 keys) --------------
// grid = B*H (64 blocks), 128 threads = one query each (N=128).
__global__ void mem_attn(const float* __restrict__ pqkv, const float* __restrict__ mqkv,
                         const float* __restrict__ bn_sim, const float* __restrict__ bn_ret,
                         float* __restrict__ retmem) {
    const int b = blockIdx.x >> 3, h = blockIdx.x & 7;
    const int n = threadIdx.x;

    __shared__ float sk[128][16];
    __shared__ float sv[128][32];

    float q[16];
    const float* qp = mqkv + (size_t)(b * 128 + n) * 512 + h * 16;
    #pragma unroll
    for (int d = 0; d < 16; d++) q[d] = qp[d];

    const float gs = bn_sim[h] * INV_C;
    const float gb = bn_sim[8 + h];

    float mi = -1e30f, li = 0.0f;
    float acc[32] = {};

    for (int t = 0; t < 33; t++) {
        const float* src = (t < 32)
            ? pqkv + (size_t)(b * 4096 + t * 128 + n) * 512
            : mqkv + (size_t)(b * 128 + n) * 512;
        // thread n stages key/value n of this tile
        {
            const float4* gk = (const float4*)(src + 128 + h * 16);
            float4* k4 = (float4*)&sk[n][0];
            k4[0] = gk[0]; k4[1] = gk[1]; k4[2] = gk[2]; k4[3] = gk[3];
            const float4* gv = (const float4*)(src + 256 + h * 32);
            float4* v4 = (float4*)&sv[n][0];
            #pragma unroll
            for (int i = 0; i < 8; i++) v4[i] = gv[i];
        }
        __syncthreads();

        for (int m = 0; m < 128; m++) {
            float dot = 0.0f;
            #pragma unroll
            for (int d = 0; d < 16; d++) dot = fmaf(q[d], sk[m][d], dot);
            float x = fmaf(dot, gs, gb);
            if (x <= mi) {
                float e = fast_exp(x - mi);
                li += e;
                #pragma unroll
                for (int d = 0; d < 32; d++) acc[d] = fmaf(e, sv[m][d], acc[d]);
            } else {
                float c = fast_exp(mi - x);
                li = fmaf(li, c, 1.0f);
                mi = x;
                #pragma unroll
                for (int d = 0; d < 32; d++) acc[d] = fmaf(acc[d], c, sv[m][d]);
            }
        }
        __syncthreads();
    }

    float inv = 1.0f / li;
    float* out = retmem + (size_t)(b * 128 + n) * 256 + h * 32;
    #pragma unroll
    for (int d = 0; d < 32; d++) {
        float r = acc[d] * inv;
        r = fmaf(r, bn_ret[h * 32 + d] * INV_C, bn_ret[256 + h * 32 + d]);
        out[d] = fmaxf(r, 0.0f);
    }
}

// -------------------- pixel-path attention (sigmoid over N=128 mem keys) --------------
// grid (32, H, B), 128 threads = one pixel-query each.
__global__ void pix_attn(const float* __restrict__ pqkv, const float* __restrict__ mqkv,
                         const float* __restrict__ bn_sim, const float* __restrict__ bn_ret,
                         float* __restrict__ pret) {
    const int lt = blockIdx.x, h = blockIdx.y, b = blockIdx.z;
    const int tid = threadIdx.x;

    __shared__ float sk[128][16];
    __shared__ float sv[128][32];
    {
        const float* src = mqkv + (size_t)(b * 128 + tid) * 512;
        const float4* gk = (const float4*)(src + 128 + h * 16);
        float4* k4 = (float4*)&sk[tid][0];
        k4[0] = gk[0]; k4[1] = gk[1]; k4[2] = gk[2]; k4[3] = gk[3];
        const float4* gv = (const float4*)(src + 256 + h * 32);
        float4* v4 = (float4*)&sv[tid][0];
        #pragma unroll
        for (int i = 0; i < 8; i++) v4[i] = gv[i];
    }

    const int l = lt * 128 + tid;
    float q[16];
    const float* qp = pqkv + (size_t)(b * 4096 + l) * 512 + h * 16;
    #pragma unroll
    for (int d = 0; d < 16; d++) q[d] = qp[d];

    const float gs = bn_sim[h] * INV_C;
    const float gb = bn_sim[8 + h];

    float acc[32] = {};
    __syncthreads();

    for (int m = 0; m < 128; m++) {
        float dot = 0.0f;
        #pragma unroll
        for (int d = 0; d < 16; d++) dot = fmaf(q[d], sk[m][d], dot);
        float p = fast_sigmoid(fmaf(dot, gs, gb));
        #pragma unroll
        for (int d = 0; d < 32; d++) acc[d] = fmaf(p, sv[m][d], acc[d]);
    }

    float* out = pret + (size_t)(b * 4096 + l) * 256 + h * 32;
    #pragma unroll
    for (int d = 0; d < 32; d++) {
        float r = fmaf(acc[d], bn_ret[h * 32 + d] * INV_C, bn_ret[256 + h * 32 + d]);
        out[d] = fmaxf(r, 0.0f);
    }
}

// -------------------- launch --------------------
extern "C" void kernel_launch(void* const* d_in, const int* in_sizes, int n_in,
                              void* d_out, int out_size) {
    const float* pixel_input  = (const float*)d_in[0];
    const float* memory_input = (const float*)d_in[1];
    const float* W_mem1     = (const float*)d_in[2];
    const float* bn_mem1    = (const float*)d_in[3];
    const float* W_pix1     = (const float*)d_in[4];
    const float* bn_pix1    = (const float*)d_in[5];
    const float* W_mem_qkv  = (const float*)d_in[6];
    const float* bn_mem_qkv = (const float*)d_in[7];
    const float* W_pix_qkv  = (const float*)d_in[8];
    const float* bn_pix_qkv = (const float*)d_in[9];
    const float* bn_mem_sim = (const float*)d_in[10];
    const float* bn_mem_ret = (const float*)d_in[11];
    const float* bn_pix_sim = (const float*)d_in[12];
    const float* bn_pix_ret = (const float*)d_in[13];
    const float* W_mem3     = (const float*)d_in[14];
    const float* bn_mem3    = (const float*)d_in[15];
    const float* W_pix3     = (const float*)d_in[16];
    const float* bn_pix3    = (const float*)d_in[17];
    const float* W_ffn1     = (const float*)d_in[18];
    const float* bn_ffn1    = (const float*)d_in[19];
    const float* W_ffn2     = (const float*)d_in[20];
    const float* bn_ffn2    = (const float*)d_in[21];

    float* out_pix = (float*)d_out;                    // (B,L,F)
    float* out_mem = (float*)d_out + (size_t)MPIX * F_;  // (B,N,F)

    float *pix, *pqkv, *mem, *mqkv, *retmem, *memout, *ffn, *pret;
    cudaGetSymbolAddress((void**)&pix,    g_pix);
    cudaGetSymbolAddress((void**)&pqkv,   g_pqkv);
    cudaGetSymbolAddress((void**)&mem,    g_mem);
    cudaGetSymbolAddress((void**)&mqkv,   g_mqkv);
    cudaGetSymbolAddress((void**)&retmem, g_retmem);
    cudaGetSymbolAddress((void**)&memout, g_memout);
    cudaGetSymbolAddress((void**)&ffn,    g_ffn);
    cudaGetSymbolAddress((void**)&pret,   g_pret);

    // stage 1: bottleneck convs
    gemm_bn<true,  false><<<dim3(BOT_/64, MPIX/64), 256>>>(pixel_input,  W_pix1, bn_pix1, nullptr, pix, MPIX, BOT_, F_);
    gemm_bn<true,  false><<<dim3(BOT_/64, MMEM/64), 256>>>(memory_input, W_mem1, bn_mem1, nullptr, mem, MMEM, BOT_, F_);
    // stage 2: qkv projections
    gemm_bn<false, false><<<dim3(512/64, MPIX/64), 256>>>(pix, W_pix_qkv, bn_pix_qkv, nullptr, pqkv, MPIX, 512, BOT_);
    gemm_bn<false, false><<<dim3(512/64, MMEM/64), 256>>>(mem, W_mem_qkv, bn_mem_qkv, nullptr, mqkv, MMEM, 512, BOT_);
    // memory path: softmax attention over pixel+memory keys, then out-proj + FFN
    mem_attn<<<B_ * H_, 128>>>(pqkv, mqkv, bn_mem_sim, bn_mem_ret, retmem);
    gemm_bn<true,  true ><<<dim3(F_/64,   MMEM/64), 256>>>(retmem, W_mem3, bn_mem3, memory_input, memout, MMEM, F_, TV_);
    gemm_bn<true,  false><<<dim3(FFN_/64, MMEM/64), 256>>>(memout, W_ffn1, bn_ffn1, nullptr, ffn, MMEM, FFN_, F_);
    gemm_bn<true,  true ><<<dim3(F_/64,   MMEM/64), 256>>>(ffn, W_ffn2, bn_ffn2, memout, out_mem, MMEM, F_, FFN_);
    // pixel path: sigmoid attention over memory keys, then out-proj
    pix_attn<<<dim3(L_/128, H_, B_), 128>>>(pqkv, mqkv, bn_pix_sim, bn_pix_ret, pret);
    gemm_bn<true,  true ><<<dim3(F_/64, MPIX/64), 256>>>(pret, W_pix3, bn_pix3, pixel_input, out_pix, MPIX, F_, TV_);
}

// round 2
// speedup vs baseline: 1.7146x; 1.7146x over previous
#include <cuda_runtime.h>

typedef unsigned long long ull;

// Problem constants
#define B_  8
#define L_  4096
#define N_  128
#define F_  128
#define H_  8
#define DK_ 16
#define DV_ 32
#define TK_ 128
#define TV_ 256
#define BOT_ 256
#define FFN_ 2048
#define INV_C 0.9995003746877732f  // 1/sqrt(1+1e-3)
#define L2E  1.4426950408889634f

#define MPIX (B_*L_)   // 32768
#define MMEM (B_*N_)   // 1024

// -------------------- scratch (device globals; no allocation) --------------------
__device__ float g_pix [MPIX*BOT_];
__device__ float g_pqkv[(size_t)MPIX*512];
__device__ float g_mem [MMEM*BOT_];
__device__ float g_mqkv[MMEM*512];
__device__ float g_retmem[MMEM*TV_];
__device__ float g_memout[MMEM*F_];
__device__ float g_ffn [MMEM*FFN_];
__device__ float g_pret[(size_t)MPIX*TV_];
__device__ float g_mpart[64*8*34*128];   // [b*8+h][split][field(0=m,1=l,2..33=acc)][n]

// -------------------- fast math --------------------
__device__ __forceinline__ float ex2a(float x){ float r; asm("ex2.approx.f32 %0, %1;" : "=f"(r):"f"(x)); return r; }
__device__ __forceinline__ float rcpa(float x){ float r; asm("rcp.approx.f32 %0, %1;" : "=f"(r):"f"(x)); return r; }

// packed f32x2 helpers
__device__ __forceinline__ ull dup2(float a){
    ull r; asm("mov.b64 %0, {%1,%1};" : "=l"(r) : "f"(a)); return r;
}
__device__ __forceinline__ void fma2(ull &d, ull a, ull b){
    asm("fma.rn.f32x2 %0, %1, %2, %0;" : "+l"(d) : "l"(a), "l"(b));
}
__device__ __forceinline__ float2 unpack2(ull v){
    float2 f; asm("mov.b64 {%0,%1}, %2;" : "=f"(f.x), "=f"(f.y) : "l"(v)); return f;
}

// -------------------- fp32x2 GEMM + BN epilogue --------------------
// C[M,N] = epi( A[M,K] @ Bw[K,N] );  M%128==0, N%128==0, K%8==0.
// 128x128 tile, 256 threads, 8x8 per thread (two 4-row x two 4-col groups),
// double-buffered smem, packed fma.rn.f32x2 accumulation.
template<bool RELU, bool RES>
__global__ void __launch_bounds__(256) gemm_bn(
        const float* __restrict__ A, const float* __restrict__ Bw,
        const float* __restrict__ bn, const float* __restrict__ res,
        float* __restrict__ C, int M, int Nn, int K) {
    __shared__ float As[2][8][132];
    __shared__ float Bs[2][8][132];
    const int tid = threadIdx.x;
    const int n0 = blockIdx.x * 128, m0 = blockIdx.y * 128;
    const int tx = tid & 15, ty = tid >> 4;

    const int ar = tid >> 1,  ak = (tid & 1) * 4;   // A load: row, k-offset
    const int bk = tid >> 5,  bnn = (tid & 31) * 4; // B load: k-row, n-offset

    const float* Ap = A  + (size_t)(m0 + ar) * K + ak;
    const float* Bp = Bw + (size_t)bk * Nn + n0 + bnn;

    ull acc[8][4];
    #pragma unroll
    for (int i = 0; i < 8; i++)
        #pragma unroll
        for (int j = 0; j < 4; j++) acc[i][j] = 0ull;

    const int KT = K >> 3;
    {
        float4 av = *(const float4*)Ap;
        float4 bv = *(const float4*)Bp;
        As[0][ak+0][ar] = av.x; As[0][ak+1][ar] = av.y;
        As[0][ak+2][ar] = av.z; As[0][ak+3][ar] = av.w;
        *(float4*)&Bs[0][bk][bnn] = bv;
    }
    __syncthreads();

    for (int kt = 0; kt < KT; kt++) {
        const int buf = kt & 1;
        const bool more = (kt + 1 < KT);
        float4 av, bv;
        if (more) {
            av = *(const float4*)(Ap + (kt + 1) * 8);
            bv = *(const float4*)(Bp + (size_t)(kt + 1) * 8 * Nn);
        }
        #pragma unroll
        for (int kk = 0; kk < 8; kk++) {
            float4 a0 = *(const float4*)&As[buf][kk][ty * 4];
            float4 a1 = *(const float4*)&As[buf][kk][64 + ty * 4];
            float4 b0 = *(const float4*)&Bs[buf][kk][tx * 4];
            float4 b1 = *(const float4*)&Bs[buf][kk][64 + tx * 4];
            ull bp0 = ((ull*)&b0)[0], bp1 = ((ull*)&b0)[1];
            ull bp2 = ((ull*)&b1)[0], bp3 = ((ull*)&b1)[1];
            float ra[8] = {a0.x, a0.y, a0.z, a0.w, a1.x, a1.y, a1.z, a1.w};
            #pragma unroll
            for (int i = 0; i < 8; i++) {
                ull ad = dup2(ra[i]);
                fma2(acc[i][0], ad, bp0);
                fma2(acc[i][1], ad, bp1);
                fma2(acc[i][2], ad, bp2);
                fma2(acc[i][3], ad, bp3);
            }
        }
        if (more) {
            const int nb = buf ^ 1;
            As[nb][ak+0][ar] = av.x; As[nb][ak+1][ar] = av.y;
            As[nb][ak+2][ar] = av.z; As[nb][ak+3][ar] = av.w;
            *(float4*)&Bs[nb][bk][bnn] = bv;
        }
        __syncthreads();
    }

    #pragma unroll
    for (int g = 0; g < 2; g++) {
        const int colb = n0 + g * 64 + tx * 4;
        float4 gam = *(const float4*)&bn[colb];
        float4 bet = *(const float4*)&bn[Nn + colb];
        gam.x *= INV_C; gam.y *= INV_C; gam.z *= INV_C; gam.w *= INV_C;
        #pragma unroll
        for (int i = 0; i < 8; i++) {
            const int row = m0 + ((i < 4) ? (ty * 4 + i) : (64 + ty * 4 + i - 4));
            float2 p0 = unpack2(acc[i][g * 2]);
            float2 p1 = unpack2(acc[i][g * 2 + 1]);
            float4 v;
            v.x = fmaf(p0.x, gam.x, bet.x);
            v.y = fmaf(p0.y, gam.y, bet.y);
            v.z = fmaf(p1.x, gam.z, bet.z);
            v.w = fmaf(p1.y, gam.w, bet.w);
            const size_t idx = (size_t)row * Nn + colb;
            if (RES) {
                float4 r = *(const float4*)&res[idx];
                v.x += r.x; v.y += r.y; v.z += r.z; v.w += r.w;
            }
            if (RELU) {
                v.x = fmaxf(v.x, 0.0f); v.y = fmaxf(v.y, 0.0f);
                v.z = fmaxf(v.z, 0.0f); v.w = fmaxf(v.w, 0.0f);
            }
            *(float4*)&C[idx] = v;
        }
    }
}

// -------------------- memory-path attention, split-K --------------------
// grid (8 splits, H, B), 128 threads = one query each.
// split s covers pixel tiles [s*4, s*4+4) (512 keys) + mem rows [s*16,(s+1)*16).
__global__ void __launch_bounds__(128) mem_attn_split(
        const float* __restrict__ pqkv, const float* __restrict__ mqkv,
        const float* __restrict__ bn_sim, float* __restrict__ part) {
    const int s = blockIdx.x, h = blockIdx.y, b = blockIdx.z;
    const int n = threadIdx.x;

    __shared__ float sk[128][16];
    __shared__ float sv[128][32];

    float q[16];
    {
        const float4* qp = (const float4*)(mqkv + (size_t)(b * 128 + n) * 512 + h * 16);
        float4 q4[4] = {qp[0], qp[1], qp[2], qp[3]};
        #pragma unroll
        for (int j = 0; j < 4; j++) {
            q[j*4+0] = ((float*)&q4[j])[0]; q[j*4+1] = ((float*)&q4[j])[1];
            q[j*4+2] = ((float*)&q4[j])[2]; q[j*4+3] = ((float*)&q4[j])[3];
        }
    }
    const float gs = bn_sim[h] * INV_C;
    const float gb = bn_sim[8 + h];

    float mi = -1e30f, li = 0.0f;
    float acc[32] = {};

    for (int t = 0; t < 4; t++) {
        const float* src = pqkv + (size_t)(b * 4096 + (s * 4 + t) * 128 + n) * 512;
        {
            const float4* gk = (const float4*)(src + 128 + h * 16);
            float4* k4 = (float4*)&sk[n][0];
            k4[0] = gk[0]; k4[1] = gk[1]; k4[2] = gk[2]; k4[3] = gk[3];
            const float4* gv = (const float4*)(src + 256 + h * 32);
            float4* v4 = (float4*)&sv[n][0];
            #pragma unroll
            for (int i = 0; i < 8; i++) v4[i] = gv[i];
        }
        __syncthreads();
        for (int m = 0; m < 128; m++) {
            float dot = 0.0f;
            #pragma unroll
            for (int d = 0; d < 16; d++) dot = fmaf(q[d], sk[m][d], dot);
            float x = fmaf(dot, gs, gb);
            if (x <= mi) {
                float e = ex2a((x - mi) * L2E);
                li += e;
                #pragma unroll
                for (int d = 0; d < 32; d++) acc[d] = fmaf(e, sv[m][d], acc[d]);
            } else {
                float c = ex2a((mi - x) * L2E);
                li = fmaf(li, c, 1.0f);
                mi = x;
                #pragma unroll
                for (int d = 0; d < 32; d++) acc[d] = fmaf(acc[d], c, sv[m][d]);
            }
        }
        __syncthreads();
    }
    // 16 memory keys
    if (n < 16) {
        const float* src = mqkv + (size_t)(b * 128 + s * 16 + n) * 512;
        const float4* gk = (const float4*)(src + 128 + h * 16);
        float4* k4 = (float4*)&sk[n][0];
        k4[0] = gk[0]; k4[1] = gk[1]; k4[2] = gk[2]; k4[3] = gk[3];
        const float4* gv = (const float4*)(src + 256 + h * 32);
        float4* v4 = (float4*)&sv[n][0];
        #pragma unroll
        for (int i = 0; i < 8; i++) v4[i] = gv[i];
    }
    __syncthreads();
    for (int m = 0; m < 16; m++) {
        float dot = 0.0f;
        #pragma unroll
        for (int d = 0; d < 16; d++) dot = fmaf(q[d], sk[m][d], dot);
        float x = fmaf(dot, gs, gb);
        if (x <= mi) {
            float e = ex2a((x - mi) * L2E);
            li += e;
            #pragma unroll
            for (int d = 0; d < 32; d++) acc[d] = fmaf(e, sv[m][d], acc[d]);
        } else {
            float c = ex2a((mi - x) * L2E);
            li = fmaf(li, c, 1.0f);
            mi = x;
            #pragma unroll
            for (int d = 0; d < 32; d++) acc[d] = fmaf(acc[d], c, sv[m][d]);
        }
    }

    float* base = part + (size_t)(((b * 8 + h) * 8 + s) * 34) * 128;
    base[0 * 128 + n] = mi;
    base[1 * 128 + n] = li;
    #pragma unroll
    for (int d = 0; d < 32; d++) base[(2 + d) * 128 + n] = acc[d];
}

// combine partials: grid 64 (b*8+h), 128 threads (query n)
__global__ void __launch_bounds__(128) mem_attn_combine(
        const float* __restrict__ part, const float* __restrict__ bn_ret,
        float* __restrict__ retmem) {
    const int bh = blockIdx.x;
    const int n = threadIdx.x;
    const int b = bh >> 3, h = bh & 7;

    float M = -1e30f;
    #pragma unroll
    for (int s = 0; s < 8; s++)
        M = fmaxf(M, part[(size_t)((bh * 8 + s) * 34) * 128 + n]);
    float Lsum = 0.0f;
    float acc[32] = {};
    #pragma unroll
    for (int s = 0; s < 8; s++) {
        const float* base = part + (size_t)((bh * 8 + s) * 34) * 128;
        float w = ex2a((base[n] - M) * L2E);
        Lsum = fmaf(base[128 + n], w, Lsum);
        #pragma unroll
        for (int d = 0; d < 32; d++)
            acc[d] = fmaf(w, base[(2 + d) * 128 + n], acc[d]);
    }
    float inv = rcpa(Lsum);
    inv = inv * (2.0f - Lsum * inv);   // 1 Newton for safety

    float* out = retmem + (size_t)(b * 128 + n) * 256 + h * 32;
    #pragma unroll
    for (int d = 0; d < 32; d++) {
        float r = acc[d] * inv;
        r = fmaf(r, bn_ret[h * 32 + d] * INV_C, bn_ret[256 + h * 32 + d]);
        out[d] = fmaxf(r, 0.0f);
    }
}

// -------------------- pixel-path attention (sigmoid over 128 mem keys) ----------
// grid (L/256, H, B), 128 threads, 2 queries per thread, f32x2 dot + accumulate.
__global__ void __launch_bounds__(128) pix_attn(
        const float* __restrict__ pqkv, const float* __restrict__ mqkv,
        const float* __restrict__ bn_sim, const float* __restrict__ bn_ret,
        float* __restrict__ pret) {
    const int lt = blockIdx.x, h = blockIdx.y, b = blockIdx.z;
    const int tid = threadIdx.x;

    __shared__ float sk[128][16];
    __shared__ float sv[128][32];
    {
        const float* src = mqkv + (size_t)(b * 128 + tid) * 512;
        const float4* gk = (const float4*)(src + 128 + h * 16);
        float4* k4 = (float4*)&sk[tid][0];
        k4[0] = gk[0]; k4[1] = gk[1]; k4[2] = gk[2]; k4[3] = gk[3];
        const float4* gv = (const float4*)(src + 256 + h * 32);
        float4* v4 = (float4*)&sv[tid][0];
        #pragma unroll
        for (int i = 0; i < 8; i++) v4[i] = gv[i];
    }

    const int l0 = lt * 256 + tid;
    const int l1 = l0 + 128;
    ull qpA[8], qpB[8];
    {
        const float4* qa = (const float4*)(pqkv + (size_t)(b * 4096 + l0) * 512 + h * 16);
        const float4* qb = (const float4*)(pqkv + (size_t)(b * 4096 + l1) * 512 + h * 16);
        #pragma unroll
        for (int j = 0; j < 4; j++) {
            float4 a = qa[j], bq = qb[j];
            qpA[2*j]   = ((ull*)&a)[0];  qpA[2*j+1] = ((ull*)&a)[1];
            qpB[2*j]   = ((ull*)&bq)[0]; qpB[2*j+1] = ((ull*)&bq)[1];
        }
    }

    const float gs = bn_sim[h] * INV_C;
    const float gb = bn_sim[8 + h];

    ull accA[16], accB[16];
    #pragma unroll
    for (int j = 0; j < 16; j++) { accA[j] = 0ull; accB[j] = 0ull; }
    __syncthreads();

    for (int m = 0; m < 128; m++) {
        const float4* k4 = (const float4*)&sk[m][0];
        ull kp[8];
        #pragma unroll
        for (int j = 0; j < 4; j++) {
            float4 kv = k4[j];
            kp[2*j]   = ((ull*)&kv)[0];
            kp[2*j+1] = ((ull*)&kv)[1];
        }
        ull dA = 0ull, dB = 0ull;
        #pragma unroll
        for (int j = 0; j < 8; j++) { fma2(dA, qpA[j], kp[j]); fma2(dB, qpB[j], kp[j]); }
        float2 fA = unpack2(dA), fB = unpack2(dB);
        float xA = fmaf(fA.x + fA.y, gs, gb);
        float xB = fmaf(fB.x + fB.y, gs, gb);
        float pA = rcpa(1.0f + ex2a(-xA * L2E));
        float pB = rcpa(1.0f + ex2a(-xB * L2E));
        ull dupA = dup2(pA), dupB = dup2(pB);

        const float4* v4 = (const float4*)&sv[m][0];
        #pragma unroll
        for (int j = 0; j < 8; j++) {
            float4 v = v4[j];
            ull v0 = ((ull*)&v)[0], v1 = ((ull*)&v)[1];
            fma2(accA[2*j],   dupA, v0);
            fma2(accA[2*j+1], dupA, v1);
            fma2(accB[2*j],   dupB, v0);
            fma2(accB[2*j+1], dupB, v1);
        }
    }

    #pragma unroll
    for (int qi = 0; qi < 2; qi++) {
        ull* acc = qi ? accB : accA;
        const int l = qi ? l1 : l0;
        float* out = pret + (size_t)(b * 4096 + l) * 256 + h * 32;
        #pragma unroll
        for (int j = 0; j < 8; j++) {
            float2 p0 = unpack2(acc[2*j]);
            float2 p1 = unpack2(acc[2*j+1]);
            float4 v;
            int d = j * 4;
            v.x = fmaxf(fmaf(p0.x, bn_ret[h*32+d+0] * INV_C, bn_ret[256+h*32+d+0]), 0.0f);
            v.y = fmaxf(fmaf(p0.y, bn_ret[h*32+d+1] * INV_C, bn_ret[256+h*32+d+1]), 0.0f);
            v.z = fmaxf(fmaf(p1.x, bn_ret[h*32+d+2] * INV_C, bn_ret[256+h*32+d+2]), 0.0f);
            v.w = fmaxf(fmaf(p1.y, bn_ret[h*32+d+3] * INV_C, bn_ret[256+h*32+d+3]), 0.0f);
            *(float4*)&out[d] = v;
        }
    }
}

// -------------------- launch --------------------
extern "C" void kernel_launch(void* const* d_in, const int* in_sizes, int n_in,
                              void* d_out, int out_size) {
    const float* pixel_input  = (const float*)d_in[0];
    const float* memory_input = (const float*)d_in[1];
    const float* W_mem1     = (const float*)d_in[2];
    const float* bn_mem1    = (const float*)d_in[3];
    const float* W_pix1     = (const float*)d_in[4];
    const float* bn_pix1    = (const float*)d_in[5];
    const float* W_mem_qkv  = (const float*)d_in[6];
    const float* bn_mem_qkv = (const float*)d_in[7];
    const float* W_pix_qkv  = (const float*)d_in[8];
    const float* bn_pix_qkv = (const float*)d_in[9];
    const float* bn_mem_sim = (const float*)d_in[10];
    const float* bn_mem_ret = (const float*)d_in[11];
    const float* bn_pix_sim = (const float*)d_in[12];
    const float* bn_pix_ret = (const float*)d_in[13];
    const float* W_mem3     = (const float*)d_in[14];
    const float* bn_mem3    = (const float*)d_in[15];
    const float* W_pix3     = (const float*)d_in[16];
    const float* bn_pix3    = (const float*)d_in[17];
    const float* W_ffn1     = (const float*)d_in[18];
    const float* bn_ffn1    = (const float*)d_in[19];
    const float* W_ffn2     = (const float*)d_in[20];
    const float* bn_ffn2    = (const float*)d_in[21];

    float* out_pix = (float*)d_out;
    float* out_mem = (float*)d_out + (size_t)MPIX * F_;

    float *pix, *pqkv, *mem, *mqkv, *retmem, *memout, *ffn, *pret, *mpart;
    cudaGetSymbolAddress((void**)&pix,    g_pix);
    cudaGetSymbolAddress((void**)&pqkv,   g_pqkv);
    cudaGetSymbolAddress((void**)&mem,    g_mem);
    cudaGetSymbolAddress((void**)&mqkv,   g_mqkv);
    cudaGetSymbolAddress((void**)&retmem, g_retmem);
    cudaGetSymbolAddress((void**)&memout, g_memout);
    cudaGetSymbolAddress((void**)&ffn,    g_ffn);
    cudaGetSymbolAddress((void**)&pret,   g_pret);
    cudaGetSymbolAddress((void**)&mpart,  g_mpart);

    // stage 1: bottleneck convs
    gemm_bn<true,  false><<<dim3(BOT_/128, MPIX/128), 256>>>(pixel_input,  W_pix1, bn_pix1, nullptr, pix, MPIX, BOT_, F_);
    gemm_bn<true,  false><<<dim3(BOT_/128, MMEM/128), 256>>>(memory_input, W_mem1, bn_mem1, nullptr, mem, MMEM, BOT_, F_);
    // stage 2: qkv projections
    gemm_bn<false, false><<<dim3(512/128, MPIX/128), 256>>>(pix, W_pix_qkv, bn_pix_qkv, nullptr, pqkv, MPIX, 512, BOT_);
    gemm_bn<false, false><<<dim3(512/128, MMEM/128), 256>>>(mem, W_mem_qkv, bn_mem_qkv, nullptr, mqkv, MMEM, 512, BOT_);
    // memory path: split-K softmax attention + out-proj + FFN
    mem_attn_split<<<dim3(8, H_, B_), 128>>>(pqkv, mqkv, bn_mem_sim, mpart);
    mem_attn_combine<<<B_ * H_, 128>>>(mpart, bn_mem_ret, retmem);
    gemm_bn<true,  true ><<<dim3(F_/128,   MMEM/128), 256>>>(retmem, W_mem3, bn_mem3, memory_input, memout, MMEM, F_, TV_);
    gemm_bn<true,  false><<<dim3(FFN_/128, MMEM/128), 256>>>(memout, W_ffn1, bn_ffn1, nullptr, ffn, MMEM, FFN_, F_);
    gemm_bn<true,  true ><<<dim3(F_/128,   MMEM/128), 256>>>(ffn, W_ffn2, bn_ffn2, memout, out_mem, MMEM, F_, FFN_);
    // pixel path: sigmoid attention + out-proj
    pix_attn<<<dim3(L_/256, H_, B_), 128>>>(pqkv, mqkv, bn_pix_sim, bn_pix_ret, pret);
    gemm_bn<true,  true ><<<dim3(F_/128, MPIX/128), 256>>>(pret, W_pix3, bn_pix3, pixel_input, out_pix, MPIX, F_, TV_);
}

// round 4
// speedup vs baseline: 2.6675x; 1.5557x over previous
#include <cuda_runtime.h>
#include <cstdint>

typedef unsigned long long ull;

// Problem constants
#define B_  8
#define L_  4096
#define N_  128
#define F_  128
#define H_  8
#define TV_ 256
#define BOT_ 256
#define FFN_ 2048
#define INV_C 0.9995003746877732f  // 1/sqrt(1+1e-3)
#define L2E  1.4426950408889634f

#define MPIX (B_*L_)   // 32768
#define MMEM (B_*N_)   // 1024

// -------------------- scratch (device globals; no allocation) --------------------
__device__ float g_pix [MPIX*BOT_];
__device__ float g_pqkv[(size_t)MPIX*512];
__device__ float g_mem [MMEM*BOT_];
__device__ float g_mqkv[MMEM*512];
__device__ float g_retmem[MMEM*TV_];
__device__ float g_memout[MMEM*F_];
__device__ float g_ffn [MMEM*FFN_];
__device__ float g_pret[(size_t)MPIX*TV_];
__device__ float g_mpart[64*8*34*128];
__device__ float g_wt[917504];          // transposed tf32-rounded weights
__device__ float g_skpart[8*MMEM*F_];   // split-K partials for ffn2

// offsets into g_wt
#define O_PIX1 0
#define O_MEM1 32768
#define O_PQKV 65536
#define O_MQKV 196608
#define O_MEM3 327680
#define O_PIX3 360448
#define O_FFN1 393216
#define O_FFN2 655360

// -------------------- fast math --------------------
__device__ __forceinline__ float ex2a(float x){ float r; asm("ex2.approx.f32 %0, %1;" : "=f"(r):"f"(x)); return r; }
__device__ __forceinline__ float rcpa(float x){ float r; asm("rcp.approx.f32 %0, %1;" : "=f"(r):"f"(x)); return r; }
__device__ __forceinline__ float tf32r(float x){ uint32_t u; asm("cvt.rna.tf32.f32 %0, %1;" : "=r"(u) : "f"(x)); return __uint_as_float(u); }

__device__ __forceinline__ ull dup2(float a){ ull r; asm("mov.b64 %0, {%1,%1};" : "=l"(r) : "f"(a)); return r; }
__device__ __forceinline__ void fma2(ull &d, ull a, ull b){ asm("fma.rn.f32x2 %0, %1, %2, %0;" : "+l"(d) : "l"(a), "l"(b)); }
__device__ __forceinline__ float2 unpack2(ull v){ float2 f; asm("mov.b64 {%0,%1}, %2;" : "=f"(f.x), "=f"(f.y) : "l"(v)); return f; }

// tf32 mma: D[16x8] += A[16x8] * B[8x8]^T  (A row-major, B "col" = [n][k])
__device__ __forceinline__ void mma8(float* d, const uint32_t* a, const uint32_t* b){
    asm volatile("mma.sync.aligned.m16n8k8.row.col.f32.tf32.tf32.f32 "
        "{%0,%1,%2,%3}, {%4,%5,%6,%7}, {%8,%9}, {%0,%1,%2,%3};"
        : "+f"(d[0]), "+f"(d[1]), "+f"(d[2]), "+f"(d[3])
        : "r"(a[0]), "r"(a[1]), "r"(a[2]), "r"(a[3]), "r"(b[0]), "r"(b[1]));
}

// swizzled smem index: row stride 32 floats (128B), 16B-quad XOR swizzle
__device__ __forceinline__ int sidx(int r, int k){
    return r * 32 + ((((k >> 2) ^ r) & 7) << 2) + (k & 3);
}

// -------------------- weight transpose (+tf32 rounding) --------------------
// in[K][N] -> out[N][K]; K,N multiples of 32.
__global__ void __launch_bounds__(256) wtrans(const float* __restrict__ in, float* __restrict__ out, int K, int Nn) {
    __shared__ float t[32][33];
    const int tx = threadIdx.x & 31, ty = threadIdx.x >> 5;
    const int bx = blockIdx.x, by = blockIdx.y;
    #pragma unroll
    for (int i = 0; i < 4; i++)
        t[ty + i * 8][tx] = in[(size_t)(by * 32 + ty + i * 8) * Nn + bx * 32 + tx];
    __syncthreads();
    #pragma unroll
    for (int i = 0; i < 4; i++)
        out[(size_t)(bx * 32 + ty + i * 8) * K + by * 32 + tx] = tf32r(t[tx][ty + i * 8]);
}

// -------------------- tf32 mma.sync GEMM + BN epilogue --------------------
// C[M,Nn] = epi( A[M,K] @ Bt[Nn,K]^T ).  M%128==0, Nn%128==0, K%32==0.
// 128x128 tile, 256 threads (8 warps: 2 along M x 4 along N), BK=32 double-buffered.
// PARTIAL: write raw partial sums to C + z*M*Nn (split-K chunk z covers K cols [z*K, (z+1)*K) of lda-wide rows)
template<bool RELU, bool RES, bool PARTIAL>
__global__ void __launch_bounds__(256) gemm_mma(
        const float* __restrict__ A, const float* __restrict__ Bt,
        const float* __restrict__ bn, const float* __restrict__ res,
        float* __restrict__ C, int M, int Nn, int K, int lda) {
    extern __shared__ float sm[];
    float* sAb = sm;            // 2 x 4096 floats
    float* sBb = sm + 8192;     // 2 x 4096 floats
    float* bns = sm + 16384;    // 256 floats
    const int tid = threadIdx.x;
    const int w = tid >> 5, lane = tid & 31;
    const int ly = lane >> 2, lx = lane & 3;
    const int wm = w >> 2, wn = w & 3;
    const int n0 = blockIdx.x * 128, m0 = blockIdx.y * 128;
    const int kbeg = PARTIAL ? blockIdx.z * K : 0;

    if (!PARTIAL && tid < 128) {
        bns[tid]       = bn[n0 + tid] * INV_C;
        bns[128 + tid] = bn[Nn + n0 + tid];
    }

    const int r = tid >> 1, h = tid & 1;
    const float* Ap = A  + (size_t)(m0 + r) * lda + kbeg + h * 16;
    const float* Bp = Bt + (size_t)(n0 + r) * lda + kbeg + h * 16;

    float4 ga[4], gb[4];
    #pragma unroll
    for (int j = 0; j < 4; j++) { ga[j] = *(const float4*)(Ap + 4 * j); gb[j] = *(const float4*)(Bp + 4 * j); }

    // stage current prefetch regs into buffer buf
    const int base_fi = r * 32;
    {
        float* dA = sAb; float* dB = sBb;
        #pragma unroll
        for (int j = 0; j < 4; j++) {
            const int k = h * 16 + 4 * j;
            const int fi = base_fi + ((((k >> 2) ^ r) & 7) << 2);
            float4 av = ga[j];
            av.x = tf32r(av.x); av.y = tf32r(av.y); av.z = tf32r(av.z); av.w = tf32r(av.w);
            *(float4*)(dA + fi) = av;
            *(float4*)(dB + fi) = gb[j];
        }
    }
    __syncthreads();

    float acc[4][4][4];
    #pragma unroll
    for (int a = 0; a < 4; a++)
        #pragma unroll
        for (int b = 0; b < 4; b++)
            #pragma unroll
            for (int c = 0; c < 4; c++) acc[a][b][c] = 0.0f;

    const int KB = K >> 5;
    for (int kb = 0; kb < KB; kb++) {
        if (kb + 1 < KB) {
            #pragma unroll
            for (int j = 0; j < 4; j++) {
                ga[j] = *(const float4*)(Ap + (kb + 1) * 32 + 4 * j);
                gb[j] = *(const float4*)(Bp + (size_t)(kb + 1) * 32 + 4 * j);
            }
        }
        const uint32_t* uA = (const uint32_t*)(sAb + (kb & 1) * 4096);
        const uint32_t* uB = (const uint32_t*)(sBb + (kb & 1) * 4096);
        #pragma unroll
        for (int kt = 0; kt < 4; kt++) {
            const int kk = kt * 8;
            uint32_t bf[4][2], af[4][4];
            #pragma unroll
            for (int nt = 0; nt < 4; nt++) {
                const int n = wn * 32 + nt * 8 + ly;
                bf[nt][0] = uB[sidx(n, kk + lx)];
                bf[nt][1] = uB[sidx(n, kk + lx + 4)];
            }
            #pragma unroll
            for (int mt = 0; mt < 4; mt++) {
                const int rr = wm * 64 + mt * 16 + ly;
                af[mt][0] = uA[sidx(rr,     kk + lx)];
                af[mt][1] = uA[sidx(rr + 8, kk + lx)];
                af[mt][2] = uA[sidx(rr,     kk + lx + 4)];
                af[mt][3] = uA[sidx(rr + 8, kk + lx + 4)];
            }
            #pragma unroll
            for (int mt = 0; mt < 4; mt++)
                #pragma unroll
                for (int nt = 0; nt < 4; nt++)
                    mma8(acc[mt][nt], af[mt], bf[nt]);
        }
        if (kb + 1 < KB) {
            const int nb = (kb + 1) & 1;
            float* dA = sAb + nb * 4096;
            float* dB = sBb + nb * 4096;
            #pragma unroll
            for (int j = 0; j < 4; j++) {
                const int k = h * 16 + 4 * j;
                const int fi = base_fi + ((((k >> 2) ^ r) & 7) << 2);
                float4 av = ga[j];
                av.x = tf32r(av.x); av.y = tf32r(av.y); av.z = tf32r(av.z); av.w = tf32r(av.w);
                *(float4*)(dA + fi) = av;
                *(float4*)(dB + fi) = gb[j];
            }
            __syncthreads();
        }
    }

    // epilogue
    if (PARTIAL) {
        float* Cp = C + (size_t)blockIdx.z * M * Nn;
        #pragma unroll
        for (int mt = 0; mt < 4; mt++) {
            const int rr = m0 + wm * 64 + mt * 16 + ly;
            #pragma unroll
            for (int nt = 0; nt < 4; nt++) {
                const int cc = n0 + wn * 32 + nt * 8 + lx * 2;
                float2 v0 = {acc[mt][nt][0], acc[mt][nt][1]};
                float2 v1 = {acc[mt][nt][2], acc[mt][nt][3]};
                *(float2*)&Cp[(size_t)rr * Nn + cc] = v0;
                *(float2*)&Cp[(size_t)(rr + 8) * Nn + cc] = v1;
            }
        }
    } else {
        #pragma unroll
        for (int mt = 0; mt < 4; mt++) {
            const int rr = m0 + wm * 64 + mt * 16 + ly;
            #pragma unroll
            for (int nt = 0; nt < 4; nt++) {
                const int lc = wn * 32 + nt * 8 + lx * 2;
                const int cc = n0 + lc;
                const float g0 = bns[lc], g1 = bns[lc + 1];
                const float b0 = bns[128 + lc], b1 = bns[128 + lc + 1];
                float2 v0, v1;
                v0.x = fmaf(acc[mt][nt][0], g0, b0);
                v0.y = fmaf(acc[mt][nt][1], g1, b1);
                v1.x = fmaf(acc[mt][nt][2], g0, b0);
                v1.y = fmaf(acc[mt][nt][3], g1, b1);
                const size_t i0 = (size_t)rr * Nn + cc;
                const size_t i1 = (size_t)(rr + 8) * Nn + cc;
                if (RES) {
                    float2 r0 = *(const float2*)&res[i0];
                    float2 r1 = *(const float2*)&res[i1];
                    v0.x += r0.x; v0.y += r0.y; v1.x += r1.x; v1.y += r1.y;
                }
                if (RELU) {
                    v0.x = fmaxf(v0.x, 0.0f); v0.y = fmaxf(v0.y, 0.0f);
                    v1.x = fmaxf(v1.x, 0.0f); v1.y = fmaxf(v1.y, 0.0f);
                }
                *(float2*)&C[i0] = v0;
                *(float2*)&C[i1] = v1;
            }
        }
    }
}

#define GEMM_SMEM ((16384 + 256) * 4)

// split-K reduce: out[m][c] = relu( (sum_s part[s][m][c]) * g + b + res[m][c] )
__global__ void __launch_bounds__(256) sk_reduce(
        const float* __restrict__ part, const float* __restrict__ bn,
        const float* __restrict__ res, float* __restrict__ out, int M, int SK) {
    const int idx = blockIdx.x * 256 + threadIdx.x;
    const int c = idx & 127;
    float s = 0.0f;
    for (int k = 0; k < SK; k++) s += part[(size_t)k * M * 128 + idx];
    float v = fmaf(s, bn[c] * INV_C, bn[128 + c]) + res[idx];
    out[idx] = fmaxf(v, 0.0f);
}

// -------------------- memory-path attention, split-K (unchanged, passing) --------------------
__global__ void __launch_bounds__(128) mem_attn_split(
        const float* __restrict__ pqkv, const float* __restrict__ mqkv,
        const float* __restrict__ bn_sim, float* __restrict__ part) {
    const int s = blockIdx.x, h = blockIdx.y, b = blockIdx.z;
    const int n = threadIdx.x;
    __shared__ float sk[128][16];
    __shared__ float sv[128][32];

    float q[16];
    {
        const float4* qp = (const float4*)(mqkv + (size_t)(b * 128 + n) * 512 + h * 16);
        #pragma unroll
        for (int j = 0; j < 4; j++) {
            float4 t = qp[j];
            q[j*4] = t.x; q[j*4+1] = t.y; q[j*4+2] = t.z; q[j*4+3] = t.w;
        }
    }
    const float gs = bn_sim[h] * INV_C;
    const float gb = bn_sim[8 + h];
    float mi = -1e30f, li = 0.0f;
    float acc[32] = {};

    for (int t = 0; t < 4; t++) {
        const float* src = pqkv + (size_t)(b * 4096 + (s * 4 + t) * 128 + n) * 512;
        {
            const float4* gk = (const float4*)(src + 128 + h * 16);
            float4* k4 = (float4*)&sk[n][0];
            k4[0] = gk[0]; k4[1] = gk[1]; k4[2] = gk[2]; k4[3] = gk[3];
            const float4* gv = (const float4*)(src + 256 + h * 32);
            float4* v4 = (float4*)&sv[n][0];
            #pragma unroll
            for (int i = 0; i < 8; i++) v4[i] = gv[i];
        }
        __syncthreads();
        for (int m = 0; m < 128; m++) {
            float dot = 0.0f;
            #pragma unroll
            for (int d = 0; d < 16; d++) dot = fmaf(q[d], sk[m][d], dot);
            float x = fmaf(dot, gs, gb);
            if (x <= mi) {
                float e = ex2a((x - mi) * L2E);
                li += e;
                #pragma unroll
                for (int d = 0; d < 32; d++) acc[d] = fmaf(e, sv[m][d], acc[d]);
            } else {
                float c = ex2a((mi - x) * L2E);
                li = fmaf(li, c, 1.0f);
                mi = x;
                #pragma unroll
                for (int d = 0; d < 32; d++) acc[d] = fmaf(acc[d], c, sv[m][d]);
            }
        }
        __syncthreads();
    }
    if (n < 16) {
        const float* src = mqkv + (size_t)(b * 128 + s * 16 + n) * 512;
        const float4* gk = (const float4*)(src + 128 + h * 16);
        float4* k4 = (float4*)&sk[n][0];
        k4[0] = gk[0]; k4[1] = gk[1]; k4[2] = gk[2]; k4[3] = gk[3];
        const float4* gv = (const float4*)(src + 256 + h * 32);
        float4* v4 = (float4*)&sv[n][0];
        #pragma unroll
        for (int i = 0; i < 8; i++) v4[i] = gv[i];
    }
    __syncthreads();
    for (int m = 0; m < 16; m++) {
        float dot = 0.0f;
        #pragma unroll
        for (int d = 0; d < 16; d++) dot = fmaf(q[d], sk[m][d], dot);
        float x = fmaf(dot, gs, gb);
        if (x <= mi) {
            float e = ex2a((x - mi) * L2E);
            li += e;
            #pragma unroll
            for (int d = 0; d < 32; d++) acc[d] = fmaf(e, sv[m][d], acc[d]);
        } else {
            float c = ex2a((mi - x) * L2E);
            li = fmaf(li, c, 1.0f);
            mi = x;
            #pragma unroll
            for (int d = 0; d < 32; d++) acc[d] = fmaf(acc[d], c, sv[m][d]);
        }
    }
    float* base = part + (size_t)(((b * 8 + h) * 8 + s) * 34) * 128;
    base[n] = mi;
    base[128 + n] = li;
    #pragma unroll
    for (int d = 0; d < 32; d++) base[(2 + d) * 128 + n] = acc[d];
}

__global__ void __launch_bounds__(128) mem_attn_combine(
        const float* __restrict__ part, const float* __restrict__ bn_ret,
        float* __restrict__ retmem) {
    const int bh = blockIdx.x;
    const int n = threadIdx.x;
    const int b = bh >> 3, h = bh & 7;
    float M = -1e30f;
    #pragma unroll
    for (int s = 0; s < 8; s++)
        M = fmaxf(M, part[(size_t)((bh * 8 + s) * 34) * 128 + n]);
    float Lsum = 0.0f;
    float acc[32] = {};
    #pragma unroll
    for (int s = 0; s < 8; s++) {
        const float* base = part + (size_t)((bh * 8 + s) * 34) * 128;
        float wgt = ex2a((base[n] - M) * L2E);
        Lsum = fmaf(base[128 + n], wgt, Lsum);
        #pragma unroll
        for (int d = 0; d < 32; d++)
            acc[d] = fmaf(wgt, base[(2 + d) * 128 + n], acc[d]);
    }
    float inv = rcpa(Lsum);
    inv = inv * (2.0f - Lsum * inv);
    float* out = retmem + (size_t)(b * 128 + n) * 256 + h * 32;
    #pragma unroll
    for (int d = 0; d < 32; d++) {
        float r = acc[d] * inv;
        r = fmaf(r, bn_ret[h * 32 + d] * INV_C, bn_ret[256 + h * 32 + d]);
        out[d] = fmaxf(r, 0.0f);
    }
}

// -------------------- pixel-path attention (unchanged, passing) --------------------
__global__ void __launch_bounds__(128) pix_attn(
        const float* __restrict__ pqkv, const float* __restrict__ mqkv,
        const float* __restrict__ bn_sim, const float* __restrict__ bn_ret,
        float* __restrict__ pret) {
    const int lt = blockIdx.x, h = blockIdx.y, b = blockIdx.z;
    const int tid = threadIdx.x;
    __shared__ float sk[128][16];
    __shared__ float sv[128][32];
    {
        const float* src = mqkv + (size_t)(b * 128 + tid) * 512;
        const float4* gk = (const float4*)(src + 128 + h * 16);
        float4* k4 = (float4*)&sk[tid][0];
        k4[0] = gk[0]; k4[1] = gk[1]; k4[2] = gk[2]; k4[3] = gk[3];
        const float4* gv = (const float4*)(src + 256 + h * 32);
        float4* v4 = (float4*)&sv[tid][0];
        #pragma unroll
        for (int i = 0; i < 8; i++) v4[i] = gv[i];
    }
    const int l0 = lt * 256 + tid;
    const int l1 = l0 + 128;
    ull qpA[8], qpB[8];
    {
        const float4* qa = (const float4*)(pqkv + (size_t)(b * 4096 + l0) * 512 + h * 16);
        const float4* qb = (const float4*)(pqkv + (size_t)(b * 4096 + l1) * 512 + h * 16);
        #pragma unroll
        for (int j = 0; j < 4; j++) {
            float4 a = qa[j], bq = qb[j];
            qpA[2*j] = ((ull*)&a)[0];  qpA[2*j+1] = ((ull*)&a)[1];
            qpB[2*j] = ((ull*)&bq)[0]; qpB[2*j+1] = ((ull*)&bq)[1];
        }
    }
    const float gs = bn_sim[h] * INV_C;
    const float gb = bn_sim[8 + h];
    ull accA[16], accB[16];
    #pragma unroll
    for (int j = 0; j < 16; j++) { accA[j] = 0ull; accB[j] = 0ull; }
    __syncthreads();

    for (int m = 0; m < 128; m++) {
        const float4* k4 = (const float4*)&sk[m][0];
        ull kp[8];
        #pragma unroll
        for (int j = 0; j < 4; j++) {
            float4 kv = k4[j];
            kp[2*j] = ((ull*)&kv)[0];
            kp[2*j+1] = ((ull*)&kv)[1];
        }
        ull dA = 0ull, dB = 0ull;
        #pragma unroll
        for (int j = 0; j < 8; j++) { fma2(dA, qpA[j], kp[j]); fma2(dB, qpB[j], kp[j]); }
        float2 fA = unpack2(dA), fB = unpack2(dB);
        float xA = fmaf(fA.x + fA.y, gs, gb);
        float xB = fmaf(fB.x + fB.y, gs, gb);
        float pA = rcpa(1.0f + ex2a(-xA * L2E));
        float pB = rcpa(1.0f + ex2a(-xB * L2E));
        ull dupA = dup2(pA), dupB = dup2(pB);
        const float4* v4 = (const float4*)&sv[m][0];
        #pragma unroll
        for (int j = 0; j < 8; j++) {
            float4 v = v4[j];
            ull v0 = ((ull*)&v)[0], v1 = ((ull*)&v)[1];
            fma2(accA[2*j],   dupA, v0);
            fma2(accA[2*j+1], dupA, v1);
            fma2(accB[2*j],   dupB, v0);
            fma2(accB[2*j+1], dupB, v1);
        }
    }
    #pragma unroll
    for (int qi = 0; qi < 2; qi++) {
        ull* acc = qi ? accB : accA;
        const int l = qi ? l1 : l0;
        float* out = pret + (size_t)(b * 4096 + l) * 256 + h * 32;
        #pragma unroll
        for (int j = 0; j < 8; j++) {
            float2 p0 = unpack2(acc[2*j]);
            float2 p1 = unpack2(acc[2*j+1]);
            float4 v;
            int d = j * 4;
            v.x = fmaxf(fmaf(p0.x, bn_ret[h*32+d+0] * INV_C, bn_ret[256+h*32+d+0]), 0.0f);
            v.y = fmaxf(fmaf(p0.y, bn_ret[h*32+d+1] * INV_C, bn_ret[256+h*32+d+1]), 0.0f);
            v.z = fmaxf(fmaf(p1.x, bn_ret[h*32+d+2] * INV_C, bn_ret[256+h*32+d+2]), 0.0f);
            v.w = fmaxf(fmaf(p1.y, bn_ret[h*32+d+3] * INV_C, bn_ret[256+h*32+d+3]), 0.0f);
            *(float4*)&out[d] = v;
        }
    }
}

// -------------------- launch --------------------
extern "C" void kernel_launch(void* const* d_in, const int* in_sizes, int n_in,
                              void* d_out, int out_size) {
    const float* pixel_input  = (const float*)d_in[0];
    const float* memory_input = (const float*)d_in[1];
    const float* W_mem1     = (const float*)d_in[2];
    const float* bn_mem1    = (const float*)d_in[3];
    const float* W_pix1     = (const float*)d_in[4];
    const float* bn_pix1    = (const float*)d_in[5];
    const float* W_mem_qkv  = (const float*)d_in[6];
    const float* bn_mem_qkv = (const float*)d_in[7];
    const float* W_pix_qkv  = (const float*)d_in[8];
    const float* bn_pix_qkv = (const float*)d_in[9];
    const float* bn_mem_sim = (const float*)d_in[10];
    const float* bn_mem_ret = (const float*)d_in[11];
    const float* bn_pix_sim = (const float*)d_in[12];
    const float* bn_pix_ret = (const float*)d_in[13];
    const float* W_mem3     = (const float*)d_in[14];
    const float* bn_mem3    = (const float*)d_in[15];
    const float* W_pix3     = (const float*)d_in[16];
    const float* bn_pix3    = (const float*)d_in[17];
    const float* W_ffn1     = (const float*)d_in[18];
    const float* bn_ffn1    = (const float*)d_in[19];
    const float* W_ffn2     = (const float*)d_in[20];
    const float* bn_ffn2    = (const float*)d_in[21];

    float* out_pix = (float*)d_out;
    float* out_mem = (float*)d_out + (size_t)MPIX * F_;

    float *pix, *pqkv, *mem, *mqkv, *retmem, *memout, *ffn, *pret, *mpart, *wt, *skp;
    cudaGetSymbolAddress((void**)&pix,    g_pix);
    cudaGetSymbolAddress((void**)&pqkv,   g_pqkv);
    cudaGetSymbolAddress((void**)&mem,    g_mem);
    cudaGetSymbolAddress((void**)&mqkv,   g_mqkv);
    cudaGetSymbolAddress((void**)&retmem, g_retmem);
    cudaGetSymbolAddress((void**)&memout, g_memout);
    cudaGetSymbolAddress((void**)&ffn,    g_ffn);
    cudaGetSymbolAddress((void**)&pret,   g_pret);
    cudaGetSymbolAddress((void**)&mpart,  g_mpart);
    cudaGetSymbolAddress((void**)&wt,     g_wt);
    cudaGetSymbolAddress((void**)&skp,    g_skpart);

    cudaFuncSetAttribute(gemm_mma<true,false,false>,  cudaFuncAttributeMaxDynamicSharedMemorySize, GEMM_SMEM);
    cudaFuncSetAttribute(gemm_mma<false,false,false>, cudaFuncAttributeMaxDynamicSharedMemorySize, GEMM_SMEM);
    cudaFuncSetAttribute(gemm_mma<true,true,false>,   cudaFuncAttributeMaxDynamicSharedMemorySize, GEMM_SMEM);
    cudaFuncSetAttribute(gemm_mma<false,false,true>,  cudaFuncAttributeMaxDynamicSharedMemorySize, GEMM_SMEM);

    // transpose + tf32-round all weights
    wtrans<<<dim3(BOT_/32, F_/32),   256>>>(W_pix1,    wt + O_PIX1, F_,  BOT_);
    wtrans<<<dim3(BOT_/32, F_/32),   256>>>(W_mem1,    wt + O_MEM1, F_,  BOT_);
    wtrans<<<dim3(512/32,  BOT_/32), 256>>>(W_pix_qkv, wt + O_PQKV, BOT_, 512);
    wtrans<<<dim3(512/32,  BOT_/32), 256>>>(W_mem_qkv, wt + O_MQKV, BOT_, 512);
    wtrans<<<dim3(F_/32,   TV_/32),  256>>>(W_mem3,    wt + O_MEM3, TV_, F_);
    wtrans<<<dim3(F_/32,   TV_/32),  256>>>(W_pix3,    wt + O_PIX3, TV_, F_);
    wtrans<<<dim3(FFN_/32, F_/32),   256>>>(W_ffn1,    wt + O_FFN1, F_,  FFN_);
    wtrans<<<dim3(F_/32,   FFN_/32), 256>>>(W_ffn2,    wt + O_FFN2, FFN_, F_);

    // stage 1: bottleneck convs
    gemm_mma<true,false,false><<<dim3(BOT_/128, MPIX/128), 256, GEMM_SMEM>>>(pixel_input,  wt + O_PIX1, bn_pix1, nullptr, pix, MPIX, BOT_, F_, F_);
    gemm_mma<true,false,false><<<dim3(BOT_/128, MMEM/128), 256, GEMM_SMEM>>>(memory_input, wt + O_MEM1, bn_mem1, nullptr, mem, MMEM, BOT_, F_, F_);
    // stage 2: qkv projections
    gemm_mma<false,false,false><<<dim3(512/128, MPIX/128), 256, GEMM_SMEM>>>(pix, wt + O_PQKV, bn_pix_qkv, nullptr, pqkv, MPIX, 512, BOT_, BOT_);
    gemm_mma<false,false,false><<<dim3(512/128, MMEM/128), 256, GEMM_SMEM>>>(mem, wt + O_MQKV, bn_mem_qkv, nullptr, mqkv, MMEM, 512, BOT_, BOT_);
    // memory path
    mem_attn_split<<<dim3(8, H_, B_), 128>>>(pqkv, mqkv, bn_mem_sim, mpart);
    mem_attn_combine<<<B_ * H_, 128>>>(mpart, bn_mem_ret, retmem);
    gemm_mma<true,true,false><<<dim3(F_/128,   MMEM/128), 256, GEMM_SMEM>>>(retmem, wt + O_MEM3, bn_mem3, memory_input, memout, MMEM, F_, TV_, TV_);
    gemm_mma<true,false,false><<<dim3(FFN_/128, MMEM/128), 256, GEMM_SMEM>>>(memout, wt + O_FFN1, bn_ffn1, nullptr, ffn, MMEM, FFN_, F_, F_);
    // ffn2: split-K x8 (K=2048 -> 8 chunks of 256), then reduce with BN+res+relu
    gemm_mma<false,false,true><<<dim3(1, MMEM/128, 8), 256, GEMM_SMEM>>>(ffn, wt + O_FFN2, nullptr, nullptr, skp, MMEM, F_, FFN_/8, FFN_);
    sk_reduce<<<(MMEM*F_)/256, 256>>>(skp, bn_ffn2, memout, out_mem, MMEM, 8);
    // pixel path
    pix_attn<<<dim3(L_/256, H_, B_), 128>>>(pqkv, mqkv, bn_pix_sim, bn_pix_ret, pret);
    gemm_mma<true,true,false><<<dim3(F_/128, MPIX/128), 256, GEMM_SMEM>>>(pret, wt + O_PIX3, bn_pix3, pixel_input, out_pix, MPIX, F_, TV_, TV_);
}

// round 8
// speedup vs baseline: 3.9467x; 1.4795x over previous
#include <cuda_runtime.h>
#include <cuda_fp16.h>
#include <cstdint>

// Problem constants
#define B_  8
#define L_  4096
#define N_  128
#define F_  128
#define H_  8
#define TV_ 256
#define BOT_ 256
#define FFN_ 2048
#define INV_C 0.9995003746877732f  // 1/sqrt(1+1e-3)
#define L2E  1.4426950408889634f

#define MPIX (B_*L_)   // 32768
#define MMEM (B_*N_)   // 1024

// -------------------- scratch (device globals; no allocation) --------------------
__device__ __half g_pixH [MPIX*BOT_];
__device__ float  g_pqkv[(size_t)MPIX*512];
__device__ __half g_memH [MMEM*BOT_];
__device__ float  g_mqkv[MMEM*512];
__device__ float  g_retmem[MMEM*TV_];
__device__ float  g_memout[MMEM*F_];
__device__ __half g_memoutH[MMEM*F_];
__device__ __half g_ffnH [MMEM*FFN_];
__device__ __half g_pretH[(size_t)MPIX*TV_];
__device__ float  g_mpart[64*8*34*128];
__device__ __half g_wth[917504];        // transposed fp16 weights
__device__ float  g_skpart[8*MMEM*F_];  // split-K partials for ffn2

// offsets into g_wth
#define O_PIX1 0
#define O_MEM1 32768
#define O_PQKV 65536
#define O_MQKV 196608
#define O_MEM3 327680
#define O_PIX3 360448
#define O_FFN1 393216
#define O_FFN2 655360

// -------------------- fast math --------------------
__device__ __forceinline__ float ex2a(float x){ float r; asm("ex2.approx.f32 %0, %1;" : "=f"(r):"f"(x)); return r; }
__device__ __forceinline__ float rcpa(float x){ float r; asm("rcp.approx.f32 %0, %1;" : "=f"(r):"f"(x)); return r; }
// pack two fp32 into half2 register: lo=a, hi=b
__device__ __forceinline__ uint32_t f22h(float a, float b){
    uint32_t r;
    asm("cvt.rn.f16x2.f32 %0, %1, %2;" : "=r"(r) : "f"(b), "f"(a));
    return r;
}

// fp16 mma: D[16x8] += A[16x16] * B[16x8]   (A row-major, B given as [n][k] rows)
__device__ __forceinline__ void mma16(float* d, const uint32_t* a, uint32_t b0, uint32_t b1){
    asm volatile("mma.sync.aligned.m16n8k16.row.col.f32.f16.f16.f32 "
        "{%0,%1,%2,%3}, {%4,%5,%6,%7}, {%8,%9}, {%0,%1,%2,%3};"
        : "+f"(d[0]), "+f"(d[1]), "+f"(d[2]), "+f"(d[3])
        : "r"(a[0]), "r"(a[1]), "r"(a[2]), "r"(a[3]), "r"(b0), "r"(b1));
}

// -------------------- fused weight transpose (fp32 [K][N] -> fp16 [N][K]) ----------
struct WTd { const float* in; __half* out; int K; int N; int tiles; };
struct WTargs { WTd d[8]; };

__global__ void __launch_bounds__(256) wtrans_all(WTargs a) {
    __shared__ float t[32][33];
    int tile = blockIdx.x;
    int i = 0;
    while (i < 7 && tile >= a.d[i].tiles) { tile -= a.d[i].tiles; i++; }
    const float* in = a.d[i].in;
    __half* out = a.d[i].out;
    const int K = a.d[i].K, Nn = a.d[i].N;
    const int ntx = Nn >> 5;
    const int bx = tile % ntx, by = tile / ntx;
    const int tx = threadIdx.x & 31, ty = threadIdx.x >> 5;
    #pragma unroll
    for (int j = 0; j < 4; j++)
        t[ty + j * 8][tx] = in[(size_t)(by * 32 + ty + j * 8) * Nn + bx * 32 + tx];
    __syncthreads();
    #pragma unroll
    for (int j = 0; j < 4; j++)
        out[(size_t)(bx * 32 + ty + j * 8) * K + by * 32 + tx] = __float2half_rn(t[tx][ty + j * 8]);
}

// -------------------- fp16 mma GEMM + BN epilogue --------------------
// C[M,Nn] = epi( A[M,K] @ Bt[Nn,K]^T ).  M%128==0, Nn%128==0, K%64==0.
// 128x128 tile, 256 threads (8 warps = 2M x 4N), BK=64 double-buffered fp16 smem.
// AH: A is fp16.  OH: 0=fp32 out, 1=fp16 out, 2=both.  PARTIAL: raw fp32 partials at C+z*M*Nn.
template<bool RELU, bool RES, bool PARTIAL, bool AH, int OH>
__global__ void __launch_bounds__(256) gemm_h(
        const void* __restrict__ A, const __half* __restrict__ Bt,
        const float* __restrict__ bn, const float* __restrict__ res,
        float* __restrict__ C, __half* __restrict__ Ch, int M, int Nn, int K, int lda) {
    extern __shared__ __half smh[];
    __half* sA = smh;               // 2 x 8192 halves
    __half* sB = smh + 16384;       // 2 x 8192 halves
    float* bns = (float*)(smh + 32768);
    const int tid = threadIdx.x;
    const int w = tid >> 5, lane = tid & 31;
    const int ly = lane >> 2, lx = lane & 3;
    const int wm = w >> 2, wn = w & 3;
    const int n0 = blockIdx.x * 128, m0 = blockIdx.y * 128;
    const int kbeg = PARTIAL ? blockIdx.z * K : 0;

    if (!PARTIAL && tid < 128) {
        bns[tid]       = bn[n0 + tid] * INV_C;
        bns[128 + tid] = bn[Nn + n0 + tid];
    }

    const int r = tid >> 1, hh = tid & 1;
    const float*  Af = (const float*)A  + (size_t)(m0 + r) * lda + kbeg + hh * 32;
    const __half* Ah = (const __half*)A + (size_t)(m0 + r) * lda + kbeg + hh * 32;
    const __half* Bp = Bt + (size_t)(n0 + r) * lda + kbeg + hh * 32;

    uint4 pa[4], pb[4];
    const int KB = K >> 6;

    // prefetch kb=0
    #pragma unroll
    for (int j = 0; j < 4; j++) {
        if (AH) {
            pa[j] = *(const uint4*)(Ah + j * 8);
        } else {
            float4 f0 = *(const float4*)(Af + j * 8);
            float4 f1 = *(const float4*)(Af + j * 8 + 4);
            pa[j].x = f22h(f0.x, f0.y); pa[j].y = f22h(f0.z, f0.w);
            pa[j].z = f22h(f1.x, f1.y); pa[j].w = f22h(f1.z, f1.w);
        }
        pb[j] = *(const uint4*)(Bp + j * 8);
    }
    {
        #pragma unroll
        for (int j = 0; j < 4; j++) {
            const int u = ((hh * 4 + j) ^ (r & 7)) << 3;
            *(uint4*)&sA[r * 64 + u] = pa[j];
            *(uint4*)&sB[r * 64 + u] = pb[j];
        }
    }
    __syncthreads();

    float acc[4][4][4];
    #pragma unroll
    for (int a = 0; a < 4; a++)
        #pragma unroll
        for (int b = 0; b < 4; b++)
            #pragma unroll
            for (int c = 0; c < 4; c++) acc[a][b][c] = 0.0f;

    for (int kb = 0; kb < KB; kb++) {
        if (kb + 1 < KB) {
            #pragma unroll
            for (int j = 0; j < 4; j++) {
                if (AH) {
                    pa[j] = *(const uint4*)(Ah + (kb + 1) * 64 + j * 8);
                } else {
                    float4 f0 = *(const float4*)(Af + (kb + 1) * 64 + j * 8);
                    float4 f1 = *(const float4*)(Af + (kb + 1) * 64 + j * 8 + 4);
                    pa[j].x = f22h(f0.x, f0.y); pa[j].y = f22h(f0.z, f0.w);
                    pa[j].z = f22h(f1.x, f1.y); pa[j].w = f22h(f1.z, f1.w);
                }
                pb[j] = *(const uint4*)(Bp + (size_t)(kb + 1) * 64 + j * 8);
            }
        }
        const __half* uA = sA + (kb & 1) * 8192;
        const __half* uB = sB + (kb & 1) * 8192;
        #pragma unroll
        for (int kt = 0; kt < 4; kt++) {
            const int sw0 = 2 * kt, sw1 = 2 * kt + 1;
            uint32_t af[4][4], bf[4][2];
            #pragma unroll
            for (int nt = 0; nt < 4; nt++) {
                const int n = wn * 32 + nt * 8 + ly;
                bf[nt][0] = *(const uint32_t*)&uB[n * 64 + ((sw0 ^ (n & 7)) << 3) + 2 * lx];
                bf[nt][1] = *(const uint32_t*)&uB[n * 64 + ((sw1 ^ (n & 7)) << 3) + 2 * lx];
            }
            #pragma unroll
            for (int mt = 0; mt < 4; mt++) {
                const int R = wm * 64 + mt * 16 + ly;
                const int u0 = ((sw0 ^ (R & 7)) << 3) + 2 * lx;
                const int u1 = ((sw1 ^ (R & 7)) << 3) + 2 * lx;
                af[mt][0] = *(const uint32_t*)&uA[R * 64 + u0];
                af[mt][1] = *(const uint32_t*)&uA[(R + 8) * 64 + u0];
                af[mt][2] = *(const uint32_t*)&uA[R * 64 + u1];
                af[mt][3] = *(const uint32_t*)&uA[(R + 8) * 64 + u1];
            }
            #pragma unroll
            for (int mt = 0; mt < 4; mt++)
                #pragma unroll
                for (int nt = 0; nt < 4; nt++)
                    mma16(acc[mt][nt], af[mt], bf[nt][0], bf[nt][1]);
        }
        if (kb + 1 < KB) {
            __half* dA = sA + ((kb + 1) & 1) * 8192;
            __half* dB = sB + ((kb + 1) & 1) * 8192;
            #pragma unroll
            for (int j = 0; j < 4; j++) {
                const int u = ((hh * 4 + j) ^ (r & 7)) << 3;
                *(uint4*)&dA[r * 64 + u] = pa[j];
                *(uint4*)&dB[r * 64 + u] = pb[j];
            }
            __syncthreads();
        }
    }

    if (PARTIAL) {
        float* Cp = C + (size_t)blockIdx.z * M * Nn;
        #pragma unroll
        for (int mt = 0; mt < 4; mt++) {
            const int rr = m0 + wm * 64 + mt * 16 + ly;
            #pragma unroll
            for (int nt = 0; nt < 4; nt++) {
                const int cc = n0 + wn * 32 + nt * 8 + lx * 2;
                float2 v0 = {acc[mt][nt][0], acc[mt][nt][1]};
                float2 v1 = {acc[mt][nt][2], acc[mt][nt][3]};
                *(float2*)&Cp[(size_t)rr * Nn + cc] = v0;
                *(float2*)&Cp[(size_t)(rr + 8) * Nn + cc] = v1;
            }
        }
    } else {
        #pragma unroll
        for (int mt = 0; mt < 4; mt++) {
            const int rr = m0 + wm * 64 + mt * 16 + ly;
            #pragma unroll
            for (int nt = 0; nt < 4; nt++) {
                const int lc = wn * 32 + nt * 8 + lx * 2;
                const int cc = n0 + lc;
                const float g0 = bns[lc], g1 = bns[lc + 1];
                const float b0 = bns[128 + lc], b1 = bns[128 + lc + 1];
                float2 v0, v1;
                v0.x = fmaf(acc[mt][nt][0], g0, b0);
                v0.y = fmaf(acc[mt][nt][1], g1, b1);
                v1.x = fmaf(acc[mt][nt][2], g0, b0);
                v1.y = fmaf(acc[mt][nt][3], g1, b1);
                const size_t i0 = (size_t)rr * Nn + cc;
                const size_t i1 = (size_t)(rr + 8) * Nn + cc;
                if (RES) {
                    float2 r0 = *(const float2*)&res[i0];
                    float2 r1 = *(const float2*)&res[i1];
                    v0.x += r0.x; v0.y += r0.y; v1.x += r1.x; v1.y += r1.y;
                }
                if (RELU) {
                    v0.x = fmaxf(v0.x, 0.0f); v0.y = fmaxf(v0.y, 0.0f);
                    v1.x = fmaxf(v1.x, 0.0f); v1.y = fmaxf(v1.y, 0.0f);
                }
                if (OH == 0 || OH == 2) {
                    *(float2*)&C[i0] = v0;
                    *(float2*)&C[i1] = v1;
                }
                if (OH >= 1) {
                    *(uint32_t*)&Ch[i0] = f22h(v0.x, v0.y);
                    *(uint32_t*)&Ch[i1] = f22h(v1.x, v1.y);
                }
            }
        }
    }
}

#define GEMM_SMEM (65536 + 1024)

// split-K reduce for ffn2
__global__ void __launch_bounds__(256) sk_reduce(
        const float* __restrict__ part, const float* __restrict__ bn,
        const float* __restrict__ res, float* __restrict__ out, int M, int SK) {
    const int idx = blockIdx.x * 256 + threadIdx.x;
    const int c = idx & 127;
    float s = 0.0f;
    for (int k = 0; k < SK; k++) s += part[(size_t)k * M * 128 + idx];
    float v = fmaf(s, bn[c] * INV_C, bn[128 + c]) + res[idx];
    out[idx] = fmaxf(v, 0.0f);
}

// -------------------- memory-path attention, split-K (FFMA; passing) --------------------
__global__ void __launch_bounds__(128) mem_attn_split(
        const float* __restrict__ pqkv, const float* __restrict__ mqkv,
        const float* __restrict__ bn_sim, float* __restrict__ part) {
    const int s = blockIdx.x, h = blockIdx.y, b = blockIdx.z;
    const int n = threadIdx.x;
    __shared__ float sk[128][16];
    __shared__ float sv[128][32];

    float q[16];
    {
        const float4* qp = (const float4*)(mqkv + (size_t)(b * 128 + n) * 512 + h * 16);
        #pragma unroll
        for (int j = 0; j < 4; j++) {
            float4 t = qp[j];
            q[j*4] = t.x; q[j*4+1] = t.y; q[j*4+2] = t.z; q[j*4+3] = t.w;
        }
    }
    const float gs = bn_sim[h] * INV_C;
    const float gb = bn_sim[8 + h];
    float mi = -1e30f, li = 0.0f;
    float acc[32] = {};

    for (int t = 0; t < 4; t++) {
        const float* src = pqkv + (size_t)(b * 4096 + (s * 4 + t) * 128 + n) * 512;
        {
            const float4* gk = (const float4*)(src + 128 + h * 16);
            float4* k4 = (float4*)&sk[n][0];
            k4[0] = gk[0]; k4[1] = gk[1]; k4[2] = gk[2]; k4[3] = gk[3];
            const float4* gv = (const float4*)(src + 256 + h * 32);
            float4* v4 = (float4*)&sv[n][0];
            #pragma unroll
            for (int i = 0; i < 8; i++) v4[i] = gv[i];
        }
        __syncthreads();
        for (int m = 0; m < 128; m++) {
            float dot = 0.0f;
            #pragma unroll
            for (int d = 0; d < 16; d++) dot = fmaf(q[d], sk[m][d], dot);
            float x = fmaf(dot, gs, gb);
            if (x <= mi) {
                float e = ex2a((x - mi) * L2E);
                li += e;
                #pragma unroll
                for (int d = 0; d < 32; d++) acc[d] = fmaf(e, sv[m][d], acc[d]);
            } else {
                float c = ex2a((mi - x) * L2E);
                li = fmaf(li, c, 1.0f);
                mi = x;
                #pragma unroll
                for (int d = 0; d < 32; d++) acc[d] = fmaf(acc[d], c, sv[m][d]);
            }
        }
        __syncthreads();
    }
    if (n < 16) {
        const float* src = mqkv + (size_t)(b * 128 + s * 16 + n) * 512;
        const float4* gk = (const float4*)(src + 128 + h * 16);
        float4* k4 = (float4*)&sk[n][0];
        k4[0] = gk[0]; k4[1] = gk[1]; k4[2] = gk[2]; k4[3] = gk[3];
        const float4* gv = (const float4*)(src + 256 + h * 32);
        float4* v4 = (float4*)&sv[n][0];
        #pragma unroll
        for (int i = 0; i < 8; i++) v4[i] = gv[i];
    }
    __syncthreads();
    for (int m = 0; m < 16; m++) {
        float dot = 0.0f;
        #pragma unroll
        for (int d = 0; d < 16; d++) dot = fmaf(q[d], sk[m][d], dot);
        float x = fmaf(dot, gs, gb);
        if (x <= mi) {
            float e = ex2a((x - mi) * L2E);
            li += e;
            #pragma unroll
            for (int d = 0; d < 32; d++) acc[d] = fmaf(e, sv[m][d], acc[d]);
        } else {
            float c = ex2a((mi - x) * L2E);
            li = fmaf(li, c, 1.0f);
            mi = x;
            #pragma unroll
            for (int d = 0; d < 32; d++) acc[d] = fmaf(acc[d], c, sv[m][d]);
        }
    }
    float* base = part + (size_t)(((b * 8 + h) * 8 + s) * 34) * 128;
    base[n] = mi;
    base[128 + n] = li;
    #pragma unroll
    for (int d = 0; d < 32; d++) base[(2 + d) * 128 + n] = acc[d];
}

__global__ void __launch_bounds__(128) mem_attn_combine(
        const float* __restrict__ part, const float* __restrict__ bn_ret,
        float* __restrict__ retmem) {
    const int bh = blockIdx.x;
    const int n = threadIdx.x;
    const int b = bh >> 3, h = bh & 7;
    float M = -1e30f;
    #pragma unroll
    for (int s = 0; s < 8; s++)
        M = fmaxf(M, part[(size_t)((bh * 8 + s) * 34) * 128 + n]);
    float Lsum = 0.0f;
    float acc[32] = {};
    #pragma unroll
    for (int s = 0; s < 8; s++) {
        const float* base = part + (size_t)((bh * 8 + s) * 34) * 128;
        float wgt = ex2a((base[n] - M) * L2E);
        Lsum = fmaf(base[128 + n], wgt, Lsum);
        #pragma unroll
        for (int d = 0; d < 32; d++)
            acc[d] = fmaf(wgt, base[(2 + d) * 128 + n], acc[d]);
    }
    float inv = rcpa(Lsum);
    inv = inv * (2.0f - Lsum * inv);
    float* out = retmem + (size_t)(b * 128 + n) * 256 + h * 32;
    #pragma unroll
    for (int d = 0; d < 32; d++) {
        float r = acc[d] * inv;
        r = fmaf(r, bn_ret[h * 32 + d] * INV_C, bn_ret[256 + h * 32 + d]);
        out[d] = fmaxf(r, 0.0f);
    }
}

// -------------------- pixel-path attention: tensor-core fused --------------------
// grid (L/128, H, B), 256 threads (8 warps x 16 query rows). Output fp16 pret.
__global__ void __launch_bounds__(256) pix_attn_tc(
        const float* __restrict__ pqkv, const float* __restrict__ mqkv,
        const float* __restrict__ bn_sim, const float* __restrict__ bn_ret,
        __half* __restrict__ pretH) {
    const int lt = blockIdx.x, h = blockIdx.y, b = blockIdx.z;
    const int tid = threadIdx.x;
    const int w = tid >> 5, lane = tid & 31;
    const int ly = lane >> 2, lx = lane & 3;

    __shared__ __half sK[128 * 16];    // [key][dim]
    __shared__ __half sVt[32 * 144];   // [dim][key], padded stride 144

    // stage K (fp32 -> fp16)
    {
        const int m = tid >> 1, hf = tid & 1;
        const float* src = mqkv + (size_t)(b * 128 + m) * 512 + 128 + h * 16 + hf * 8;
        float4 f0 = *(const float4*)src;
        float4 f1 = *(const float4*)(src + 4);
        uint4 u;
        u.x = f22h(f0.x, f0.y); u.y = f22h(f0.z, f0.w);
        u.z = f22h(f1.x, f1.y); u.w = f22h(f1.z, f1.w);
        *(uint4*)&sK[m * 16 + hf * 8] = u;
    }
    // stage V transposed
    {
        #pragma unroll
        for (int i = 0; i < 16; i++) {
            const int m = w * 16 + i;
            float v = mqkv[(size_t)(b * 128 + m) * 512 + 256 + h * 32 + lane];
            sVt[lane * 144 + m] = __float2half_rn(v);
        }
    }
    // Q fragment (16 query rows per warp)
    const int q0 = lt * 128 + w * 16;
    uint32_t aq[4];
    {
        const float* qp = pqkv + (size_t)(b * 4096 + q0) * 512 + h * 16;
        const float* r0 = qp + (size_t)ly * 512;
        const float* r1 = qp + (size_t)(ly + 8) * 512;
        float2 x0 = *(const float2*)(r0 + 2 * lx);
        float2 x1 = *(const float2*)(r1 + 2 * lx);
        float2 x2 = *(const float2*)(r0 + 2 * lx + 8);
        float2 x3 = *(const float2*)(r1 + 2 * lx + 8);
        aq[0] = f22h(x0.x, x0.y); aq[1] = f22h(x1.x, x1.y);
        aq[2] = f22h(x2.x, x2.y); aq[3] = f22h(x3.x, x3.y);
    }
    const float gs = bn_sim[h] * INV_C;
    const float gb = bn_sim[8 + h];
    __syncthreads();

    // S = Q @ K^T : 16 n-tiles of 8 keys
    float S[16][4];
    #pragma unroll
    for (int nt = 0; nt < 16; nt++) {
        S[nt][0] = S[nt][1] = S[nt][2] = S[nt][3] = 0.0f;
        uint32_t b0 = *(const uint32_t*)&sK[(nt * 8 + ly) * 16 + 2 * lx];
        uint32_t b1 = *(const uint32_t*)&sK[(nt * 8 + ly) * 16 + 8 + 2 * lx];
        mma16(S[nt], aq, b0, b1);
    }
    // sigmoid
    #pragma unroll
    for (int nt = 0; nt < 16; nt++)
        #pragma unroll
        for (int j = 0; j < 4; j++) {
            float x = fmaf(S[nt][j], gs, gb);
            S[nt][j] = rcpa(1.0f + ex2a(-x * L2E));
        }
    // O = S @ V : k-tiles of 16 keys, 4 n-tiles of 8 dims
    float O[4][4];
    #pragma unroll
    for (int i = 0; i < 4; i++) O[i][0] = O[i][1] = O[i][2] = O[i][3] = 0.0f;
    #pragma unroll
    for (int j = 0; j < 8; j++) {
        uint32_t as[4];
        as[0] = f22h(S[2*j][0],   S[2*j][1]);
        as[1] = f22h(S[2*j][2],   S[2*j][3]);
        as[2] = f22h(S[2*j+1][0], S[2*j+1][1]);
        as[3] = f22h(S[2*j+1][2], S[2*j+1][3]);
        #pragma unroll
        for (int nt = 0; nt < 4; nt++) {
            uint32_t b0 = *(const uint32_t*)&sVt[(nt * 8 + ly) * 144 + j * 16 + 2 * lx];
            uint32_t b1 = *(const uint32_t*)&sVt[(nt * 8 + ly) * 144 + j * 16 + 8 + 2 * lx];
            mma16(O[nt], as, b0, b1);
        }
    }
    // epilogue: BN + relu -> fp16 pret
    #pragma unroll
    for (int nt = 0; nt < 4; nt++) {
        const int d = nt * 8 + 2 * lx;
        const float g0 = bn_ret[h * 32 + d] * INV_C;
        const float g1 = bn_ret[h * 32 + d + 1] * INV_C;
        const float c0 = bn_ret[256 + h * 32 + d];
        const float c1 = bn_ret[256 + h * 32 + d + 1];
        const int l0 = q0 + ly, l1 = q0 + ly + 8;
        float v0 = fmaxf(fmaf(O[nt][0], g0, c0), 0.0f);
        float v1 = fmaxf(fmaf(O[nt][1], g1, c1), 0.0f);
        float v2 = fmaxf(fmaf(O[nt][2], g0, c0), 0.0f);
        float v3 = fmaxf(fmaf(O[nt][3], g1, c1), 0.0f);
        *(uint32_t*)&pretH[(size_t)(b * 4096 + l0) * 256 + h * 32 + d] = f22h(v0, v1);
        *(uint32_t*)&pretH[(size_t)(b * 4096 + l1) * 256 + h * 32 + d] = f22h(v2, v3);
    }
}

// -------------------- launch --------------------
extern "C" void kernel_launch(void* const* d_in, const int* in_sizes, int n_in,
                              void* d_out, int out_size) {
    const float* pixel_input  = (const float*)d_in[0];
    const float* memory_input = (const float*)d_in[1];
    const float* W_mem1     = (const float*)d_in[2];
    const float* bn_mem1    = (const float*)d_in[3];
    const float* W_pix1     = (const float*)d_in[4];
    const float* bn_pix1    = (const float*)d_in[5];
    const float* W_mem_qkv  = (const float*)d_in[6];
    const float* bn_mem_qkv = (const float*)d_in[7];
    const float* W_pix_qkv  = (const float*)d_in[8];
    const float* bn_pix_qkv = (const float*)d_in[9];
    const float* bn_mem_sim = (const float*)d_in[10];
    const float* bn_mem_ret = (const float*)d_in[11];
    const float* bn_pix_sim = (const float*)d_in[12];
    const float* bn_pix_ret = (const float*)d_in[13];
    const float* W_mem3     = (const float*)d_in[14];
    const float* bn_mem3    = (const float*)d_in[15];
    const float* W_pix3     = (const float*)d_in[16];
    const float* bn_pix3    = (const float*)d_in[17];
    const float* W_ffn1     = (const float*)d_in[18];
    const float* bn_ffn1    = (const float*)d_in[19];
    const float* W_ffn2     = (const float*)d_in[20];
    const float* bn_ffn2    = (const float*)d_in[21];

    float* out_pix = (float*)d_out;
    float* out_mem = (float*)d_out + (size_t)MPIX * F_;

    __half *pixH, *memH, *memoutH, *ffnH, *pretH, *wth;
    float *pqkv, *mqkv, *retmem, *memout, *mpart, *skp;
    cudaGetSymbolAddress((void**)&pixH,    g_pixH);
    cudaGetSymbolAddress((void**)&pqkv,    g_pqkv);
    cudaGetSymbolAddress((void**)&memH,    g_memH);
    cudaGetSymbolAddress((void**)&mqkv,    g_mqkv);
    cudaGetSymbolAddress((void**)&retmem,  g_retmem);
    cudaGetSymbolAddress((void**)&memout,  g_memout);
    cudaGetSymbolAddress((void**)&memoutH, g_memoutH);
    cudaGetSymbolAddress((void**)&ffnH,    g_ffnH);
    cudaGetSymbolAddress((void**)&pretH,   g_pretH);
    cudaGetSymbolAddress((void**)&mpart,   g_mpart);
    cudaGetSymbolAddress((void**)&wth,     g_wth);
    cudaGetSymbolAddress((void**)&skp,     g_skpart);

    cudaFuncSetAttribute(gemm_h<true,false,false,false,1>,  cudaFuncAttributeMaxDynamicSharedMemorySize, GEMM_SMEM);
    cudaFuncSetAttribute(gemm_h<false,false,false,true,0>,  cudaFuncAttributeMaxDynamicSharedMemorySize, GEMM_SMEM);
    cudaFuncSetAttribute(gemm_h<true,true,false,false,2>,   cudaFuncAttributeMaxDynamicSharedMemorySize, GEMM_SMEM);
    cudaFuncSetAttribute(gemm_h<true,false,false,true,1>,   cudaFuncAttributeMaxDynamicSharedMemorySize, GEMM_SMEM);
    cudaFuncSetAttribute(gemm_h<false,false,true,true,0>,   cudaFuncAttributeMaxDynamicSharedMemorySize, GEMM_SMEM);
    cudaFuncSetAttribute(gemm_h<true,true,false,true,0>,    cudaFuncAttributeMaxDynamicSharedMemorySize, GEMM_SMEM);

    // fused weight transpose (fp32 -> fp16, [K][N] -> [N][K]), one launch
    WTargs wa;
    wa.d[0] = {W_pix1,    wth + O_PIX1, F_,   BOT_, (BOT_/32)*(F_/32)};     // 32
    wa.d[1] = {W_mem1,    wth + O_MEM1, F_,   BOT_, (BOT_/32)*(F_/32)};     // 32
    wa.d[2] = {W_pix_qkv, wth + O_PQKV, BOT_, 512,  (512/32)*(BOT_/32)};    // 128
    wa.d[3] = {W_mem_qkv, wth + O_MQKV, BOT_, 512,  (512/32)*(BOT_/32)};    // 128
    wa.d[4] = {W_mem3,    wth + O_MEM3, TV_,  F_,   (F_/32)*(TV_/32)};      // 32
    wa.d[5] = {W_pix3,    wth + O_PIX3, TV_,  F_,   (F_/32)*(TV_/32)};      // 32
    wa.d[6] = {W_ffn1,    wth + O_FFN1, F_,   FFN_, (FFN_/32)*(F_/32)};     // 256
    wa.d[7] = {W_ffn2,    wth + O_FFN2, FFN_, F_,   (F_/32)*(FFN_/32)};     // 256
    wtrans_all<<<896, 256>>>(wa);

    // stage 1: bottleneck convs (out fp16)
    gemm_h<true,false,false,false,1><<<dim3(2, 256), 256, GEMM_SMEM>>>(pixel_input,  wth + O_PIX1, bn_pix1, nullptr, nullptr, pixH, MPIX, BOT_, F_, F_);
    gemm_h<true,false,false,false,1><<<dim3(2, 8),   256, GEMM_SMEM>>>(memory_input, wth + O_MEM1, bn_mem1, nullptr, nullptr, memH, MMEM, BOT_, F_, F_);
    // stage 2: qkv projections (A fp16, out fp32)
    gemm_h<false,false,false,true,0><<<dim3(4, 256), 256, GEMM_SMEM>>>(pixH, wth + O_PQKV, bn_pix_qkv, nullptr, pqkv, nullptr, MPIX, 512, BOT_, BOT_);
    gemm_h<false,false,false,true,0><<<dim3(4, 8),   256, GEMM_SMEM>>>(memH, wth + O_MQKV, bn_mem_qkv, nullptr, mqkv, nullptr, MMEM, 512, BOT_, BOT_);
    // memory path
    mem_attn_split<<<dim3(8, H_, B_), 128>>>(pqkv, mqkv, bn_mem_sim, mpart);
    mem_attn_combine<<<B_ * H_, 128>>>(mpart, bn_mem_ret, retmem);
    gemm_h<true,true,false,false,2><<<dim3(1, 8), 256, GEMM_SMEM>>>(retmem, wth + O_MEM3, bn_mem3, memory_input, memout, memoutH, MMEM, F_, TV_, TV_);
    gemm_h<true,false,false,true,1><<<dim3(16, 8), 256, GEMM_SMEM>>>(memoutH, wth + O_FFN1, bn_ffn1, nullptr, nullptr, ffnH, MMEM, FFN_, F_, F_);
    gemm_h<false,false,true,true,0><<<dim3(1, 8, 8), 256, GEMM_SMEM>>>(ffnH, wth + O_FFN2, nullptr, nullptr, skp, nullptr, MMEM, F_, FFN_/8, FFN_);
    sk_reduce<<<(MMEM*F_)/256, 256>>>(skp, bn_ffn2, memout, out_mem, MMEM, 8);
    // pixel path
    pix_attn_tc<<<dim3(L_/128, H_, B_), 256>>>(pqkv, mqkv, bn_pix_sim, bn_pix_ret, pretH);
    gemm_h<true,true,false,true,0><<<dim3(1, 256), 256, GEMM_SMEM>>>(pretH, wth + O_PIX3, bn_pix3, pixel_input, out_pix, nullptr, MPIX, F_, TV_, TV_);
}

// round 9
// speedup vs baseline: 4.2940x; 1.0880x over previous
#include <cuda_runtime.h>
#include <cuda_fp16.h>
#include <cstdint>

// Problem constants
#define B_  8
#define L_  4096
#define N_  128
#define F_  128
#define H_  8
#define TV_ 256
#define BOT_ 256
#define FFN_ 2048
#define INV_C 0.9995003746877732f  // 1/sqrt(1+1e-3)
#define L2E  1.4426950408889634f

#define MPIX (B_*L_)   // 32768
#define MMEM (B_*N_)   // 1024

// -------------------- scratch (device globals; no allocation) --------------------
__device__ __half g_pixinH[MPIX*F_];
__device__ __half g_meminH[MMEM*F_];
__device__ __half g_pixH [MPIX*BOT_];
__device__ float  g_pqkv[(size_t)MPIX*512];
__device__ __half g_memH [MMEM*BOT_];
__device__ float  g_mqkv[MMEM*512];
__device__ __half g_retmemH[MMEM*TV_];
__device__ float  g_memout[MMEM*F_];
__device__ __half g_memoutH[MMEM*F_];
__device__ __half g_ffnH [MMEM*FFN_];
__device__ __half g_pretH[(size_t)MPIX*TV_];
__device__ float  g_mpart[64*8*34*128];
__device__ __half g_wth[917504];        // transposed fp16 weights
__device__ float  g_skpart[8*MMEM*F_];  // split-K partials for ffn2

// offsets into g_wth
#define O_PIX1 0
#define O_MEM1 32768
#define O_PQKV 65536
#define O_MQKV 196608
#define O_MEM3 327680
#define O_PIX3 360448
#define O_FFN1 393216
#define O_FFN2 655360

// -------------------- fast math --------------------
__device__ __forceinline__ float ex2a(float x){ float r; asm("ex2.approx.f32 %0, %1;" : "=f"(r):"f"(x)); return r; }
__device__ __forceinline__ float rcpa(float x){ float r; asm("rcp.approx.f32 %0, %1;" : "=f"(r):"f"(x)); return r; }
__device__ __forceinline__ uint32_t f22h(float a, float b){
    uint32_t r;
    asm("cvt.rn.f16x2.f32 %0, %1, %2;" : "=r"(r) : "f"(b), "f"(a));
    return r;
}
__device__ __forceinline__ uint32_t smem_u32(const void* p){
    uint32_t a; asm("{ .reg .u64 t; cvta.to.shared.u64 t, %1; cvt.u32.u64 %0, t; }" : "=r"(a) : "l"(p));
    return a;
}
__device__ __forceinline__ void cpa16(uint32_t s, const void* g){
    asm volatile("cp.async.ca.shared.global [%0], [%1], 16;" :: "r"(s), "l"(g));
}
#define CP_COMMIT() asm volatile("cp.async.commit_group;" ::: "memory")

__device__ __forceinline__ void ldsm4(uint32_t* r, uint32_t addr){
    asm volatile("ldmatrix.sync.aligned.m8n8.x4.shared.b16 {%0,%1,%2,%3}, [%4];"
        : "=r"(r[0]), "=r"(r[1]), "=r"(r[2]), "=r"(r[3]) : "r"(addr));
}

// fp16 mma: D[16x8] += A[16x16] * B[16x8]
__device__ __forceinline__ void mma16(float* d, const uint32_t* a, uint32_t b0, uint32_t b1){
    asm volatile("mma.sync.aligned.m16n8k16.row.col.f32.f16.f16.f32 "
        "{%0,%1,%2,%3}, {%4,%5,%6,%7}, {%8,%9}, {%0,%1,%2,%3};"
        : "+f"(d[0]), "+f"(d[1]), "+f"(d[2]), "+f"(d[3])
        : "r"(a[0]), "r"(a[1]), "r"(a[2]), "r"(a[3]), "r"(b0), "r"(b1));
}

// -------------------- input convert fp32 -> fp16 --------------------
__global__ void __launch_bounds__(256) cvt_inputs(
        const float* __restrict__ a, __half* __restrict__ ah, int na,
        const float* __restrict__ b, __half* __restrict__ bh) {
    const int q = (blockIdx.x * 256 + threadIdx.x) * 4;
    if (q < na) {
        float4 v = *(const float4*)(a + q);
        uint2 u = {f22h(v.x, v.y), f22h(v.z, v.w)};
        *(uint2*)(ah + q) = u;
    } else {
        const int p = q - na;
        float4 v = *(const float4*)(b + p);
        uint2 u = {f22h(v.x, v.y), f22h(v.z, v.w)};
        *(uint2*)(bh + p) = u;
    }
}

// -------------------- fused weight transpose (fp32 [K][N] -> fp16 [N][K]) ----------
struct WTd { const float* in; __half* out; int K; int N; int tiles; };
struct WTargs { WTd d[8]; };

__global__ void __launch_bounds__(256) wtrans_all(WTargs a) {
    __shared__ float t[32][33];
    int tile = blockIdx.x;
    int i = 0;
    while (i < 7 && tile >= a.d[i].tiles) { tile -= a.d[i].tiles; i++; }
    const float* in = a.d[i].in;
    __half* out = a.d[i].out;
    const int K = a.d[i].K, Nn = a.d[i].N;
    const int ntx = Nn >> 5;
    const int bx = tile % ntx, by = tile / ntx;
    const int tx = threadIdx.x & 31, ty = threadIdx.x >> 5;
    #pragma unroll
    for (int j = 0; j < 4; j++)
        t[ty + j * 8][tx] = in[(size_t)(by * 32 + ty + j * 8) * Nn + bx * 32 + tx];
    __syncthreads();
    #pragma unroll
    for (int j = 0; j < 4; j++)
        out[(size_t)(bx * 32 + ty + j * 8) * K + by * 32 + tx] = __float2half_rn(t[tx][ty + j * 8]);
}

// -------------------- fp16 mma GEMM: cp.async + ldmatrix --------------------
// C[M,Nn] = epi( A[M,K] @ Bt[Nn,K]^T ); A fp16, Bt fp16 pre-transposed.
// M%128==0, Nn%128==0, K%64==0. 128x128 tile, 256 threads (8 warps = 2M x 4N),
// BK=64 double-buffered. OH: 0=fp32 out, 1=fp16 out, 2=both.
template<bool RELU, bool RES, bool PARTIAL, int OH>
__global__ void __launch_bounds__(256) gemm_h(
        const __half* __restrict__ A, const __half* __restrict__ Bt,
        const float* __restrict__ bn, const float* __restrict__ res,
        float* __restrict__ C, __half* __restrict__ Ch, int M, int Nn, int K, int lda) {
    extern __shared__ __half smh[];
    float* bns = (float*)(smh + 32768);
    const uint32_t sAu = smem_u32(smh);           // A: 2 x 16KB
    const uint32_t sBu = sAu + 32768;             // B: 2 x 16KB
    const int tid = threadIdx.x;
    const int w = tid >> 5, lane = tid & 31;
    const int lx = lane & 3;
    const int wm = w >> 2, wn = w & 3;
    const int n0 = blockIdx.x * 128, m0 = blockIdx.y * 128;
    const int kbeg = PARTIAL ? blockIdx.z * K : 0;

    if (!PARTIAL && tid < 128) {
        bns[tid]       = bn[n0 + tid] * INV_C;
        bns[128 + tid] = bn[Nn + n0 + tid];
    }

    // staging mapping: thread -> row r, half hh (32 k each)
    const int r = tid >> 1, hh = tid & 1;
    const __half* Ap = A  + (size_t)(m0 + r) * lda + kbeg + hh * 32;
    const __half* Bp = Bt + (size_t)(n0 + r) * lda + kbeg + hh * 32;
    uint32_t stA[4], stB[4];
    #pragma unroll
    for (int j = 0; j < 4; j++) {
        const uint32_t u = (uint32_t)(((hh * 4 + j) ^ (r & 7)) << 3);
        stA[j] = sAu + (uint32_t)(r * 64 + u) * 2;
        stB[j] = sBu + (uint32_t)(r * 64 + u) * 2;
    }

    // ldmatrix lane constants
    const int sub = lane >> 3;
    const int a_ro = (sub & 1) * 8 + (lane & 7);
    const int a_c  = sub >> 1;
    const int b_ro = (sub >> 1) * 8 + (lane & 7);
    const int b_c  = sub & 1;
    uint32_t rowA_b[4]; int rpA[4];
    #pragma unroll
    for (int mt = 0; mt < 4; mt++) {
        const int row = wm * 64 + mt * 16 + a_ro;
        rowA_b[mt] = (uint32_t)row * 128;
        rpA[mt] = row & 7;
    }
    uint32_t rowB_b[2]; int rpB[2];
    #pragma unroll
    for (int p = 0; p < 2; p++) {
        const int n = wn * 32 + p * 16 + b_ro;
        rowB_b[p] = (uint32_t)n * 128;
        rpB[p] = n & 7;
    }

    const int KB = K >> 6;
    // prologue: stage 0
    #pragma unroll
    for (int j = 0; j < 4; j++) {
        cpa16(stA[j], Ap + j * 8);
        cpa16(stB[j], Bp + j * 8);
    }
    CP_COMMIT();

    float acc[4][4][4];
    #pragma unroll
    for (int a = 0; a < 4; a++)
        #pragma unroll
        for (int b = 0; b < 4; b++)
            #pragma unroll
            for (int c = 0; c < 4; c++) acc[a][b][c] = 0.0f;

    for (int kb = 0; kb < KB; kb++) {
        if (kb + 1 < KB) {
            const uint32_t bo = (uint32_t)(((kb + 1) & 1) * 16384);
            #pragma unroll
            for (int j = 0; j < 4; j++) {
                cpa16(stA[j] + bo, Ap + (size_t)(kb + 1) * 64 + j * 8);
                cpa16(stB[j] + bo, Bp + (size_t)(kb + 1) * 64 + j * 8);
            }
            CP_COMMIT();
            asm volatile("cp.async.wait_group 1;" ::: "memory");
        } else {
            asm volatile("cp.async.wait_group 0;" ::: "memory");
        }
        __syncthreads();

        const uint32_t bufA = sAu + (uint32_t)((kb & 1) * 16384);
        const uint32_t bufB = sBu + (uint32_t)((kb & 1) * 16384);
        #pragma unroll
        for (int kt = 0; kt < 4; kt++) {
            const int ub = 2 * kt;
            uint32_t af[4][4], bf[4][2];
            #pragma unroll
            for (int p = 0; p < 2; p++) {
                uint32_t rr[4];
                ldsm4(rr, bufB + rowB_b[p] + (uint32_t)(((ub + b_c) ^ rpB[p]) << 4));
                bf[2*p][0]   = rr[0]; bf[2*p][1]   = rr[1];
                bf[2*p+1][0] = rr[2]; bf[2*p+1][1] = rr[3];
            }
            #pragma unroll
            for (int mt = 0; mt < 4; mt++)
                ldsm4(af[mt], bufA + rowA_b[mt] + (uint32_t)(((ub + a_c) ^ rpA[mt]) << 4));
            #pragma unroll
            for (int mt = 0; mt < 4; mt++)
                #pragma unroll
                for (int nt = 0; nt < 4; nt++)
                    mma16(acc[mt][nt], af[mt], bf[nt][0], bf[nt][1]);
        }
        __syncthreads();
    }

    const int ly = lane >> 2;
    if (PARTIAL) {
        float* Cp = C + (size_t)blockIdx.z * M * Nn;
        #pragma unroll
        for (int mt = 0; mt < 4; mt++) {
            const int rr = m0 + wm * 64 + mt * 16 + ly;
            #pragma unroll
            for (int nt = 0; nt < 4; nt++) {
                const int cc = n0 + wn * 32 + nt * 8 + lx * 2;
                float2 v0 = {acc[mt][nt][0], acc[mt][nt][1]};
                float2 v1 = {acc[mt][nt][2], acc[mt][nt][3]};
                *(float2*)&Cp[(size_t)rr * Nn + cc] = v0;
                *(float2*)&Cp[(size_t)(rr + 8) * Nn + cc] = v1;
            }
        }
    } else {
        #pragma unroll
        for (int mt = 0; mt < 4; mt++) {
            const int rr = m0 + wm * 64 + mt * 16 + ly;
            #pragma unroll
            for (int nt = 0; nt < 4; nt++) {
                const int lc = wn * 32 + nt * 8 + lx * 2;
                const int cc = n0 + lc;
                const float g0 = bns[lc], g1 = bns[lc + 1];
                const float b0 = bns[128 + lc], b1 = bns[128 + lc + 1];
                float2 v0, v1;
                v0.x = fmaf(acc[mt][nt][0], g0, b0);
                v0.y = fmaf(acc[mt][nt][1], g1, b1);
                v1.x = fmaf(acc[mt][nt][2], g0, b0);
                v1.y = fmaf(acc[mt][nt][3], g1, b1);
                const size_t i0 = (size_t)rr * Nn + cc;
                const size_t i1 = (size_t)(rr + 8) * Nn + cc;
                if (RES) {
                    float2 r0 = *(const float2*)&res[i0];
                    float2 r1 = *(const float2*)&res[i1];
                    v0.x += r0.x; v0.y += r0.y; v1.x += r1.x; v1.y += r1.y;
                }
                if (RELU) {
                    v0.x = fmaxf(v0.x, 0.0f); v0.y = fmaxf(v0.y, 0.0f);
                    v1.x = fmaxf(v1.x, 0.0f); v1.y = fmaxf(v1.y, 0.0f);
                }
                if (OH == 0 || OH == 2) {
                    *(float2*)&C[i0] = v0;
                    *(float2*)&C[i1] = v1;
                }
                if (OH >= 1) {
                    *(uint32_t*)&Ch[i0] = f22h(v0.x, v0.y);
                    *(uint32_t*)&Ch[i1] = f22h(v1.x, v1.y);
                }
            }
        }
    }
}

#define GEMM_SMEM (65536 + 1024)

// split-K reduce for ffn2
__global__ void __launch_bounds__(256) sk_reduce(
        const float* __restrict__ part, const float* __restrict__ bn,
        const float* __restrict__ res, float* __restrict__ out, int M, int SK) {
    const int idx = blockIdx.x * 256 + threadIdx.x;
    const int c = idx & 127;
    float s = 0.0f;
    for (int k = 0; k < SK; k++) s += part[(size_t)k * M * 128 + idx];
    float v = fmaf(s, bn[c] * INV_C, bn[128 + c]) + res[idx];
    out[idx] = fmaxf(v, 0.0f);
}

// -------------------- memory-path attention, split-K --------------------
__global__ void __launch_bounds__(128) mem_attn_split(
        const float* __restrict__ pqkv, const float* __restrict__ mqkv,
        const float* __restrict__ bn_sim, float* __restrict__ part) {
    const int s = blockIdx.x, h = blockIdx.y, b = blockIdx.z;
    const int n = threadIdx.x;
    __shared__ float sk[128][16];
    __shared__ float sv[128][32];

    float q[16];
    {
        const float4* qp = (const float4*)(mqkv + (size_t)(b * 128 + n) * 512 + h * 16);
        #pragma unroll
        for (int j = 0; j < 4; j++) {
            float4 t = qp[j];
            q[j*4] = t.x; q[j*4+1] = t.y; q[j*4+2] = t.z; q[j*4+3] = t.w;
        }
    }
    const float gs = bn_sim[h] * INV_C;
    const float gb = bn_sim[8 + h];
    float mi = -1e30f, li = 0.0f;
    float acc[32] = {};

    for (int t = 0; t < 4; t++) {
        const float* src = pqkv + (size_t)(b * 4096 + (s * 4 + t) * 128 + n) * 512;
        {
            const float4* gk = (const float4*)(src + 128 + h * 16);
            float4* k4 = (float4*)&sk[n][0];
            k4[0] = gk[0]; k4[1] = gk[1]; k4[2] = gk[2]; k4[3] = gk[3];
            const float4* gv = (const float4*)(src + 256 + h * 32);
            float4* v4 = (float4*)&sv[n][0];
            #pragma unroll
            for (int i = 0; i < 8; i++) v4[i] = gv[i];
        }
        __syncthreads();
        for (int m = 0; m < 128; m++) {
            float dot = 0.0f;
            #pragma unroll
            for (int d = 0; d < 16; d++) dot = fmaf(q[d], sk[m][d], dot);
            float x = fmaf(dot, gs, gb);
            if (x <= mi) {
                float e = ex2a((x - mi) * L2E);
                li += e;
                #pragma unroll
                for (int d = 0; d < 32; d++) acc[d] = fmaf(e, sv[m][d], acc[d]);
            } else {
                float c = ex2a((mi - x) * L2E);
                li = fmaf(li, c, 1.0f);
                mi = x;
                #pragma unroll
                for (int d = 0; d < 32; d++) acc[d] = fmaf(acc[d], c, sv[m][d]);
            }
        }
        __syncthreads();
    }
    if (n < 16) {
        const float* src = mqkv + (size_t)(b * 128 + s * 16 + n) * 512;
        const float4* gk = (const float4*)(src + 128 + h * 16);
        float4* k4 = (float4*)&sk[n][0];
        k4[0] = gk[0]; k4[1] = gk[1]; k4[2] = gk[2]; k4[3] = gk[3];
        const float4* gv = (const float4*)(src + 256 + h * 32);
        float4* v4 = (float4*)&sv[n][0];
        #pragma unroll
        for (int i = 0; i < 8; i++) v4[i] = gv[i];
    }
    __syncthreads();
    for (int m = 0; m < 16; m++) {
        float dot = 0.0f;
        #pragma unroll
        for (int d = 0; d < 16; d++) dot = fmaf(q[d], sk[m][d], dot);
        float x = fmaf(dot, gs, gb);
        if (x <= mi) {
            float e = ex2a((x - mi) * L2E);
            li += e;
            #pragma unroll
            for (int d = 0; d < 32; d++) acc[d] = fmaf(e, sv[m][d], acc[d]);
        } else {
            float c = ex2a((mi - x) * L2E);
            li = fmaf(li, c, 1.0f);
            mi = x;
            #pragma unroll
            for (int d = 0; d < 32; d++) acc[d] = fmaf(acc[d], c, sv[m][d]);
        }
    }
    float* base = part + (size_t)(((b * 8 + h) * 8 + s) * 34) * 128;
    base[n] = mi;
    base[128 + n] = li;
    #pragma unroll
    for (int d = 0; d < 32; d++) base[(2 + d) * 128 + n] = acc[d];
}

// combine: outputs fp16 retmem
__global__ void __launch_bounds__(128) mem_attn_combine(
        const float* __restrict__ part, const float* __restrict__ bn_ret,
        __half* __restrict__ retmemH) {
    const int bh = blockIdx.x;
    const int n = threadIdx.x;
    const int b = bh >> 3, h = bh & 7;
    float M = -1e30f;
    #pragma unroll
    for (int s = 0; s < 8; s++)
        M = fmaxf(M, part[(size_t)((bh * 8 + s) * 34) * 128 + n]);
    float Lsum = 0.0f;
    float acc[32] = {};
    #pragma unroll
    for (int s = 0; s < 8; s++) {
        const float* base = part + (size_t)((bh * 8 + s) * 34) * 128;
        float wgt = ex2a((base[n] - M) * L2E);
        Lsum = fmaf(base[128 + n], wgt, Lsum);
        #pragma unroll
        for (int d = 0; d < 32; d++)
            acc[d] = fmaf(wgt, base[(2 + d) * 128 + n], acc[d]);
    }
    float inv = rcpa(Lsum);
    inv = inv * (2.0f - Lsum * inv);
    __half* out = retmemH + (size_t)(b * 128 + n) * 256 + h * 32;
    #pragma unroll
    for (int d = 0; d < 16; d++) {
        float r0 = acc[2*d]   * inv;
        float r1 = acc[2*d+1] * inv;
        r0 = fmaxf(fmaf(r0, bn_ret[h * 32 + 2*d]   * INV_C, bn_ret[256 + h * 32 + 2*d]),   0.0f);
        r1 = fmaxf(fmaf(r1, bn_ret[h * 32 + 2*d+1] * INV_C, bn_ret[256 + h * 32 + 2*d+1]), 0.0f);
        *(uint32_t*)&out[2*d] = f22h(r0, r1);
    }
}

// -------------------- pixel-path attention: tensor-core fused --------------------
__global__ void __launch_bounds__(256) pix_attn_tc(
        const float* __restrict__ pqkv, const float* __restrict__ mqkv,
        const float* __restrict__ bn_sim, const float* __restrict__ bn_ret,
        __half* __restrict__ pretH) {
    const int lt = blockIdx.x, h = blockIdx.y, b = blockIdx.z;
    const int tid = threadIdx.x;
    const int w = tid >> 5, lane = tid & 31;
    const int ly = lane >> 2, lx = lane & 3;

    __shared__ __half sK[128 * 16];    // [key][dim]
    __shared__ __half sVt[32 * 144];   // [dim][key], padded stride 144

    {
        const int m = tid >> 1, hf = tid & 1;
        const float* src = mqkv + (size_t)(b * 128 + m) * 512 + 128 + h * 16 + hf * 8;
        float4 f0 = *(const float4*)src;
        float4 f1 = *(const float4*)(src + 4);
        uint4 u;
        u.x = f22h(f0.x, f0.y); u.y = f22h(f0.z, f0.w);
        u.z = f22h(f1.x, f1.y); u.w = f22h(f1.z, f1.w);
        *(uint4*)&sK[m * 16 + hf * 8] = u;
    }
    {
        #pragma unroll
        for (int i = 0; i < 16; i++) {
            const int m = w * 16 + i;
            float v = mqkv[(size_t)(b * 128 + m) * 512 + 256 + h * 32 + lane];
            sVt[lane * 144 + m] = __float2half_rn(v);
        }
    }
    const int q0 = lt * 128 + w * 16;
    uint32_t aq[4];
    {
        const float* qp = pqkv + (size_t)(b * 4096 + q0) * 512 + h * 16;
        const float* r0 = qp + (size_t)ly * 512;
        const float* r1 = qp + (size_t)(ly + 8) * 512;
        float2 x0 = *(const float2*)(r0 + 2 * lx);
        float2 x1 = *(const float2*)(r1 + 2 * lx);
        float2 x2 = *(const float2*)(r0 + 2 * lx + 8);
        float2 x3 = *(const float2*)(r1 + 2 * lx + 8);
        aq[0] = f22h(x0.x, x0.y); aq[1] = f22h(x1.x, x1.y);
        aq[2] = f22h(x2.x, x2.y); aq[3] = f22h(x3.x, x3.y);
    }
    const float gs = bn_sim[h] * INV_C;
    const float gb = bn_sim[8 + h];
    __syncthreads();

    float S[16][4];
    #pragma unroll
    for (int nt = 0; nt < 16; nt++) {
        S[nt][0] = S[nt][1] = S[nt][2] = S[nt][3] = 0.0f;
        uint32_t b0 = *(const uint32_t*)&sK[(nt * 8 + ly) * 16 + 2 * lx];
        uint32_t b1 = *(const uint32_t*)&sK[(nt * 8 + ly) * 16 + 8 + 2 * lx];
        mma16(S[nt], aq, b0, b1);
    }
    #pragma unroll
    for (int nt = 0; nt < 16; nt++)
        #pragma unroll
        for (int j = 0; j < 4; j++) {
            float x = fmaf(S[nt][j], gs, gb);
            S[nt][j] = rcpa(1.0f + ex2a(-x * L2E));
        }
    float O[4][4];
    #pragma unroll
    for (int i = 0; i < 4; i++) O[i][0] = O[i][1] = O[i][2] = O[i][3] = 0.0f;
    #pragma unroll
    for (int j = 0; j < 8; j++) {
        uint32_t as[4];
        as[0] = f22h(S[2*j][0],   S[2*j][1]);
        as[1] = f22h(S[2*j][2],   S[2*j][3]);
        as[2] = f22h(S[2*j+1][0], S[2*j+1][1]);
        as[3] = f22h(S[2*j+1][2], S[2*j+1][3]);
        #pragma unroll
        for (int nt = 0; nt < 4; nt++) {
            uint32_t b0 = *(const uint32_t*)&sVt[(nt * 8 + ly) * 144 + j * 16 + 2 * lx];
            uint32_t b1 = *(const uint32_t*)&sVt[(nt * 8 + ly) * 144 + j * 16 + 8 + 2 * lx];
            mma16(O[nt], as, b0, b1);
        }
    }
    #pragma unroll
    for (int nt = 0; nt < 4; nt++) {
        const int d = nt * 8 + 2 * lx;
        const float g0 = bn_ret[h * 32 + d] * INV_C;
        const float g1 = bn_ret[h * 32 + d + 1] * INV_C;
        const float c0 = bn_ret[256 + h * 32 + d];
        const float c1 = bn_ret[256 + h * 32 + d + 1];
        const int l0 = q0 + ly, l1 = q0 + ly + 8;
        float v0 = fmaxf(fmaf(O[nt][0], g0, c0), 0.0f);
        float v1 = fmaxf(fmaf(O[nt][1], g1, c1), 0.0f);
        float v2 = fmaxf(fmaf(O[nt][2], g0, c0), 0.0f);
        float v3 = fmaxf(fmaf(O[nt][3], g1, c1), 0.0f);
        *(uint32_t*)&pretH[(size_t)(b * 4096 + l0) * 256 + h * 32 + d] = f22h(v0, v1);
        *(uint32_t*)&pretH[(size_t)(b * 4096 + l1) * 256 + h * 32 + d] = f22h(v2, v3);
    }
}

// -------------------- launch --------------------
extern "C" void kernel_launch(void* const* d_in, const int* in_sizes, int n_in,
                              void* d_out, int out_size) {
    const float* pixel_input  = (const float*)d_in[0];
    const float* memory_input = (const float*)d_in[1];
    const float* W_mem1     = (const float*)d_in[2];
    const float* bn_mem1    = (const float*)d_in[3];
    const float* W_pix1     = (const float*)d_in[4];
    const float* bn_pix1    = (const float*)d_in[5];
    const float* W_mem_qkv  = (const float*)d_in[6];
    const float* bn_mem_qkv = (const float*)d_in[7];
    const float* W_pix_qkv  = (const float*)d_in[8];
    const float* bn_pix_qkv = (const float*)d_in[9];
    const float* bn_mem_sim = (const float*)d_in[10];
    const float* bn_mem_ret = (const float*)d_in[11];
    const float* bn_pix_sim = (const float*)d_in[12];
    const float* bn_pix_ret = (const float*)d_in[13];
    const float* W_mem3     = (const float*)d_in[14];
    const float* bn_mem3    = (const float*)d_in[15];
    const float* W_pix3     = (const float*)d_in[16];
    const float* bn_pix3    = (const float*)d_in[17];
    const float* W_ffn1     = (const float*)d_in[18];
    const float* bn_ffn1    = (const float*)d_in[19];
    const float* W_ffn2     = (const float*)d_in[20];
    const float* bn_ffn2    = (const float*)d_in[21];

    float* out_pix = (float*)d_out;
    float* out_mem = (float*)d_out + (size_t)MPIX * F_;

    __half *pixinH, *meminH, *pixH, *memH, *retmemH, *memoutH, *ffnH, *pretH, *wth;
    float *pqkv, *mqkv, *memout, *mpart, *skp;
    cudaGetSymbolAddress((void**)&pixinH,  g_pixinH);
    cudaGetSymbolAddress((void**)&meminH,  g_meminH);
    cudaGetSymbolAddress((void**)&pixH,    g_pixH);
    cudaGetSymbolAddress((void**)&pqkv,    g_pqkv);
    cudaGetSymbolAddress((void**)&memH,    g_memH);
    cudaGetSymbolAddress((void**)&mqkv,    g_mqkv);
    cudaGetSymbolAddress((void**)&retmemH, g_retmemH);
    cudaGetSymbolAddress((void**)&memout,  g_memout);
    cudaGetSymbolAddress((void**)&memoutH, g_memoutH);
    cudaGetSymbolAddress((void**)&ffnH,    g_ffnH);
    cudaGetSymbolAddress((void**)&pretH,   g_pretH);
    cudaGetSymbolAddress((void**)&mpart,   g_mpart);
    cudaGetSymbolAddress((void**)&wth,     g_wth);
    cudaGetSymbolAddress((void**)&skp,     g_skpart);

    cudaFuncSetAttribute(gemm_h<true,false,false,1>, cudaFuncAttributeMaxDynamicSharedMemorySize, GEMM_SMEM);
    cudaFuncSetAttribute(gemm_h<false,false,false,0>,cudaFuncAttributeMaxDynamicSharedMemorySize, GEMM_SMEM);
    cudaFuncSetAttribute(gemm_h<true,true,false,2>,  cudaFuncAttributeMaxDynamicSharedMemorySize, GEMM_SMEM);
    cudaFuncSetAttribute(gemm_h<false,false,true,0>, cudaFuncAttributeMaxDynamicSharedMemorySize, GEMM_SMEM);
    cudaFuncSetAttribute(gemm_h<true,true,false,0>,  cudaFuncAttributeMaxDynamicSharedMemorySize, GEMM_SMEM);

    // input conversions + fused weight transpose
    cvt_inputs<<<(MPIX*F_ + MMEM*F_) / 1024, 256>>>(pixel_input, pixinH, MPIX*F_, memory_input, meminH);
    WTargs wa;
    wa.d[0] = {W_pix1,    wth + O_PIX1, F_,   BOT_, (BOT_/32)*(F_/32)};
    wa.d[1] = {W_mem1,    wth + O_MEM1, F_,   BOT_, (BOT_/32)*(F_/32)};
    wa.d[2] = {W_pix_qkv, wth + O_PQKV, BOT_, 512,  (512/32)*(BOT_/32)};
    wa.d[3] = {W_mem_qkv, wth + O_MQKV, BOT_, 512,  (512/32)*(BOT_/32)};
    wa.d[4] = {W_mem3,    wth + O_MEM3, TV_,  F_,   (F_/32)*(TV_/32)};
    wa.d[5] = {W_pix3,    wth + O_PIX3, TV_,  F_,   (F_/32)*(TV_/32)};
    wa.d[6] = {W_ffn1,    wth + O_FFN1, F_,   FFN_, (FFN_/32)*(F_/32)};
    wa.d[7] = {W_ffn2,    wth + O_FFN2, FFN_, F_,   (F_/32)*(FFN_/32)};
    wtrans_all<<<896, 256>>>(wa);

    // stage 1: bottleneck convs (out fp16)
    gemm_h<true,false,false,1><<<dim3(2, 256), 256, GEMM_SMEM>>>(pixinH, wth + O_PIX1, bn_pix1, nullptr, nullptr, pixH, MPIX, BOT_, F_, F_);
    gemm_h<true,false,false,1><<<dim3(2, 8),   256, GEMM_SMEM>>>(meminH, wth + O_MEM1, bn_mem1, nullptr, nullptr, memH, MMEM, BOT_, F_, F_);
    // stage 2: qkv projections (out fp32)
    gemm_h<false,false,false,0><<<dim3(4, 256), 256, GEMM_SMEM>>>(pixH, wth + O_PQKV, bn_pix_qkv, nullptr, pqkv, nullptr, MPIX, 512, BOT_, BOT_);
    gemm_h<false,false,false,0><<<dim3(4, 8),   256, GEMM_SMEM>>>(memH, wth + O_MQKV, bn_mem_qkv, nullptr, mqkv, nullptr, MMEM, 512, BOT_, BOT_);
    // memory path
    mem_attn_split<<<dim3(8, H_, B_), 128>>>(pqkv, mqkv, bn_mem_sim, mpart);
    mem_attn_combine<<<B_ * H_, 128>>>(mpart, bn_mem_ret, retmemH);
    gemm_h<true,true,false,2><<<dim3(1, 8), 256, GEMM_SMEM>>>(retmemH, wth + O_MEM3, bn_mem3, memory_input, memout, memoutH, MMEM, F_, TV_, TV_);
    gemm_h<true,false,false,1><<<dim3(16, 8), 256, GEMM_SMEM>>>(memoutH, wth + O_FFN1, bn_ffn1, nullptr, nullptr, ffnH, MMEM, FFN_, F_, F_);
    gemm_h<false,false,true,0><<<dim3(1, 8, 8), 256, GEMM_SMEM>>>(ffnH, wth + O_FFN2, nullptr, nullptr, skp, nullptr, MMEM, F_, FFN_/8, FFN_);
    sk_reduce<<<(MMEM*F_)/256, 256>>>(skp, bn_ffn2, memout, out_mem, MMEM, 8);
    // pixel path
    pix_attn_tc<<<dim3(L_/128, H_, B_), 256>>>(pqkv, mqkv, bn_pix_sim, bn_pix_ret, pretH);
    gemm_h<true,true,false,0><<<dim3(1, 256), 256, GEMM_SMEM>>>(pretH, wth + O_PIX3, bn_pix3, pixel_input, out_pix, nullptr, MPIX, F_, TV_, TV_);
}

// round 10
// speedup vs baseline: 7.0774x; 1.6482x over previous
#include <cuda_runtime.h>
#include <cuda_fp16.h>
#include <cstdint>

// Problem constants
#define B_  8
#define L_  4096
#define N_  128
#define F_  128
#define H_  8
#define TV_ 256
#define BOT_ 256
#define FFN_ 2048
#define INV_C 0.9995003746877732f  // 1/sqrt(1+1e-3)
#define L2E  1.4426950408889634f

#define MPIX (B_*L_)   // 32768
#define MMEM (B_*N_)   // 1024
#define NSPLIT 9       // 8 pixel-key splits + 1 mem-key split

// -------------------- scratch (device globals; no allocation) --------------------
__device__ __half g_pixinH[MPIX*F_];
__device__ __half g_meminH[MMEM*F_];
__device__ __half g_pixH [MPIX*BOT_];
__device__ float  g_pqkv[(size_t)MPIX*512];
__device__ __half g_memH [MMEM*BOT_];
__device__ float  g_mqkv[MMEM*512];
__device__ __half g_retmemH[MMEM*TV_];
__device__ float  g_memout[MMEM*F_];
__device__ __half g_memoutH[MMEM*F_];
__device__ __half g_ffnH [MMEM*FFN_];
__device__ __half g_pretH[(size_t)MPIX*TV_];
__device__ float  g_mpart[64*NSPLIT*34*128];
__device__ __half g_wth[917504];        // transposed fp16 weights
__device__ float  g_skpart[8*MMEM*F_];  // split-K partials for ffn2

// offsets into g_wth
#define O_PIX1 0
#define O_MEM1 32768
#define O_PQKV 65536
#define O_MQKV 196608
#define O_MEM3 327680
#define O_PIX3 360448
#define O_FFN1 393216
#define O_FFN2 655360

// -------------------- fast math --------------------
__device__ __forceinline__ float ex2a(float x){ float r; asm("ex2.approx.f32 %0, %1;" : "=f"(r):"f"(x)); return r; }
__device__ __forceinline__ float rcpa(float x){ float r; asm("rcp.approx.f32 %0, %1;" : "=f"(r):"f"(x)); return r; }
__device__ __forceinline__ uint32_t f22h(float a, float b){
    uint32_t r;
    asm("cvt.rn.f16x2.f32 %0, %1, %2;" : "=r"(r) : "f"(b), "f"(a));
    return r;
}
__device__ __forceinline__ uint32_t smem_u32(const void* p){
    uint32_t a; asm("{ .reg .u64 t; cvta.to.shared.u64 t, %1; cvt.u32.u64 %0, t; }" : "=r"(a) : "l"(p));
    return a;
}
__device__ __forceinline__ void cpa16(uint32_t s, const void* g){
    asm volatile("cp.async.ca.shared.global [%0], [%1], 16;" :: "r"(s), "l"(g));
}
#define CP_COMMIT() asm volatile("cp.async.commit_group;" ::: "memory")

__device__ __forceinline__ void ldsm4(uint32_t* r, uint32_t addr){
    asm volatile("ldmatrix.sync.aligned.m8n8.x4.shared.b16 {%0,%1,%2,%3}, [%4];"
        : "=r"(r[0]), "=r"(r[1]), "=r"(r[2]), "=r"(r[3]) : "r"(addr));
}

// fp16 mma: D[16x8] += A[16x16] * B[16x8]
__device__ __forceinline__ void mma16(float* d, const uint32_t* a, uint32_t b0, uint32_t b1){
    asm volatile("mma.sync.aligned.m16n8k16.row.col.f32.f16.f16.f32 "
        "{%0,%1,%2,%3}, {%4,%5,%6,%7}, {%8,%9}, {%0,%1,%2,%3};"
        : "+f"(d[0]), "+f"(d[1]), "+f"(d[2]), "+f"(d[3])
        : "r"(a[0]), "r"(a[1]), "r"(a[2]), "r"(a[3]), "r"(b0), "r"(b1));
}

// -------------------- input convert fp32 -> fp16 --------------------
__global__ void __launch_bounds__(256) cvt_inputs(
        const float* __restrict__ a, __half* __restrict__ ah, int na,
        const float* __restrict__ b, __half* __restrict__ bh) {
    const int q = (blockIdx.x * 256 + threadIdx.x) * 4;
    if (q < na) {
        float4 v = *(const float4*)(a + q);
        uint2 u = {f22h(v.x, v.y), f22h(v.z, v.w)};
        *(uint2*)(ah + q) = u;
    } else {
        const int p = q - na;
        float4 v = *(const float4*)(b + p);
        uint2 u = {f22h(v.x, v.y), f22h(v.z, v.w)};
        *(uint2*)(bh + p) = u;
    }
}

// -------------------- fused weight transpose (fp32 [K][N] -> fp16 [N][K]) ----------
struct WTd { const float* in; __half* out; int K; int N; int tiles; };
struct WTargs { WTd d[8]; };

__global__ void __launch_bounds__(256) wtrans_all(WTargs a) {
    __shared__ float t[32][33];
    int tile = blockIdx.x;
    int i = 0;
    while (i < 7 && tile >= a.d[i].tiles) { tile -= a.d[i].tiles; i++; }
    const float* in = a.d[i].in;
    __half* out = a.d[i].out;
    const int K = a.d[i].K, Nn = a.d[i].N;
    const int ntx = Nn >> 5;
    const int bx = tile % ntx, by = tile / ntx;
    const int tx = threadIdx.x & 31, ty = threadIdx.x >> 5;
    #pragma unroll
    for (int j = 0; j < 4; j++)
        t[ty + j * 8][tx] = in[(size_t)(by * 32 + ty + j * 8) * Nn + bx * 32 + tx];
    __syncthreads();
    #pragma unroll
    for (int j = 0; j < 4; j++)
        out[(size_t)(bx * 32 + ty + j * 8) * K + by * 32 + tx] = __float2half_rn(t[tx][ty + j * 8]);
}

// -------------------- fp16 mma GEMM: cp.async + ldmatrix --------------------
// C[M,Nn] = epi( A[M,K] @ Bt[Nn,K]^T ); A fp16, Bt fp16 pre-transposed.
// 128x128 tile, 256 threads (8 warps = 2M x 4N), BK=64 double-buffered.
// OH: 0=fp32 out, 1=fp16 out, 2=both.
template<bool RELU, bool RES, bool PARTIAL, int OH>
__global__ void __launch_bounds__(256, 2) gemm_h(
        const __half* __restrict__ A, const __half* __restrict__ Bt,
        const float* __restrict__ bn, const float* __restrict__ res,
        float* __restrict__ C, __half* __restrict__ Ch, int M, int Nn, int K, int lda) {
    extern __shared__ __half smh[];
    float* bns = (float*)(smh + 32768);
    const uint32_t sAu = smem_u32(smh);           // A: 2 x 16KB
    const uint32_t sBu = sAu + 32768;             // B: 2 x 16KB
    const int tid = threadIdx.x;
    const int w = tid >> 5, lane = tid & 31;
    const int lx = lane & 3;
    const int wm = w >> 2, wn = w & 3;
    const int n0 = blockIdx.x * 128, m0 = blockIdx.y * 128;
    const int kbeg = PARTIAL ? blockIdx.z * K : 0;

    if (!PARTIAL && tid < 128) {
        bns[tid]       = bn[n0 + tid] * INV_C;
        bns[128 + tid] = bn[Nn + n0 + tid];
    }

    const int r = tid >> 1, hh = tid & 1;
    const __half* Ap = A  + (size_t)(m0 + r) * lda + kbeg + hh * 32;
    const __half* Bp = Bt + (size_t)(n0 + r) * lda + kbeg + hh * 32;
    uint32_t stA[4], stB[4];
    #pragma unroll
    for (int j = 0; j < 4; j++) {
        const uint32_t u = (uint32_t)(((hh * 4 + j) ^ (r & 7)) << 3);
        stA[j] = sAu + (uint32_t)(r * 64 + u) * 2;
        stB[j] = sBu + (uint32_t)(r * 64 + u) * 2;
    }

    const int sub = lane >> 3;
    const int a_ro = (sub & 1) * 8 + (lane & 7);
    const int a_c  = sub >> 1;
    const int b_ro = (sub >> 1) * 8 + (lane & 7);
    const int b_c  = sub & 1;
    uint32_t rowA_b[4]; int rpA[4];
    #pragma unroll
    for (int mt = 0; mt < 4; mt++) {
        const int row = wm * 64 + mt * 16 + a_ro;
        rowA_b[mt] = (uint32_t)row * 128;
        rpA[mt] = row & 7;
    }
    uint32_t rowB_b[2]; int rpB[2];
    #pragma unroll
    for (int p = 0; p < 2; p++) {
        const int n = wn * 32 + p * 16 + b_ro;
        rowB_b[p] = (uint32_t)n * 128;
        rpB[p] = n & 7;
    }

    const int KB = K >> 6;
    #pragma unroll
    for (int j = 0; j < 4; j++) {
        cpa16(stA[j], Ap + j * 8);
        cpa16(stB[j], Bp + j * 8);
    }
    CP_COMMIT();

    float acc[4][4][4];
    #pragma unroll
    for (int a = 0; a < 4; a++)
        #pragma unroll
        for (int b = 0; b < 4; b++)
            #pragma unroll
            for (int c = 0; c < 4; c++) acc[a][b][c] = 0.0f;

    for (int kb = 0; kb < KB; kb++) {
        if (kb + 1 < KB) {
            const uint32_t bo = (uint32_t)(((kb + 1) & 1) * 16384);
            #pragma unroll
            for (int j = 0; j < 4; j++) {
                cpa16(stA[j] + bo, Ap + (size_t)(kb + 1) * 64 + j * 8);
                cpa16(stB[j] + bo, Bp + (size_t)(kb + 1) * 64 + j * 8);
            }
            CP_COMMIT();
            asm volatile("cp.async.wait_group 1;" ::: "memory");
        } else {
            asm volatile("cp.async.wait_group 0;" ::: "memory");
        }
        __syncthreads();

        const uint32_t bufA = sAu + (uint32_t)((kb & 1) * 16384);
        const uint32_t bufB = sBu + (uint32_t)((kb & 1) * 16384);
        #pragma unroll
        for (int kt = 0; kt < 4; kt++) {
            const int ub = 2 * kt;
            uint32_t af[4][4], bf[4][2];
            #pragma unroll
            for (int p = 0; p < 2; p++) {
                uint32_t rr[4];
                ldsm4(rr, bufB + rowB_b[p] + (uint32_t)(((ub + b_c) ^ rpB[p]) << 4));
                bf[2*p][0]   = rr[0]; bf[2*p][1]   = rr[1];
                bf[2*p+1][0] = rr[2]; bf[2*p+1][1] = rr[3];
            }
            #pragma unroll
            for (int mt = 0; mt < 4; mt++)
                ldsm4(af[mt], bufA + rowA_b[mt] + (uint32_t)(((ub + a_c) ^ rpA[mt]) << 4));
            #pragma unroll
            for (int mt = 0; mt < 4; mt++)
                #pragma unroll
                for (int nt = 0; nt < 4; nt++)
                    mma16(acc[mt][nt], af[mt], bf[nt][0], bf[nt][1]);
        }
        __syncthreads();
    }

    const int ly = lane >> 2;
    if (PARTIAL) {
        float* Cp = C + (size_t)blockIdx.z * M * Nn;
        #pragma unroll
        for (int mt = 0; mt < 4; mt++) {
            const int rr = m0 + wm * 64 + mt * 16 + ly;
            #pragma unroll
            for (int nt = 0; nt < 4; nt++) {
                const int cc = n0 + wn * 32 + nt * 8 + lx * 2;
                float2 v0 = {acc[mt][nt][0], acc[mt][nt][1]};
                float2 v1 = {acc[mt][nt][2], acc[mt][nt][3]};
                *(float2*)&Cp[(size_t)rr * Nn + cc] = v0;
                *(float2*)&Cp[(size_t)(rr + 8) * Nn + cc] = v1;
            }
        }
    } else {
        #pragma unroll
        for (int mt = 0; mt < 4; mt++) {
            const int rr = m0 + wm * 64 + mt * 16 + ly;
            #pragma unroll
            for (int nt = 0; nt < 4; nt++) {
                const int lc = wn * 32 + nt * 8 + lx * 2;
                const int cc = n0 + lc;
                const float g0 = bns[lc], g1 = bns[lc + 1];
                const float b0 = bns[128 + lc], b1 = bns[128 + lc + 1];
                float2 v0, v1;
                v0.x = fmaf(acc[mt][nt][0], g0, b0);
                v0.y = fmaf(acc[mt][nt][1], g1, b1);
                v1.x = fmaf(acc[mt][nt][2], g0, b0);
                v1.y = fmaf(acc[mt][nt][3], g1, b1);
                const size_t i0 = (size_t)rr * Nn + cc;
                const size_t i1 = (size_t)(rr + 8) * Nn + cc;
                if (RES) {
                    float2 r0 = *(const float2*)&res[i0];
                    float2 r1 = *(const float2*)&res[i1];
                    v0.x += r0.x; v0.y += r0.y; v1.x += r1.x; v1.y += r1.y;
                }
                if (RELU) {
                    v0.x = fmaxf(v0.x, 0.0f); v0.y = fmaxf(v0.y, 0.0f);
                    v1.x = fmaxf(v1.x, 0.0f); v1.y = fmaxf(v1.y, 0.0f);
                }
                if (OH == 0 || OH == 2) {
                    *(float2*)&C[i0] = v0;
                    *(float2*)&C[i1] = v1;
                }
                if (OH >= 1) {
                    *(uint32_t*)&Ch[i0] = f22h(v0.x, v0.y);
                    *(uint32_t*)&Ch[i1] = f22h(v1.x, v1.y);
                }
            }
        }
    }
}

#define GEMM_SMEM (65536 + 1024)

// split-K reduce for ffn2
__global__ void __launch_bounds__(256) sk_reduce(
        const float* __restrict__ part, const float* __restrict__ bn,
        const float* __restrict__ res, float* __restrict__ out, int M, int SK) {
    const int idx = blockIdx.x * 256 + threadIdx.x;
    const int c = idx & 127;
    float s = 0.0f;
    for (int k = 0; k < SK; k++) s += part[(size_t)k * M * 128 + idx];
    float v = fmaf(s, bn[c] * INV_C, bn[128 + c]) + res[idx];
    out[idx] = fmaxf(v, 0.0f);
}

// -------------------- memory-path attention: tensor-core flash split --------------------
// grid (NSPLIT, H, B), 256 threads (8 warps x 16 query rows = 128 mem queries).
// splits 0..7: 512 pixel keys each (4 tiles); split 8: the 128 memory keys (1 tile).
// Writes per-(bh,split) partials: m[128], li[128], acc[32][128].
__global__ void __launch_bounds__(256) mem_attn_split_tc(
        const float* __restrict__ pqkv, const float* __restrict__ mqkv,
        const float* __restrict__ bn_sim, float* __restrict__ part) {
    const int s = blockIdx.x, h = blockIdx.y, b = blockIdx.z;
    const int tid = threadIdx.x;
    const int w = tid >> 5, lane = tid & 31;
    const int ly = lane >> 2, lx = lane & 3;

    __shared__ __half sK[128 * 16];
    __shared__ __half sVt[32 * 144];

    // Q fragment: 16 mem-query rows per warp, Q at field offset 0
    const int q0 = w * 16;
    uint32_t aq[4];
    {
        const float* qp = mqkv + (size_t)(b * 128 + q0) * 512 + h * 16;
        const float* r0 = qp + (size_t)ly * 512;
        const float* r1 = qp + (size_t)(ly + 8) * 512;
        float2 x0 = *(const float2*)(r0 + 2 * lx);
        float2 x1 = *(const float2*)(r1 + 2 * lx);
        float2 x2 = *(const float2*)(r0 + 2 * lx + 8);
        float2 x3 = *(const float2*)(r1 + 2 * lx + 8);
        aq[0] = f22h(x0.x, x0.y); aq[1] = f22h(x1.x, x1.y);
        aq[2] = f22h(x2.x, x2.y); aq[3] = f22h(x3.x, x3.y);
    }
    const float gs = bn_sim[h] * INV_C;
    const float gb = bn_sim[8 + h];

    float m0 = -1e30f, m1 = -1e30f, li0 = 0.0f, li1 = 0.0f;
    float O[4][4];
    #pragma unroll
    for (int i = 0; i < 4; i++) O[i][0] = O[i][1] = O[i][2] = O[i][3] = 0.0f;

    const int ntiles = (s < 8) ? 4 : 1;
    for (int t = 0; t < ntiles; t++) {
        const float* kvbase = (s < 8)
            ? pqkv + (size_t)(b * 4096 + s * 512 + t * 128) * 512
            : mqkv + (size_t)(b * 128) * 512;
        // stage K tile (128 keys x 16 dims, fp32->fp16)
        {
            const int m = tid >> 1, hf = tid & 1;
            const float* src = kvbase + (size_t)m * 512 + 128 + h * 16 + hf * 8;
            float4 f0 = *(const float4*)src;
            float4 f1 = *(const float4*)(src + 4);
            uint4 u;
            u.x = f22h(f0.x, f0.y); u.y = f22h(f0.z, f0.w);
            u.z = f22h(f1.x, f1.y); u.w = f22h(f1.z, f1.w);
            *(uint4*)&sK[m * 16 + hf * 8] = u;
        }
        // stage V transposed (32 dims x 128 keys)
        {
            #pragma unroll
            for (int i = 0; i < 16; i++) {
                const int m = w * 16 + i;
                float v = kvbase[(size_t)m * 512 + 256 + h * 32 + lane];
                sVt[lane * 144 + m] = __float2half_rn(v);
            }
        }
        __syncthreads();

        // S = Q @ K^T over 128 keys (16 n-frags of 8)
        float S[16][4];
        #pragma unroll
        for (int nt = 0; nt < 16; nt++) {
            S[nt][0] = S[nt][1] = S[nt][2] = S[nt][3] = 0.0f;
            uint32_t b0 = *(const uint32_t*)&sK[(nt * 8 + ly) * 16 + 2 * lx];
            uint32_t b1 = *(const uint32_t*)&sK[(nt * 8 + ly) * 16 + 8 + 2 * lx];
            mma16(S[nt], aq, b0, b1);
        }
        // logits + per-row local max
        float lm0 = -1e30f, lm1 = -1e30f;
        #pragma unroll
        for (int nt = 0; nt < 16; nt++) {
            S[nt][0] = fmaf(S[nt][0], gs, gb);
            S[nt][1] = fmaf(S[nt][1], gs, gb);
            S[nt][2] = fmaf(S[nt][2], gs, gb);
            S[nt][3] = fmaf(S[nt][3], gs, gb);
            lm0 = fmaxf(lm0, fmaxf(S[nt][0], S[nt][1]));
            lm1 = fmaxf(lm1, fmaxf(S[nt][2], S[nt][3]));
        }
        lm0 = fmaxf(lm0, __shfl_xor_sync(0xffffffffu, lm0, 1));
        lm0 = fmaxf(lm0, __shfl_xor_sync(0xffffffffu, lm0, 2));
        lm1 = fmaxf(lm1, __shfl_xor_sync(0xffffffffu, lm1, 1));
        lm1 = fmaxf(lm1, __shfl_xor_sync(0xffffffffu, lm1, 2));
        const float nm0 = fmaxf(m0, lm0), nm1 = fmaxf(m1, lm1);
        const float c0 = ex2a((m0 - nm0) * L2E);
        const float c1 = ex2a((m1 - nm1) * L2E);
        m0 = nm0; m1 = nm1;
        li0 *= c0; li1 *= c1;
        #pragma unroll
        for (int nt = 0; nt < 4; nt++) {
            O[nt][0] *= c0; O[nt][1] *= c0;
            O[nt][2] *= c1; O[nt][3] *= c1;
        }
        // P = exp(x - m), accumulate li, P@V
        #pragma unroll
        for (int nt = 0; nt < 16; nt++) {
            S[nt][0] = ex2a((S[nt][0] - nm0) * L2E);
            S[nt][1] = ex2a((S[nt][1] - nm0) * L2E);
            S[nt][2] = ex2a((S[nt][2] - nm1) * L2E);
            S[nt][3] = ex2a((S[nt][3] - nm1) * L2E);
            li0 += S[nt][0] + S[nt][1];
            li1 += S[nt][2] + S[nt][3];
        }
        #pragma unroll
        for (int j = 0; j < 8; j++) {
            uint32_t as[4];
            as[0] = f22h(S[2*j][0],   S[2*j][1]);
            as[1] = f22h(S[2*j][2],   S[2*j][3]);
            as[2] = f22h(S[2*j+1][0], S[2*j+1][1]);
            as[3] = f22h(S[2*j+1][2], S[2*j+1][3]);
            #pragma unroll
            for (int nt = 0; nt < 4; nt++) {
                uint32_t b0 = *(const uint32_t*)&sVt[(nt * 8 + ly) * 144 + j * 16 + 2 * lx];
                uint32_t b1 = *(const uint32_t*)&sVt[(nt * 8 + ly) * 144 + j * 16 + 8 + 2 * lx];
                mma16(O[nt], as, b0, b1);
            }
        }
        __syncthreads();
    }

    // reduce li across the 4 lanes sharing a row
    li0 += __shfl_xor_sync(0xffffffffu, li0, 1);
    li0 += __shfl_xor_sync(0xffffffffu, li0, 2);
    li1 += __shfl_xor_sync(0xffffffffu, li1, 1);
    li1 += __shfl_xor_sync(0xffffffffu, li1, 2);

    float* base = part + (size_t)(((b * 8 + h) * NSPLIT + s) * 34) * 128;
    const int r0 = q0 + ly, r1 = q0 + ly + 8;
    if (lx == 0) {
        base[r0] = m0;        base[r1] = m1;
        base[128 + r0] = li0; base[128 + r1] = li1;
    }
    #pragma unroll
    for (int nt = 0; nt < 4; nt++) {
        const int c = nt * 8 + 2 * lx;
        base[(2 + c)     * 128 + r0] = O[nt][0];
        base[(2 + c + 1) * 128 + r0] = O[nt][1];
        base[(2 + c)     * 128 + r1] = O[nt][2];
        base[(2 + c + 1) * 128 + r1] = O[nt][3];
    }
}

// combine: outputs fp16 retmem
__global__ void __launch_bounds__(128) mem_attn_combine(
        const float* __restrict__ part, const float* __restrict__ bn_ret,
        __half* __restrict__ retmemH) {
    const int bh = blockIdx.x;
    const int n = threadIdx.x;
    const int b = bh >> 3, h = bh & 7;
    float M = -1e30f;
    #pragma unroll
    for (int s = 0; s < NSPLIT; s++)
        M = fmaxf(M, part[(size_t)((bh * NSPLIT + s) * 34) * 128 + n]);
    float Lsum = 0.0f;
    float acc[32] = {};
    #pragma unroll
    for (int s = 0; s < NSPLIT; s++) {
        const float* base = part + (size_t)((bh * NSPLIT + s) * 34) * 128;
        float wgt = ex2a((base[n] - M) * L2E);
        Lsum = fmaf(base[128 + n], wgt, Lsum);
        #pragma unroll
        for (int d = 0; d < 32; d++)
            acc[d] = fmaf(wgt, base[(2 + d) * 128 + n], acc[d]);
    }
    float inv = rcpa(Lsum);
    inv = inv * (2.0f - Lsum * inv);
    __half* out = retmemH + (size_t)(b * 128 + n) * 256 + h * 32;
    #pragma unroll
    for (int d = 0; d < 16; d++) {
        float r0 = acc[2*d]   * inv;
        float r1 = acc[2*d+1] * inv;
        r0 = fmaxf(fmaf(r0, bn_ret[h * 32 + 2*d]   * INV_C, bn_ret[256 + h * 32 + 2*d]),   0.0f);
        r1 = fmaxf(fmaf(r1, bn_ret[h * 32 + 2*d+1] * INV_C, bn_ret[256 + h * 32 + 2*d+1]), 0.0f);
        *(uint32_t*)&out[2*d] = f22h(r0, r1);
    }
}

// -------------------- pixel-path attention: tensor-core fused --------------------
__global__ void __launch_bounds__(256) pix_attn_tc(
        const float* __restrict__ pqkv, const float* __restrict__ mqkv,
        const float* __restrict__ bn_sim, const float* __restrict__ bn_ret,
        __half* __restrict__ pretH) {
    const int lt = blockIdx.x, h = blockIdx.y, b = blockIdx.z;
    const int tid = threadIdx.x;
    const int w = tid >> 5, lane = tid & 31;
    const int ly = lane >> 2, lx = lane & 3;

    __shared__ __half sK[128 * 16];
    __shared__ __half sVt[32 * 144];

    {
        const int m = tid >> 1, hf = tid & 1;
        const float* src = mqkv + (size_t)(b * 128 + m) * 512 + 128 + h * 16 + hf * 8;
        float4 f0 = *(const float4*)src;
        float4 f1 = *(const float4*)(src + 4);
        uint4 u;
        u.x = f22h(f0.x, f0.y); u.y = f22h(f0.z, f0.w);
        u.z = f22h(f1.x, f1.y); u.w = f22h(f1.z, f1.w);
        *(uint4*)&sK[m * 16 + hf * 8] = u;
    }
    {
        #pragma unroll
        for (int i = 0; i < 16; i++) {
            const int m = w * 16 + i;
            float v = mqkv[(size_t)(b * 128 + m) * 512 + 256 + h * 32 + lane];
            sVt[lane * 144 + m] = __float2half_rn(v);
        }
    }
    const int q0 = lt * 128 + w * 16;
    uint32_t aq[4];
    {
        const float* qp = pqkv + (size_t)(b * 4096 + q0) * 512 + h * 16;
        const float* r0 = qp + (size_t)ly * 512;
        const float* r1 = qp + (size_t)(ly + 8) * 512;
        float2 x0 = *(const float2*)(r0 + 2 * lx);
        float2 x1 = *(const float2*)(r1 + 2 * lx);
        float2 x2 = *(const float2*)(r0 + 2 * lx + 8);
        float2 x3 = *(const float2*)(r1 + 2 * lx + 8);
        aq[0] = f22h(x0.x, x0.y); aq[1] = f22h(x1.x, x1.y);
        aq[2] = f22h(x2.x, x2.y); aq[3] = f22h(x3.x, x3.y);
    }
    const float gs = bn_sim[h] * INV_C;
    const float gb = bn_sim[8 + h];
    __syncthreads();

    float S[16][4];
    #pragma unroll
    for (int nt = 0; nt < 16; nt++) {
        S[nt][0] = S[nt][1] = S[nt][2] = S[nt][3] = 0.0f;
        uint32_t b0 = *(const uint32_t*)&sK[(nt * 8 + ly) * 16 + 2 * lx];
        uint32_t b1 = *(const uint32_t*)&sK[(nt * 8 + ly) * 16 + 8 + 2 * lx];
        mma16(S[nt], aq, b0, b1);
    }
    #pragma unroll
    for (int nt = 0; nt < 16; nt++)
        #pragma unroll
        for (int j = 0; j < 4; j++) {
            float x = fmaf(S[nt][j], gs, gb);
            S[nt][j] = rcpa(1.0f + ex2a(-x * L2E));
        }
    float O[4][4];
    #pragma unroll
    for (int i = 0; i < 4; i++) O[i][0] = O[i][1] = O[i][2] = O[i][3] = 0.0f;
    #pragma unroll
    for (int j = 0; j < 8; j++) {
        uint32_t as[4];
        as[0] = f22h(S[2*j][0],   S[2*j][1]);
        as[1] = f22h(S[2*j][2],   S[2*j][3]);
        as[2] = f22h(S[2*j+1][0], S[2*j+1][1]);
        as[3] = f22h(S[2*j+1][2], S[2*j+1][3]);
        #pragma unroll
        for (int nt = 0; nt < 4; nt++) {
            uint32_t b0 = *(const uint32_t*)&sVt[(nt * 8 + ly) * 144 + j * 16 + 2 * lx];
            uint32_t b1 = *(const uint32_t*)&sVt[(nt * 8 + ly) * 144 + j * 16 + 8 + 2 * lx];
            mma16(O[nt], as, b0, b1);
        }
    }
    #pragma unroll
    for (int nt = 0; nt < 4; nt++) {
        const int d = nt * 8 + 2 * lx;
        const float g0 = bn_ret[h * 32 + d] * INV_C;
        const float g1 = bn_ret[h * 32 + d + 1] * INV_C;
        const float c0 = bn_ret[256 + h * 32 + d];
        const float c1 = bn_ret[256 + h * 32 + d + 1];
        const int l0 = q0 + ly, l1 = q0 + ly + 8;
        float v0 = fmaxf(fmaf(O[nt][0], g0, c0), 0.0f);
        float v1 = fmaxf(fmaf(O[nt][1], g1, c1), 0.0f);
        float v2 = fmaxf(fmaf(O[nt][2], g0, c0), 0.0f);
        float v3 = fmaxf(fmaf(O[nt][3], g1, c1), 0.0f);
        *(uint32_t*)&pretH[(size_t)(b * 4096 + l0) * 256 + h * 32 + d] = f22h(v0, v1);
        *(uint32_t*)&pretH[(size_t)(b * 4096 + l1) * 256 + h * 32 + d] = f22h(v2, v3);
    }
}

// -------------------- launch --------------------
extern "C" void kernel_launch(void* const* d_in, const int* in_sizes, int n_in,
                              void* d_out, int out_size) {
    const float* pixel_input  = (const float*)d_in[0];
    const float* memory_input = (const float*)d_in[1];
    const float* W_mem1     = (const float*)d_in[2];
    const float* bn_mem1    = (const float*)d_in[3];
    const float* W_pix1     = (const float*)d_in[4];
    const float* bn_pix1    = (const float*)d_in[5];
    const float* W_mem_qkv  = (const float*)d_in[6];
    const float* bn_mem_qkv = (const float*)d_in[7];
    const float* W_pix_qkv  = (const float*)d_in[8];
    const float* bn_pix_qkv = (const float*)d_in[9];
    const float* bn_mem_sim = (const float*)d_in[10];
    const float* bn_mem_ret = (const float*)d_in[11];
    const float* bn_pix_sim = (const float*)d_in[12];
    const float* bn_pix_ret = (const float*)d_in[13];
    const float* W_mem3     = (const float*)d_in[14];
    const float* bn_mem3    = (const float*)d_in[15];
    const float* W_pix3     = (const float*)d_in[16];
    const float* bn_pix3    = (const float*)d_in[17];
    const float* W_ffn1     = (const float*)d_in[18];
    const float* bn_ffn1    = (const float*)d_in[19];
    const float* W_ffn2     = (const float*)d_in[20];
    const float* bn_ffn2    = (const float*)d_in[21];

    float* out_pix = (float*)d_out;
    float* out_mem = (float*)d_out + (size_t)MPIX * F_;

    __half *pixinH, *meminH, *pixH, *memH, *retmemH, *memoutH, *ffnH, *pretH, *wth;
    float *pqkv, *mqkv, *memout, *mpart, *skp;
    cudaGetSymbolAddress((void**)&pixinH,  g_pixinH);
    cudaGetSymbolAddress((void**)&meminH,  g_meminH);
    cudaGetSymbolAddress((void**)&pixH,    g_pixH);
    cudaGetSymbolAddress((void**)&pqkv,    g_pqkv);
    cudaGetSymbolAddress((void**)&memH,    g_memH);
    cudaGetSymbolAddress((void**)&mqkv,    g_mqkv);
    cudaGetSymbolAddress((void**)&retmemH, g_retmemH);
    cudaGetSymbolAddress((void**)&memout,  g_memout);
    cudaGetSymbolAddress((void**)&memoutH, g_memoutH);
    cudaGetSymbolAddress((void**)&ffnH,    g_ffnH);
    cudaGetSymbolAddress((void**)&pretH,   g_pretH);
    cudaGetSymbolAddress((void**)&mpart,   g_mpart);
    cudaGetSymbolAddress((void**)&wth,     g_wth);
    cudaGetSymbolAddress((void**)&skp,     g_skpart);

    cudaFuncSetAttribute(gemm_h<true,false,false,1>, cudaFuncAttributeMaxDynamicSharedMemorySize, GEMM_SMEM);
    cudaFuncSetAttribute(gemm_h<false,false,false,0>,cudaFuncAttributeMaxDynamicSharedMemorySize, GEMM_SMEM);
    cudaFuncSetAttribute(gemm_h<true,true,false,2>,  cudaFuncAttributeMaxDynamicSharedMemorySize, GEMM_SMEM);
    cudaFuncSetAttribute(gemm_h<false,false,true,0>, cudaFuncAttributeMaxDynamicSharedMemorySize, GEMM_SMEM);
    cudaFuncSetAttribute(gemm_h<true,true,false,0>,  cudaFuncAttributeMaxDynamicSharedMemorySize, GEMM_SMEM);

    // input conversions + fused weight transpose
    cvt_inputs<<<(MPIX*F_ + MMEM*F_) / 1024, 256>>>(pixel_input, pixinH, MPIX*F_, memory_input, meminH);
    WTargs wa;
    wa.d[0] = {W_pix1,    wth + O_PIX1, F_,   BOT_, (BOT_/32)*(F_/32)};
    wa.d[1] = {W_mem1,    wth + O_MEM1, F_,   BOT_, (BOT_/32)*(F_/32)};
    wa.d[2] = {W_pix_qkv, wth + O_PQKV, BOT_, 512,  (512/32)*(BOT_/32)};
    wa.d[3] = {W_mem_qkv, wth + O_MQKV, BOT_, 512,  (512/32)*(BOT_/32)};
    wa.d[4] = {W_mem3,    wth + O_MEM3, TV_,  F_,   (F_/32)*(TV_/32)};
    wa.d[5] = {W_pix3,    wth + O_PIX3, TV_,  F_,   (F_/32)*(TV_/32)};
    wa.d[6] = {W_ffn1,    wth + O_FFN1, F_,   FFN_, (FFN_/32)*(F_/32)};
    wa.d[7] = {W_ffn2,    wth + O_FFN2, FFN_, F_,   (F_/32)*(FFN_/32)};
    wtrans_all<<<896, 256>>>(wa);

    // stage 1: bottleneck convs (out fp16)
    gemm_h<true,false,false,1><<<dim3(2, 256), 256, GEMM_SMEM>>>(pixinH, wth + O_PIX1, bn_pix1, nullptr, nullptr, pixH, MPIX, BOT_, F_, F_);
    gemm_h<true,false,false,1><<<dim3(2, 8),   256, GEMM_SMEM>>>(meminH, wth + O_MEM1, bn_mem1, nullptr, nullptr, memH, MMEM, BOT_, F_, F_);
    // stage 2: qkv projections (out fp32)
    gemm_h<false,false,false,0><<<dim3(4, 256), 256, GEMM_SMEM>>>(pixH, wth + O_PQKV, bn_pix_qkv, nullptr, pqkv, nullptr, MPIX, 512, BOT_, BOT_);
    gemm_h<false,false,false,0><<<dim3(4, 8),   256, GEMM_SMEM>>>(memH, wth + O_MQKV, bn_mem_qkv, nullptr, mqkv, nullptr, MMEM, 512, BOT_, BOT_);
    // memory path (tensor-core flash attention)
    mem_attn_split_tc<<<dim3(NSPLIT, H_, B_), 256>>>(pqkv, mqkv, bn_mem_sim, mpart);
    mem_attn_combine<<<B_ * H_, 128>>>(mpart, bn_mem_ret, retmemH);
    gemm_h<true,true,false,2><<<dim3(1, 8), 256, GEMM_SMEM>>>(retmemH, wth + O_MEM3, bn_mem3, memory_input, memout, memoutH, MMEM, F_, TV_, TV_);
    gemm_h<true,false,false,1><<<dim3(16, 8), 256, GEMM_SMEM>>>(memoutH, wth + O_FFN1, bn_ffn1, nullptr, nullptr, ffnH, MMEM, FFN_, F_, F_);
    gemm_h<false,false,true,0><<<dim3(1, 8, 8), 256, GEMM_SMEM>>>(ffnH, wth + O_FFN2, nullptr, nullptr, skp, nullptr, MMEM, F_, FFN_/8, FFN_);
    sk_reduce<<<(MMEM*F_)/256, 256>>>(skp, bn_ffn2, memout, out_mem, MMEM, 8);
    // pixel path
    pix_attn_tc<<<dim3(L_/128, H_, B_), 256>>>(pqkv, mqkv, bn_pix_sim, bn_pix_ret, pretH);
    gemm_h<true,true,false,0><<<dim3(1, 256), 256, GEMM_SMEM>>>(pretH, wth + O_PIX3, bn_pix3, pixel_input, out_pix, nullptr, MPIX, F_, TV_, TV_);
}

// round 12
// speedup vs baseline: 8.3922x; 1.1858x over previous
#include <cuda_runtime.h>
#include <cuda_fp16.h>
#include <cstdint>

// Problem constants
#define B_  8
#define L_  4096
#define N_  128
#define F_  128
#define H_  8
#define TV_ 256
#define BOT_ 256
#define FFN_ 2048
#define INV_C 0.9995003746877732f  // 1/sqrt(1+1e-3)
#define L2E  1.4426950408889634f

#define MPIX (B_*L_)   // 32768
#define MMEM (B_*N_)   // 1024
#define NSPLIT 9       // 8 pixel-key splits + 1 mem-key split

// -------------------- scratch (device globals; no allocation) --------------------
__device__ __half g_pixinH[MPIX*F_];
__device__ __half g_meminH[MMEM*F_];
__device__ __half g_pixH [MPIX*BOT_];
__device__ float  g_pqkv[(size_t)MPIX*512];
__device__ __half g_memH [MMEM*BOT_];
__device__ float  g_mqkv[MMEM*512];
__device__ __half g_retmemH[MMEM*TV_];
__device__ float  g_memout[MMEM*F_];
__device__ __half g_memoutH[MMEM*F_];
__device__ __half g_ffnH [MMEM*FFN_];
__device__ __half g_pretH[(size_t)MPIX*TV_];
__device__ float  g_mpart[64*NSPLIT*34*128];
__device__ __half g_wth[917504];        // transposed fp16 weights
__device__ float  g_skpart[8*MMEM*F_];  // split-K partials for ffn2

// offsets into g_wth
#define O_PIX1 0
#define O_MEM1 32768
#define O_PQKV 65536
#define O_MQKV 196608
#define O_MEM3 327680
#define O_PIX3 360448
#define O_FFN1 393216
#define O_FFN2 655360

// -------------------- streams/events for capture fork-join (static init; no per-call churn) --
struct ForkCtx {
    cudaStream_t s2;
    cudaEvent_t evF, evJ;
    ForkCtx() {
        cudaStreamCreate(&s2);
        cudaEventCreateWithFlags(&evF, cudaEventDisableTiming);
        cudaEventCreateWithFlags(&evJ, cudaEventDisableTiming);
    }
};
static ForkCtx g_fork;

// -------------------- fast math --------------------
__device__ __forceinline__ float ex2a(float x){ float r; asm("ex2.approx.f32 %0, %1;" : "=f"(r):"f"(x)); return r; }
__device__ __forceinline__ float rcpa(float x){ float r; asm("rcp.approx.f32 %0, %1;" : "=f"(r):"f"(x)); return r; }
__device__ __forceinline__ uint32_t f22h(float a, float b){
    uint32_t r;
    asm("cvt.rn.f16x2.f32 %0, %1, %2;" : "=r"(r) : "f"(b), "f"(a));
    return r;
}
__device__ __forceinline__ uint32_t smem_u32(const void* p){
    uint32_t a; asm("{ .reg .u64 t; cvta.to.shared.u64 t, %1; cvt.u32.u64 %0, t; }" : "=r"(a) : "l"(p));
    return a;
}
__device__ __forceinline__ void cpa16(uint32_t s, const void* g){
    asm volatile("cp.async.ca.shared.global [%0], [%1], 16;" :: "r"(s), "l"(g));
}
#define CP_COMMIT() asm volatile("cp.async.commit_group;" ::: "memory")

__device__ __forceinline__ void ldsm4(uint32_t* r, uint32_t addr){
    asm volatile("ldmatrix.sync.aligned.m8n8.x4.shared.b16 {%0,%1,%2,%3}, [%4];"
        : "=r"(r[0]), "=r"(r[1]), "=r"(r[2]), "=r"(r[3]) : "r"(addr));
}

// fp16 mma: D[16x8] += A[16x16] * B[16x8]
__device__ __forceinline__ void mma16(float* d, const uint32_t* a, uint32_t b0, uint32_t b1){
    asm volatile("mma.sync.aligned.m16n8k16.row.col.f32.f16.f16.f32 "
        "{%0,%1,%2,%3}, {%4,%5,%6,%7}, {%8,%9}, {%0,%1,%2,%3};"
        : "+f"(d[0]), "+f"(d[1]), "+f"(d[2]), "+f"(d[3])
        : "r"(a[0]), "r"(a[1]), "r"(a[2]), "r"(a[3]), "r"(b0), "r"(b1));
}

// -------------------- prep: input cvt + weight transpose, one launch --------------------
struct WTd { const float* in; __half* out; int K; int N; int tiles; };
struct WTargs { WTd d[8]; };

__global__ void __launch_bounds__(256) prep_all(
        WTargs a,
        const float* __restrict__ pin, __half* __restrict__ pinH, int na,
        const float* __restrict__ min_, __half* __restrict__ minH, int ncvt) {
    __shared__ float t[32][33];
    if ((int)blockIdx.x < ncvt) {
        const int q = (blockIdx.x * 256 + threadIdx.x) * 4;
        if (q < na) {
            float4 v = *(const float4*)(pin + q);
            uint2 u = {f22h(v.x, v.y), f22h(v.z, v.w)};
            *(uint2*)(pinH + q) = u;
        } else {
            const int p = q - na;
            float4 v = *(const float4*)(min_ + p);
            uint2 u = {f22h(v.x, v.y), f22h(v.z, v.w)};
            *(uint2*)(minH + p) = u;
        }
        return;
    }
    int tile = blockIdx.x - ncvt;
    int i = 0;
    while (i < 7 && tile >= a.d[i].tiles) { tile -= a.d[i].tiles; i++; }
    const float* in = a.d[i].in;
    __half* out = a.d[i].out;
    const int K = a.d[i].K, Nn = a.d[i].N;
    const int ntx = Nn >> 5;
    const int bx = tile % ntx, by = tile / ntx;
    const int tx = threadIdx.x & 31, ty = threadIdx.x >> 5;
    #pragma unroll
    for (int j = 0; j < 4; j++)
        t[ty + j * 8][tx] = in[(size_t)(by * 32 + ty + j * 8) * Nn + bx * 32 + tx];
    __syncthreads();
    #pragma unroll
    for (int j = 0; j < 4; j++)
        out[(size_t)(bx * 32 + ty + j * 8) * K + by * 32 + tx] = __float2half_rn(t[tx][ty + j * 8]);
}

// -------------------- fp16 mma GEMM: cp.async + ldmatrix --------------------
// C[M,Nn] = epi( A[M,K] @ Bt[Nn,K]^T ). 128x128 tile, 256 threads, BK=64 double-buffered.
// OH: 0=fp32 out, 1=fp16 out, 2=both.
// DUAL: blockIdx.y >= ysplit selects second problem (A2/bn2/C2/Ch2), same Nn/K/lda.
template<bool RELU, bool RES, bool PARTIAL, int OH, bool DUAL>
__global__ void __launch_bounds__(256, 2) gemm_h(
        const __half* __restrict__ A, const __half* __restrict__ Bt,
        const float* __restrict__ bn, const float* __restrict__ res,
        float* __restrict__ C, __half* __restrict__ Ch, int M, int Nn, int K, int lda,
        const __half* __restrict__ A2, const __half* __restrict__ Bt2,
        const float* __restrict__ bn2, float* __restrict__ C2, __half* __restrict__ Ch2,
        int ysplit) {
    extern __shared__ __half smh[];
    float* bns = (float*)(smh + 32768);
    const uint32_t sAu = smem_u32(smh);
    const uint32_t sBu = sAu + 32768;
    const int tid = threadIdx.x;
    const int w = tid >> 5, lane = tid & 31;
    const int lx = lane & 3;
    const int wm = w >> 2, wn = w & 3;
    const int n0 = blockIdx.x * 128;

    const __half* Abase = A;
    const __half* Btb = Bt;
    const float* bnp = bn;
    float* Cp_ = C;
    __half* Chp = Ch;
    int by = blockIdx.y;
    if (DUAL && by >= ysplit) {
        by -= ysplit;
        Abase = A2; Btb = Bt2; bnp = bn2; Cp_ = C2; Chp = Ch2;
    }
    const int m0 = by * 128;
    const int kbeg = PARTIAL ? blockIdx.z * K : 0;

    if (!PARTIAL && tid < 128) {
        bns[tid]       = bnp[n0 + tid] * INV_C;
        bns[128 + tid] = bnp[Nn + n0 + tid];
    }

    const int r = tid >> 1, hh = tid & 1;
    const __half* Ap = Abase + (size_t)(m0 + r) * lda + kbeg + hh * 32;
    const __half* Bp = Btb + (size_t)(n0 + r) * lda + kbeg + hh * 32;
    uint32_t stA[4], stB[4];
    #pragma unroll
    for (int j = 0; j < 4; j++) {
        const uint32_t u = (uint32_t)(((hh * 4 + j) ^ (r & 7)) << 3);
        stA[j] = sAu + (uint32_t)(r * 64 + u) * 2;
        stB[j] = sBu + (uint32_t)(r * 64 + u) * 2;
    }

    const int sub = lane >> 3;
    const int a_ro = (sub & 1) * 8 + (lane & 7);
    const int a_c  = sub >> 1;
    const int b_ro = (sub >> 1) * 8 + (lane & 7);
    const int b_c  = sub & 1;
    uint32_t rowA_b[4]; int rpA[4];
    #pragma unroll
    for (int mt = 0; mt < 4; mt++) {
        const int row = wm * 64 + mt * 16 + a_ro;
        rowA_b[mt] = (uint32_t)row * 128;
        rpA[mt] = row & 7;
    }
    uint32_t rowB_b[2]; int rpB[2];
    #pragma unroll
    for (int p = 0; p < 2; p++) {
        const int n = wn * 32 + p * 16 + b_ro;
        rowB_b[p] = (uint32_t)n * 128;
        rpB[p] = n & 7;
    }

    const int KB = K >> 6;
    #pragma unroll
    for (int j = 0; j < 4; j++) {
        cpa16(stA[j], Ap + j * 8);
        cpa16(stB[j], Bp + j * 8);
    }
    CP_COMMIT();

    float acc[4][4][4];
    #pragma unroll
    for (int a = 0; a < 4; a++)
        #pragma unroll
        for (int b = 0; b < 4; b++)
            #pragma unroll
            for (int c = 0; c < 4; c++) acc[a][b][c] = 0.0f;

    for (int kb = 0; kb < KB; kb++) {
        if (kb + 1 < KB) {
            const uint32_t bo = (uint32_t)(((kb + 1) & 1) * 16384);
            #pragma unroll
            for (int j = 0; j < 4; j++) {
                cpa16(stA[j] + bo, Ap + (size_t)(kb + 1) * 64 + j * 8);
                cpa16(stB[j] + bo, Bp + (size_t)(kb + 1) * 64 + j * 8);
            }
            CP_COMMIT();
            asm volatile("cp.async.wait_group 1;" ::: "memory");
        } else {
            asm volatile("cp.async.wait_group 0;" ::: "memory");
        }
        __syncthreads();

        const uint32_t bufA = sAu + (uint32_t)((kb & 1) * 16384);
        const uint32_t bufB = sBu + (uint32_t)((kb & 1) * 16384);
        #pragma unroll
        for (int kt = 0; kt < 4; kt++) {
            const int ub = 2 * kt;
            uint32_t af[4][4], bf[4][2];
            #pragma unroll
            for (int p = 0; p < 2; p++) {
                uint32_t rr[4];
                ldsm4(rr, bufB + rowB_b[p] + (uint32_t)(((ub + b_c) ^ rpB[p]) << 4));
                bf[2*p][0]   = rr[0]; bf[2*p][1]   = rr[1];
                bf[2*p+1][0] = rr[2]; bf[2*p+1][1] = rr[3];
            }
            #pragma unroll
            for (int mt = 0; mt < 4; mt++)
                ldsm4(af[mt], bufA + rowA_b[mt] + (uint32_t)(((ub + a_c) ^ rpA[mt]) << 4));
            #pragma unroll
            for (int mt = 0; mt < 4; mt++)
                #pragma unroll
                for (int nt = 0; nt < 4; nt++)
                    mma16(acc[mt][nt], af[mt], bf[nt][0], bf[nt][1]);
        }
        __syncthreads();
    }

    const int ly = lane >> 2;
    if (PARTIAL) {
        float* Cpz = Cp_ + (size_t)blockIdx.z * M * Nn;
        #pragma unroll
        for (int mt = 0; mt < 4; mt++) {
            const int rr = m0 + wm * 64 + mt * 16 + ly;
            #pragma unroll
            for (int nt = 0; nt < 4; nt++) {
                const int cc = n0 + wn * 32 + nt * 8 + lx * 2;
                float2 v0 = {acc[mt][nt][0], acc[mt][nt][1]};
                float2 v1 = {acc[mt][nt][2], acc[mt][nt][3]};
                *(float2*)&Cpz[(size_t)rr * Nn + cc] = v0;
                *(float2*)&Cpz[(size_t)(rr + 8) * Nn + cc] = v1;
            }
        }
    } else {
        #pragma unroll
        for (int mt = 0; mt < 4; mt++) {
            const int rr = m0 + wm * 64 + mt * 16 + ly;
            #pragma unroll
            for (int nt = 0; nt < 4; nt++) {
                const int lc = wn * 32 + nt * 8 + lx * 2;
                const int cc = n0 + lc;
                const float g0 = bns[lc], g1 = bns[lc + 1];
                const float b0 = bns[128 + lc], b1 = bns[128 + lc + 1];
                float2 v0, v1;
                v0.x = fmaf(acc[mt][nt][0], g0, b0);
                v0.y = fmaf(acc[mt][nt][1], g1, b1);
                v1.x = fmaf(acc[mt][nt][2], g0, b0);
                v1.y = fmaf(acc[mt][nt][3], g1, b1);
                const size_t i0 = (size_t)rr * Nn + cc;
                const size_t i1 = (size_t)(rr + 8) * Nn + cc;
                if (RES) {
                    float2 r0 = *(const float2*)&res[i0];
                    float2 r1 = *(const float2*)&res[i1];
                    v0.x += r0.x; v0.y += r0.y; v1.x += r1.x; v1.y += r1.y;
                }
                if (RELU) {
                    v0.x = fmaxf(v0.x, 0.0f); v0.y = fmaxf(v0.y, 0.0f);
                    v1.x = fmaxf(v1.x, 0.0f); v1.y = fmaxf(v1.y, 0.0f);
                }
                if (OH == 0 || OH == 2) {
                    *(float2*)&Cp_[i0] = v0;
                    *(float2*)&Cp_[i1] = v1;
                }
                if (OH >= 1) {
                    *(uint32_t*)&Chp[i0] = f22h(v0.x, v0.y);
                    *(uint32_t*)&Chp[i1] = f22h(v1.x, v1.y);
                }
            }
        }
    }
}

#define GEMM_SMEM (65536 + 1024)

// split-K reduce for ffn2
__global__ void __launch_bounds__(256) sk_reduce(
        const float* __restrict__ part, const float* __restrict__ bn,
        const float* __restrict__ res, float* __restrict__ out, int M, int SK) {
    const int idx = blockIdx.x * 256 + threadIdx.x;
    const int c = idx & 127;
    float s = 0.0f;
    for (int k = 0; k < SK; k++) s += part[(size_t)k * M * 128 + idx];
    float v = fmaf(s, bn[c] * INV_C, bn[128 + c]) + res[idx];
    out[idx] = fmaxf(v, 0.0f);
}

// -------------------- memory-path attention: tensor-core flash split --------------------
__global__ void __launch_bounds__(256) mem_attn_split_tc(
        const float* __restrict__ pqkv, const float* __restrict__ mqkv,
        const float* __restrict__ bn_sim, float* __restrict__ part) {
    const int s = blockIdx.x, h = blockIdx.y, b = blockIdx.z;
    const int tid = threadIdx.x;
    const int w = tid >> 5, lane = tid & 31;
    const int ly = lane >> 2, lx = lane & 3;

    __shared__ __half sK[128 * 16];
    __shared__ __half sVt[32 * 144];

    const int q0 = w * 16;
    uint32_t aq[4];
    {
        const float* qp = mqkv + (size_t)(b * 128 + q0) * 512 + h * 16;
        const float* r0 = qp + (size_t)ly * 512;
        const float* r1 = qp + (size_t)(ly + 8) * 512;
        float2 x0 = *(const float2*)(r0 + 2 * lx);
        float2 x1 = *(const float2*)(r1 + 2 * lx);
        float2 x2 = *(const float2*)(r0 + 2 * lx + 8);
        float2 x3 = *(const float2*)(r1 + 2 * lx + 8);
        aq[0] = f22h(x0.x, x0.y); aq[1] = f22h(x1.x, x1.y);
        aq[2] = f22h(x2.x, x2.y); aq[3] = f22h(x3.x, x3.y);
    }
    const float gs = bn_sim[h] * INV_C;
    const float gb = bn_sim[8 + h];

    float m0 = -1e30f, m1 = -1e30f, li0 = 0.0f, li1 = 0.0f;
    float O[4][4];
    #pragma unroll
    for (int i = 0; i < 4; i++) O[i][0] = O[i][1] = O[i][2] = O[i][3] = 0.0f;

    const int ntiles = (s < 8) ? 4 : 1;
    for (int t = 0; t < ntiles; t++) {
        const float* kvbase = (s < 8)
            ? pqkv + (size_t)(b * 4096 + s * 512 + t * 128) * 512
            : mqkv + (size_t)(b * 128) * 512;
        {
            const int m = tid >> 1, hf = tid & 1;
            const float* src = kvbase + (size_t)m * 512 + 128 + h * 16 + hf * 8;
            float4 f0 = *(const float4*)src;
            float4 f1 = *(const float4*)(src + 4);
            uint4 u;
            u.x = f22h(f0.x, f0.y); u.y = f22h(f0.z, f0.w);
            u.z = f22h(f1.x, f1.y); u.w = f22h(f1.z, f1.w);
            *(uint4*)&sK[m * 16 + hf * 8] = u;
        }
        {
            #pragma unroll
            for (int i = 0; i < 16; i++) {
                const int m = w * 16 + i;
                float v = kvbase[(size_t)m * 512 + 256 + h * 32 + lane];
                sVt[lane * 144 + m] = __float2half_rn(v);
            }
        }
        __syncthreads();

        float S[16][4];
        #pragma unroll
        for (int nt = 0; nt < 16; nt++) {
            S[nt][0] = S[nt][1] = S[nt][2] = S[nt][3] = 0.0f;
            uint32_t b0 = *(const uint32_t*)&sK[(nt * 8 + ly) * 16 + 2 * lx];
            uint32_t b1 = *(const uint32_t*)&sK[(nt * 8 + ly) * 16 + 8 + 2 * lx];
            mma16(S[nt], aq, b0, b1);
        }
        float lm0 = -1e30f, lm1 = -1e30f;
        #pragma unroll
        for (int nt = 0; nt < 16; nt++) {
            S[nt][0] = fmaf(S[nt][0], gs, gb);
            S[nt][1] = fmaf(S[nt][1], gs, gb);
            S[nt][2] = fmaf(S[nt][2], gs, gb);
            S[nt][3] = fmaf(S[nt][3], gs, gb);
            lm0 = fmaxf(lm0, fmaxf(S[nt][0], S[nt][1]));
            lm1 = fmaxf(lm1, fmaxf(S[nt][2], S[nt][3]));
        }
        lm0 = fmaxf(lm0, __shfl_xor_sync(0xffffffffu, lm0, 1));
        lm0 = fmaxf(lm0, __shfl_xor_sync(0xffffffffu, lm0, 2));
        lm1 = fmaxf(lm1, __shfl_xor_sync(0xffffffffu, lm1, 1));
        lm1 = fmaxf(lm1, __shfl_xor_sync(0xffffffffu, lm1, 2));
        const float nm0 = fmaxf(m0, lm0), nm1 = fmaxf(m1, lm1);
        const float c0 = ex2a((m0 - nm0) * L2E);
        const float c1 = ex2a((m1 - nm1) * L2E);
        m0 = nm0; m1 = nm1;
        li0 *= c0; li1 *= c1;
        #pragma unroll
        for (int nt = 0; nt < 4; nt++) {
            O[nt][0] *= c0; O[nt][1] *= c0;
            O[nt][2] *= c1; O[nt][3] *= c1;
        }
        #pragma unroll
        for (int nt = 0; nt < 16; nt++) {
            S[nt][0] = ex2a((S[nt][0] - nm0) * L2E);
            S[nt][1] = ex2a((S[nt][1] - nm0) * L2E);
            S[nt][2] = ex2a((S[nt][2] - nm1) * L2E);
            S[nt][3] = ex2a((S[nt][3] - nm1) * L2E);
            li0 += S[nt][0] + S[nt][1];
            li1 += S[nt][2] + S[nt][3];
        }
        #pragma unroll
        for (int j = 0; j < 8; j++) {
            uint32_t as[4];
            as[0] = f22h(S[2*j][0],   S[2*j][1]);
            as[1] = f22h(S[2*j][2],   S[2*j][3]);
            as[2] = f22h(S[2*j+1][0], S[2*j+1][1]);
            as[3] = f22h(S[2*j+1][2], S[2*j+1][3]);
            #pragma unroll
            for (int nt = 0; nt < 4; nt++) {
                uint32_t b0 = *(const uint32_t*)&sVt[(nt * 8 + ly) * 144 + j * 16 + 2 * lx];
                uint32_t b1 = *(const uint32_t*)&sVt[(nt * 8 + ly) * 144 + j * 16 + 8 + 2 * lx];
                mma16(O[nt], as, b0, b1);
            }
        }
        __syncthreads();
    }

    li0 += __shfl_xor_sync(0xffffffffu, li0, 1);
    li0 += __shfl_xor_sync(0xffffffffu, li0, 2);
    li1 += __shfl_xor_sync(0xffffffffu, li1, 1);
    li1 += __shfl_xor_sync(0xffffffffu, li1, 2);

    float* base = part + (size_t)(((b * 8 + h) * NSPLIT + s) * 34) * 128;
    const int r0 = q0 + ly, r1 = q0 + ly + 8;
    if (lx == 0) {
        base[r0] = m0;        base[r1] = m1;
        base[128 + r0] = li0; base[128 + r1] = li1;
    }
    #pragma unroll
    for (int nt = 0; nt < 4; nt++) {
        const int c = nt * 8 + 2 * lx;
        base[(2 + c)     * 128 + r0] = O[nt][0];
        base[(2 + c + 1) * 128 + r0] = O[nt][1];
        base[(2 + c)     * 128 + r1] = O[nt][2];
        base[(2 + c + 1) * 128 + r1] = O[nt][3];
    }
}

// combine: outputs fp16 retmem
__global__ void __launch_bounds__(128) mem_attn_combine(
        const float* __restrict__ part, const float* __restrict__ bn_ret,
        __half* __restrict__ retmemH) {
    const int bh = blockIdx.x;
    const int n = threadIdx.x;
    const int b = bh >> 3, h = bh & 7;
    float M = -1e30f;
    #pragma unroll
    for (int s = 0; s < NSPLIT; s++)
        M = fmaxf(M, part[(size_t)((bh * NSPLIT + s) * 34) * 128 + n]);
    float Lsum = 0.0f;
    float acc[32] = {};
    #pragma unroll
    for (int s = 0; s < NSPLIT; s++) {
        const float* base = part + (size_t)((bh * NSPLIT + s) * 34) * 128;
        float wgt = ex2a((base[n] - M) * L2E);
        Lsum = fmaf(base[128 + n], wgt, Lsum);
        #pragma unroll
        for (int d = 0; d < 32; d++)
            acc[d] = fmaf(wgt, base[(2 + d) * 128 + n], acc[d]);
    }
    float inv = rcpa(Lsum);
    inv = inv * (2.0f - Lsum * inv);
    __half* out = retmemH + (size_t)(b * 128 + n) * 256 + h * 32;
    #pragma unroll
    for (int d = 0; d < 16; d++) {
        float r0 = acc[2*d]   * inv;
        float r1 = acc[2*d+1] * inv;
        r0 = fmaxf(fmaf(r0, bn_ret[h * 32 + 2*d]   * INV_C, bn_ret[256 + h * 32 + 2*d]),   0.0f);
        r1 = fmaxf(fmaf(r1, bn_ret[h * 32 + 2*d+1] * INV_C, bn_ret[256 + h * 32 + 2*d+1]), 0.0f);
        *(uint32_t*)&out[2*d] = f22h(r0, r1);
    }
}

// -------------------- pixel-path attention: tensor-core fused --------------------
__global__ void __launch_bounds__(256) pix_attn_tc(
        const float* __restrict__ pqkv, const float* __restrict__ mqkv,
        const float* __restrict__ bn_sim, const float* __restrict__ bn_ret,
        __half* __restrict__ pretH) {
    const int lt = blockIdx.x, h = blockIdx.y, b = blockIdx.z;
    const int tid = threadIdx.x;
    const int w = tid >> 5, lane = tid & 31;
    const int ly = lane >> 2, lx = lane & 3;

    __shared__ __half sK[128 * 16];
    __shared__ __half sVt[32 * 144];

    {
        const int m = tid >> 1, hf = tid & 1;
        const float* src = mqkv + (size_t)(b * 128 + m) * 512 + 128 + h * 16 + hf * 8;
        float4 f0 = *(const float4*)src;
        float4 f1 = *(const float4*)(src + 4);
        uint4 u;
        u.x = f22h(f0.x, f0.y); u.y = f22h(f0.z, f0.w);
        u.z = f22h(f1.x, f1.y); u.w = f22h(f1.z, f1.w);
        *(uint4*)&sK[m * 16 + hf * 8] = u;
    }
    {
        #pragma unroll
        for (int i = 0; i < 16; i++) {
            const int m = w * 16 + i;
            float v = mqkv[(size_t)(b * 128 + m) * 512 + 256 + h * 32 + lane];
            sVt[lane * 144 + m] = __float2half_rn(v);
        }
    }
    const int q0 = lt * 128 + w * 16;
    uint32_t aq[4];
    {
        const float* qp = pqkv + (size_t)(b * 4096 + q0) * 512 + h * 16;
        const float* r0 = qp + (size_t)ly * 512;
        const float* r1 = qp + (size_t)(ly + 8) * 512;
        float2 x0 = *(const float2*)(r0 + 2 * lx);
        float2 x1 = *(const float2*)(r1 + 2 * lx);
        float2 x2 = *(const float2*)(r0 + 2 * lx + 8);
        float2 x3 = *(const float2*)(r1 + 2 * lx + 8);
        aq[0] = f22h(x0.x, x0.y); aq[1] = f22h(x1.x, x1.y);
        aq[2] = f22h(x2.x, x2.y); aq[3] = f22h(x3.x, x3.y);
    }
    const float gs = bn_sim[h] * INV_C;
    const float gb = bn_sim[8 + h];
    __syncthreads();

    float S[16][4];
    #pragma unroll
    for (int nt = 0; nt < 16; nt++) {
        S[nt][0] = S[nt][1] = S[nt][2] = S[nt][3] = 0.0f;
        uint32_t b0 = *(const uint32_t*)&sK[(nt * 8 + ly) * 16 + 2 * lx];
        uint32_t b1 = *(const uint32_t*)&sK[(nt * 8 + ly) * 16 + 8 + 2 * lx];
        mma16(S[nt], aq, b0, b1);
    }
    #pragma unroll
    for (int nt = 0; nt < 16; nt++)
        #pragma unroll
        for (int j = 0; j < 4; j++) {
            float x = fmaf(S[nt][j], gs, gb);
            S[nt][j] = rcpa(1.0f + ex2a(-x * L2E));
        }
    float O[4][4];
    #pragma unroll
    for (int i = 0; i < 4; i++) O[i][0] = O[i][1] = O[i][2] = O[i][3] = 0.0f;
    #pragma unroll
    for (int j = 0; j < 8; j++) {
        uint32_t as[4];
        as[0] = f22h(S[2*j][0],   S[2*j][1]);
        as[1] = f22h(S[2*j][2],   S[2*j][3]);
        as[2] = f22h(S[2*j+1][0], S[2*j+1][1]);
        as[3] = f22h(S[2*j+1][2], S[2*j+1][3]);
        #pragma unroll
        for (int nt = 0; nt < 4; nt++) {
            uint32_t b0 = *(const uint32_t*)&sVt[(nt * 8 + ly) * 144 + j * 16 + 2 * lx];
            uint32_t b1 = *(const uint32_t*)&sVt[(nt * 8 + ly) * 144 + j * 16 + 8 + 2 * lx];
            mma16(O[nt], as, b0, b1);
        }
    }
    #pragma unroll
    for (int nt = 0; nt < 4; nt++) {
        const int d = nt * 8 + 2 * lx;
        const float g0 = bn_ret[h * 32 + d] * INV_C;
        const float g1 = bn_ret[h * 32 + d + 1] * INV_C;
        const float c0 = bn_ret[256 + h * 32 + d];
        const float c1 = bn_ret[256 + h * 32 + d + 1];
        const int l0 = q0 + ly, l1 = q0 + ly + 8;
        float v0 = fmaxf(fmaf(O[nt][0], g0, c0), 0.0f);
        float v1 = fmaxf(fmaf(O[nt][1], g1, c1), 0.0f);
        float v2 = fmaxf(fmaf(O[nt][2], g0, c0), 0.0f);
        float v3 = fmaxf(fmaf(O[nt][3], g1, c1), 0.0f);
        *(uint32_t*)&pretH[(size_t)(b * 4096 + l0) * 256 + h * 32 + d] = f22h(v0, v1);
        *(uint32_t*)&pretH[(size_t)(b * 4096 + l1) * 256 + h * 32 + d] = f22h(v2, v3);
    }
}

// -------------------- launch --------------------
#define NILP nullptr, nullptr, nullptr, nullptr, nullptr, 0

extern "C" void kernel_launch(void* const* d_in, const int* in_sizes, int n_in,
                              void* d_out, int out_size) {
    const float* pixel_input  = (const float*)d_in[0];
    const float* memory_input = (const float*)d_in[1];
    const float* W_mem1     = (const float*)d_in[2];
    const float* bn_mem1    = (const float*)d_in[3];
    const float* W_pix1     = (const float*)d_in[4];
    const float* bn_pix1    = (const float*)d_in[5];
    const float* W_mem_qkv  = (const float*)d_in[6];
    const float* bn_mem_qkv = (const float*)d_in[7];
    const float* W_pix_qkv  = (const float*)d_in[8];
    const float* bn_pix_qkv = (const float*)d_in[9];
    const float* bn_mem_sim = (const float*)d_in[10];
    const float* bn_mem_ret = (const float*)d_in[11];
    const float* bn_pix_sim = (const float*)d_in[12];
    const float* bn_pix_ret = (const float*)d_in[13];
    const float* W_mem3     = (const float*)d_in[14];
    const float* bn_mem3    = (const float*)d_in[15];
    const float* W_pix3     = (const float*)d_in[16];
    const float* bn_pix3    = (const float*)d_in[17];
    const float* W_ffn1     = (const float*)d_in[18];
    const float* bn_ffn1    = (const float*)d_in[19];
    const float* W_ffn2     = (const float*)d_in[20];
    const float* bn_ffn2    = (const float*)d_in[21];

    float* out_pix = (float*)d_out;
    float* out_mem = (float*)d_out + (size_t)MPIX * F_;

    __half *pixinH, *meminH, *pixH, *memH, *retmemH, *memoutH, *ffnH, *pretH, *wth;
    float *pqkv, *mqkv, *memout, *mpart, *skp;
    cudaGetSymbolAddress((void**)&pixinH,  g_pixinH);
    cudaGetSymbolAddress((void**)&meminH,  g_meminH);
    cudaGetSymbolAddress((void**)&pixH,    g_pixH);
    cudaGetSymbolAddress((void**)&pqkv,    g_pqkv);
    cudaGetSymbolAddress((void**)&memH,    g_memH);
    cudaGetSymbolAddress((void**)&mqkv,    g_mqkv);
    cudaGetSymbolAddress((void**)&retmemH, g_retmemH);
    cudaGetSymbolAddress((void**)&memout,  g_memout);
    cudaGetSymbolAddress((void**)&memoutH, g_memoutH);
    cudaGetSymbolAddress((void**)&ffnH,    g_ffnH);
    cudaGetSymbolAddress((void**)&pretH,   g_pretH);
    cudaGetSymbolAddress((void**)&mpart,   g_mpart);
    cudaGetSymbolAddress((void**)&wth,     g_wth);
    cudaGetSymbolAddress((void**)&skp,     g_skpart);

    cudaFuncSetAttribute(gemm_h<true,false,false,1,true>,  cudaFuncAttributeMaxDynamicSharedMemorySize, GEMM_SMEM);
    cudaFuncSetAttribute(gemm_h<false,false,false,0,true>, cudaFuncAttributeMaxDynamicSharedMemorySize, GEMM_SMEM);
    cudaFuncSetAttribute(gemm_h<true,true,false,2,false>,  cudaFuncAttributeMaxDynamicSharedMemorySize, GEMM_SMEM);
    cudaFuncSetAttribute(gemm_h<true,false,false,1,false>, cudaFuncAttributeMaxDynamicSharedMemorySize, GEMM_SMEM);
    cudaFuncSetAttribute(gemm_h<false,false,true,0,false>, cudaFuncAttributeMaxDynamicSharedMemorySize, GEMM_SMEM);
    cudaFuncSetAttribute(gemm_h<true,true,false,0,false>,  cudaFuncAttributeMaxDynamicSharedMemorySize, GEMM_SMEM);

    // prep: input conversions + weight transposes, one launch
    WTargs wa;
    wa.d[0] = {W_pix1,    wth + O_PIX1, F_,   BOT_, (BOT_/32)*(F_/32)};
    wa.d[1] = {W_mem1,    wth + O_MEM1, F_,   BOT_, (BOT_/32)*(F_/32)};
    wa.d[2] = {W_pix_qkv, wth + O_PQKV, BOT_, 512,  (512/32)*(BOT_/32)};
    wa.d[3] = {W_mem_qkv, wth + O_MQKV, BOT_, 512,  (512/32)*(BOT_/32)};
    wa.d[4] = {W_mem3,    wth + O_MEM3, TV_,  F_,   (F_/32)*(TV_/32)};
    wa.d[5] = {W_pix3,    wth + O_PIX3, TV_,  F_,   (F_/32)*(TV_/32)};
    wa.d[6] = {W_ffn1,    wth + O_FFN1, F_,   FFN_, (FFN_/32)*(F_/32)};
    wa.d[7] = {W_ffn2,    wth + O_FFN2, FFN_, F_,   (F_/32)*(FFN_/32)};
    const int ncvt = (MPIX*F_ + MMEM*F_) / 1024;  // 4224
    prep_all<<<ncvt + 896, 256>>>(wa, pixel_input, pixinH, MPIX*F_, memory_input, meminH, ncvt);

    // stage 1: pix1 + mem1 merged (out fp16)
    gemm_h<true,false,false,1,true><<<dim3(2, 264), 256, GEMM_SMEM>>>(
        pixinH, wth + O_PIX1, bn_pix1, nullptr, nullptr, pixH, MPIX, BOT_, F_, F_,
        meminH, wth + O_MEM1, bn_mem1, nullptr, memH, 256);
    // stage 2: pqkv + mqkv merged (out fp32)
    gemm_h<false,false,false,0,true><<<dim3(4, 264), 256, GEMM_SMEM>>>(
        pixH, wth + O_PQKV, bn_pix_qkv, nullptr, pqkv, nullptr, MPIX, 512, BOT_, BOT_,
        memH, wth + O_MQKV, bn_mem_qkv, mqkv, nullptr, 256);

    // fork: memory path on side stream, pixel path on main stream
    cudaEventRecord(g_fork.evF, 0);
    cudaStreamWaitEvent(g_fork.s2, g_fork.evF, 0);

    // ---- memory path (stream s2) ----
    mem_attn_split_tc<<<dim3(NSPLIT, H_, B_), 256, 0, g_fork.s2>>>(pqkv, mqkv, bn_mem_sim, mpart);
    mem_attn_combine<<<B_ * H_, 128, 0, g_fork.s2>>>(mpart, bn_mem_ret, retmemH);
    gemm_h<true,true,false,2,false><<<dim3(1, 8), 256, GEMM_SMEM, g_fork.s2>>>(
        retmemH, wth + O_MEM3, bn_mem3, memory_input, memout, memoutH, MMEM, F_, TV_, TV_, NILP);
    gemm_h<true,false,false,1,false><<<dim3(16, 8), 256, GEMM_SMEM, g_fork.s2>>>(
        memoutH, wth + O_FFN1, bn_ffn1, nullptr, nullptr, ffnH, MMEM, FFN_, F_, F_, NILP);
    gemm_h<false,false,true,0,false><<<dim3(1, 8, 8), 256, GEMM_SMEM, g_fork.s2>>>(
        ffnH, wth + O_FFN2, nullptr, nullptr, skp, nullptr, MMEM, F_, FFN_/8, FFN_, NILP);
    sk_reduce<<<(MMEM*F_)/256, 256, 0, g_fork.s2>>>(skp, bn_ffn2, memout, out_mem, MMEM, 8);

    // ---- pixel path (main stream) ----
    pix_attn_tc<<<dim3(L_/128, H_, B_), 256>>>(pqkv, mqkv, bn_pix_sim, bn_pix_ret, pretH);
    gemm_h<true,true,false,0,false><<<dim3(1, 256), 256, GEMM_SMEM>>>(
        pretH, wth + O_PIX3, bn_pix3, pixel_input, out_pix, nullptr, MPIX, F_, TV_, TV_, NILP);

    // join
    cudaEventRecord(g_fork.evJ, g_fork.s2);
    cudaStreamWaitEvent(0, g_fork.evJ, 0);
}